// round 1
// baseline (speedup 1.0000x reference)
#include <cuda_runtime.h>
#include <math.h>

#define BATCH 128
#define DIMN  512
#define TE    600
#define TF    120

// ---------------- scratch (device globals; no allocation allowed) ----------------
__device__ float g_Qe[BATCH * TE * DIMN];
__device__ float g_Ke[BATCH * TE * DIMN];
__device__ float g_Ve[BATCH * TE * DIMN];
__device__ float g_Qf[BATCH * TF * DIMN];
__device__ float g_Kf[BATCH * TF * DIMN];
__device__ float g_Vf[BATCH * TF * DIMN];

// ---------------- projection GEMM: C[M,512] = A[M,512] @ W[512,512] + b ----------
// 128x128 tile, BK=8, 256 threads, 8x8 micro-tile per thread.
__global__ __launch_bounds__(256, 2)
void gemm_bias_kernel(const float* __restrict__ A, const float* __restrict__ W,
                      const float* __restrict__ bias, float* __restrict__ C, int M)
{
    __shared__ float As[8][132];   // transposed, padded
    __shared__ float Bs[8][128];

    const int tid = threadIdx.x;
    const int m0  = blockIdx.y * 128;
    const int n0  = blockIdx.x * 128;
    const int tx  = tid & 15;
    const int ty  = tid >> 4;

    const int ar = tid >> 1;           // 0..127 (A tile row)
    const int ac = (tid & 1) * 4;      // 0 or 4 (A tile k-offset)
    const int br = tid >> 5;           // 0..7   (W tile k-row)
    const int bc = (tid & 31) * 4;     // 0..124 (W tile col)

    float acc[8][8];
#pragma unroll
    for (int i = 0; i < 8; i++)
#pragma unroll
        for (int j = 0; j < 8; j++) acc[i][j] = 0.f;

    const float* Aptr = A + (size_t)(m0 + ar) * DIMN + ac;
    const float* Wptr = W + (size_t)br * DIMN + n0 + bc;

    for (int k0 = 0; k0 < DIMN; k0 += 8) {
        float4 av = *(const float4*)(Aptr + k0);
        float4 bv = *(const float4*)(Wptr + (size_t)k0 * DIMN);
        __syncthreads();
        As[ac + 0][ar] = av.x;
        As[ac + 1][ar] = av.y;
        As[ac + 2][ar] = av.z;
        As[ac + 3][ar] = av.w;
        *(float4*)&Bs[br][bc] = bv;
        __syncthreads();
#pragma unroll
        for (int kk = 0; kk < 8; kk++) {
            float a[8], b[8];
#pragma unroll
            for (int i = 0; i < 8; i++) a[i] = As[kk][ty * 8 + i];
#pragma unroll
            for (int j = 0; j < 8; j++) b[j] = Bs[kk][tx * 8 + j];
#pragma unroll
            for (int i = 0; i < 8; i++)
#pragma unroll
                for (int j = 0; j < 8; j++) acc[i][j] += a[i] * b[j];
        }
    }

    float bv8[8];
#pragma unroll
    for (int j = 0; j < 8; j++) bv8[j] = bias[n0 + tx * 8 + j];
#pragma unroll
    for (int i = 0; i < 8; i++) {
        float* crow = C + (size_t)(m0 + ty * 8 + i) * DIMN + n0 + tx * 8;
        float4 o0 = make_float4(acc[i][0] + bv8[0], acc[i][1] + bv8[1],
                                acc[i][2] + bv8[2], acc[i][3] + bv8[3]);
        float4 o1 = make_float4(acc[i][4] + bv8[4], acc[i][5] + bv8[5],
                                acc[i][6] + bv8[6], acc[i][7] + bv8[7]);
        *(float4*)crow       = o0;
        *(float4*)(crow + 4) = o1;
    }
}

// ---------------- fused masked cross-attention ----------------
// One block = (batch b, 64-query tile). Computes full S row block in smem,
// exact reference masking (-1e9 fill), softmax, then O = P @ V.
// TKP = padded key count (multiple of 128). E2F selects the mask direction.
template <int TKP, bool E2F>
__global__ __launch_bounds__(256)
void attn_kernel(const float* __restrict__ Q, const float* __restrict__ K,
                 const float* __restrict__ V, float* __restrict__ O,
                 int Tq, int Tk)
{
    extern __shared__ float sm[];
    float* Ss = sm;                       // [64][TKP]
    float* Qs = sm + 64 * TKP;            // [16][68]  (phase 1)
    float* Ks = Qs + 16 * 68;             // [16][132] (phase 1)
    float* Vs = sm + 64 * TKP;            // [32][132] (phase 3, aliases Qs/Ks)

    const int tid = threadIdx.x;
    const int b   = blockIdx.y;
    const int q0  = blockIdx.x * 64;
    const int tx  = tid & 15;
    const int ty  = tid >> 4;
    const int ty4 = ty * 4;
    const int tx8 = tx * 8;
    const float scale = 0.044194173824159216f;  // 512^-0.5
    const float NEG_INF = __int_as_float(0xff800000);

    const float* Qb = Q + (size_t)b * Tq * DIMN;
    const float* Kb = K + (size_t)b * Tk * DIMN;
    const float* Vb = V + (size_t)b * Tk * DIMN;

    // ---------- Phase 1: S = scale * Q K^T with reference masking ----------
    const int qr = tid >> 2;          // 0..63
    const int qc = (tid & 3) * 4;     // 0,4,8,12
    const int kr = tid >> 1;          // 0..127
    const int kc = (tid & 1) * 8;     // 0 or 8
    const int qrow = q0 + qr;
    const bool qok = (qrow < Tq);

    for (int nk = 0; nk < TKP / 128; nk++) {
        float acc[4][8];
#pragma unroll
        for (int i = 0; i < 4; i++)
#pragma unroll
            for (int j = 0; j < 8; j++) acc[i][j] = 0.f;

        const int key_l = nk * 128 + kr;
        const bool kok = (key_l < Tk);

        for (int k0 = 0; k0 < DIMN; k0 += 16) {
            float4 qv = make_float4(0.f, 0.f, 0.f, 0.f);
            if (qok) qv = *(const float4*)(Qb + (size_t)qrow * DIMN + k0 + qc);
            float4 kv0 = make_float4(0.f, 0.f, 0.f, 0.f);
            float4 kv1 = make_float4(0.f, 0.f, 0.f, 0.f);
            if (kok) {
                const float* kp = Kb + (size_t)key_l * DIMN + k0 + kc;
                kv0 = *(const float4*)kp;
                kv1 = *(const float4*)(kp + 4);
            }
            __syncthreads();
            Qs[(qc + 0) * 68 + qr] = qv.x;
            Qs[(qc + 1) * 68 + qr] = qv.y;
            Qs[(qc + 2) * 68 + qr] = qv.z;
            Qs[(qc + 3) * 68 + qr] = qv.w;
            Ks[(kc + 0) * 132 + kr] = kv0.x;
            Ks[(kc + 1) * 132 + kr] = kv0.y;
            Ks[(kc + 2) * 132 + kr] = kv0.z;
            Ks[(kc + 3) * 132 + kr] = kv0.w;
            Ks[(kc + 4) * 132 + kr] = kv1.x;
            Ks[(kc + 5) * 132 + kr] = kv1.y;
            Ks[(kc + 6) * 132 + kr] = kv1.z;
            Ks[(kc + 7) * 132 + kr] = kv1.w;
            __syncthreads();
#pragma unroll
            for (int kk = 0; kk < 16; kk++) {
                float qf[4], kf[8];
#pragma unroll
                for (int i = 0; i < 4; i++) qf[i] = Qs[kk * 68 + ty4 + i];
#pragma unroll
                for (int j = 0; j < 8; j++) kf[j] = Ks[kk * 132 + tx8 + j];
#pragma unroll
                for (int i = 0; i < 4; i++)
#pragma unroll
                    for (int j = 0; j < 8; j++) acc[i][j] += qf[i] * kf[j];
            }
        }

        // mask (exactly like reference: scale first, then -1e9 fill) and stage to smem
#pragma unroll
        for (int i = 0; i < 4; i++) {
            const int q   = q0 + ty4 + i;
            const int j0g = q / 20;
#pragma unroll
            for (int j = 0; j < 8; j++) {
                const int key = nk * 128 + tx8 + j;
                float val;
                if (key >= Tk) {
                    val = NEG_INF;  // padding column: exp -> 0
                } else {
                    bool valid;
                    if (E2F) {
                        valid = (key >= j0g + 20) && (key <= j0g + 80);
                    } else {
                        const int g = key / 20;
                        valid = (q >= g + 20) && (q <= g + 80);
                    }
                    val = valid ? acc[i][j] * scale : -1e9f;
                }
                Ss[(ty4 + i) * TKP + key] = val;
            }
        }
    }
    __syncthreads();

    // ---------- Phase 2: softmax over each row (4 threads per row) ----------
    {
        const int row  = tid >> 2;
        const int part = tid & 3;
        float* srow = Ss + row * TKP;
        float mx = NEG_INF;
        for (int c = part; c < TKP; c += 4) mx = fmaxf(mx, srow[c]);
        mx = fmaxf(mx, __shfl_xor_sync(0xffffffffu, mx, 1));
        mx = fmaxf(mx, __shfl_xor_sync(0xffffffffu, mx, 2));
        float sum = 0.f;
        for (int c = part; c < TKP; c += 4) {
            float e = expf(srow[c] - mx);
            srow[c] = e;
            sum += e;
        }
        sum += __shfl_xor_sync(0xffffffffu, sum, 1);
        sum += __shfl_xor_sync(0xffffffffu, sum, 2);
        const float inv = 1.f / sum;
        for (int c = part; c < TKP; c += 4) srow[c] *= inv;
    }
    __syncthreads();

    // ---------- Phase 3: O = P @ V ----------
    const int vr  = tid >> 3;          // 0..31
    const int vcb = (tid & 7) * 16;    // 0..112
    for (int nc = 0; nc < 4; nc++) {
        const int n0 = nc * 128;
        float acc[4][8];
#pragma unroll
        for (int i = 0; i < 4; i++)
#pragma unroll
            for (int j = 0; j < 8; j++) acc[i][j] = 0.f;

        for (int ks = 0; ks < TKP / 32; ks++) {
            const int key = ks * 32 + vr;
            float4 v4[4];
#pragma unroll
            for (int t = 0; t < 4; t++) v4[t] = make_float4(0.f, 0.f, 0.f, 0.f);
            if (key < Tk) {
                const float* vp = Vb + (size_t)key * DIMN + n0 + vcb;
#pragma unroll
                for (int t = 0; t < 4; t++) v4[t] = *(const float4*)(vp + t * 4);
            }
            __syncthreads();
#pragma unroll
            for (int t = 0; t < 4; t++) *(float4*)&Vs[vr * 132 + vcb + t * 4] = v4[t];
            __syncthreads();
#pragma unroll
            for (int kk = 0; kk < 32; kk++) {
                float p[4], v[8];
#pragma unroll
                for (int i = 0; i < 4; i++) p[i] = Ss[(ty4 + i) * TKP + ks * 32 + kk];
#pragma unroll
                for (int j = 0; j < 8; j++) v[j] = Vs[kk * 132 + tx8 + j];
#pragma unroll
                for (int i = 0; i < 4; i++)
#pragma unroll
                    for (int j = 0; j < 8; j++) acc[i][j] += p[i] * v[j];
            }
        }
#pragma unroll
        for (int i = 0; i < 4; i++) {
            const int q = q0 + ty4 + i;
            if (q < Tq) {
                float* op = O + ((size_t)b * Tq + q) * DIMN + n0 + tx8;
                float4 o0 = make_float4(acc[i][0], acc[i][1], acc[i][2], acc[i][3]);
                float4 o1 = make_float4(acc[i][4], acc[i][5], acc[i][6], acc[i][7]);
                *(float4*)op       = o0;
                *(float4*)(op + 4) = o1;
            }
        }
    }
}

// smem sizes: S block + max(phase1 scratch, phase3 V tile) = S + 32*132 floats
static const int SMEM_E2F = (64 * 128 + 32 * 132) * 4;  // 49,664 B
static const int SMEM_F2E = (64 * 640 + 32 * 132) * 4;  // 180,736 B

extern "C" void kernel_launch(void* const* d_in, const int* in_sizes, int n_in,
                              void* d_out, int out_size)
{
    (void)in_sizes; (void)n_in; (void)out_size;

    const float* eeg   = (const float*)d_in[0];
    const float* fnirs = (const float*)d_in[1];
    const float* Wqe = (const float*)d_in[2];
    const float* bqe = (const float*)d_in[3];
    const float* Wke = (const float*)d_in[4];
    const float* bke = (const float*)d_in[5];
    const float* Wve = (const float*)d_in[6];
    const float* bve = (const float*)d_in[7];
    const float* Wqf = (const float*)d_in[8];
    const float* bqf = (const float*)d_in[9];
    const float* Wkf = (const float*)d_in[10];
    const float* bkf = (const float*)d_in[11];
    const float* Wvf = (const float*)d_in[12];
    const float* bvf = (const float*)d_in[13];

    float *Qe, *Ke, *Ve, *Qf, *Kf, *Vf;
    cudaGetSymbolAddress((void**)&Qe, g_Qe);
    cudaGetSymbolAddress((void**)&Ke, g_Ke);
    cudaGetSymbolAddress((void**)&Ve, g_Ve);
    cudaGetSymbolAddress((void**)&Qf, g_Qf);
    cudaGetSymbolAddress((void**)&Kf, g_Kf);
    cudaGetSymbolAddress((void**)&Vf, g_Vf);

    float* out           = (float*)d_out;
    float* aligned_eeg   = out;                                // [B, TF, D] (f2e result)
    float* aligned_fnirs = out + (size_t)BATCH * TF * DIMN;    // [B, TE, D] (e2f result)

    const int Me = BATCH * TE;  // 76800
    const int Mf = BATCH * TF;  // 15360

    dim3 blk(256);
    gemm_bias_kernel<<<dim3(4, Me / 128), blk>>>(eeg,   Wqe, bqe, Qe, Me);
    gemm_bias_kernel<<<dim3(4, Me / 128), blk>>>(eeg,   Wke, bke, Ke, Me);
    gemm_bias_kernel<<<dim3(4, Me / 128), blk>>>(eeg,   Wve, bve, Ve, Me);
    gemm_bias_kernel<<<dim3(4, Mf / 128), blk>>>(fnirs, Wqf, bqf, Qf, Mf);
    gemm_bias_kernel<<<dim3(4, Mf / 128), blk>>>(fnirs, Wkf, bkf, Kf, Mf);
    gemm_bias_kernel<<<dim3(4, Mf / 128), blk>>>(fnirs, Wvf, bvf, Vf, Mf);

    cudaFuncSetAttribute(attn_kernel<128, true>,
                         cudaFuncAttributeMaxDynamicSharedMemorySize, SMEM_E2F);
    cudaFuncSetAttribute(attn_kernel<640, false>,
                         cudaFuncAttributeMaxDynamicSharedMemorySize, SMEM_F2E);

    // e2f: Q from eeg (Tq=600), K/V from fnirs (Tk=120) -> aligned_fnirs
    attn_kernel<128, true><<<dim3((TE + 63) / 64, BATCH), blk, SMEM_E2F>>>(
        Qe, Kf, Vf, aligned_fnirs, TE, TF);
    // f2e: Q from fnirs (Tq=120), K/V from eeg (Tk=600) -> aligned_eeg
    attn_kernel<640, false><<<dim3((TF + 63) / 64, BATCH), blk, SMEM_F2E>>>(
        Qf, Ke, Ve, aligned_eeg, TF, TE);
}

// round 3
// speedup vs baseline: 1.6655x; 1.6655x over previous
#include <cuda_runtime.h>
#include <cstdint>
#include <math.h>

#define BATCH 128
#define DIMN  512
#define TE    600
#define TF    120

// ---------------- scratch (device globals; no allocation allowed) ----------------
__device__ float g_Qe[BATCH * TE * DIMN];
__device__ float g_Ke[BATCH * TE * DIMN];
__device__ float g_Ve[BATCH * TE * DIMN];
__device__ float g_Qf[BATCH * TF * DIMN];
__device__ float g_Kf[BATCH * TF * DIMN];
__device__ float g_Vf[BATCH * TF * DIMN];

__device__ __forceinline__ uint32_t f2tf32(float f) {
    uint32_t r; asm("cvt.rna.tf32.f32 %0, %1;" : "=r"(r) : "f"(f)); return r;
}

// m16n8k8 tf32 MMA, row.col, fp32 accumulate
__device__ __forceinline__ void mma_tf32(float* c, const uint32_t* a, const uint32_t* b) {
    asm volatile("mma.sync.aligned.m16n8k8.row.col.f32.tf32.tf32.f32 "
        "{%0,%1,%2,%3}, {%4,%5,%6,%7}, {%8,%9}, {%0,%1,%2,%3};"
        : "+f"(c[0]), "+f"(c[1]), "+f"(c[2]), "+f"(c[3])
        : "r"(a[0]), "r"(a[1]), "r"(a[2]), "r"(a[3]), "r"(b[0]), "r"(b[1]));
}

// ======================= tf32 mma.sync projection GEMM ===========================
// C[M,512] = A[M,512] @ W[512,512] + b.
// CTA: 128x128 tile, 256 threads (8 warps, each 64x32), BK=32, 16 chunks.
__global__ __launch_bounds__(256, 2)
void gemm_mma_kernel(const float* __restrict__ A, const float* __restrict__ W,
                     const float* __restrict__ bias, float* __restrict__ C)
{
    __shared__ uint32_t As[128][36];   // A[m][k], stride 36 -> conflict-free frag loads
    __shared__ uint32_t Bs[32][132];   // B[k][n], stride 132

    const int tid    = threadIdx.x;
    const int wid    = tid >> 5;
    const int lane   = tid & 31;
    const int warp_m = wid & 1;        // 2 warps over 128 rows (64 each)
    const int warp_n = wid >> 1;       // 4 warps over 128 cols (32 each)
    const int g      = lane >> 2;      // 0..7
    const int t4     = lane & 3;       // 0..3
    const int m0 = blockIdx.y * 128;
    const int n0 = blockIdx.x * 128;

    float acc[4][4][4];
#pragma unroll
    for (int mt = 0; mt < 4; mt++)
#pragma unroll
        for (int nt = 0; nt < 4; nt++)
#pragma unroll
            for (int r = 0; r < 4; r++) acc[mt][nt][r] = 0.f;

    for (int c = 0; c < 16; ++c) {
        __syncthreads();  // previous chunk's compute must finish before overwrite
        // ---- A chunk: 128 rows x 32 k (coalesced LDG.128, cvt to tf32)
#pragma unroll
        for (int i = 0; i < 4; ++i) {
            const int lin = i * 256 + tid;
            const int m = lin >> 3, q = lin & 7;
            const float4 v = *(const float4*)(A + (size_t)(m0 + m) * DIMN + c * 32 + q * 4);
            uint32_t* p = &As[m][q * 4];
            p[0] = f2tf32(v.x); p[1] = f2tf32(v.y); p[2] = f2tf32(v.z); p[3] = f2tf32(v.w);
        }
        // ---- W chunk: 32 k x 128 n (no transpose needed; coalesced)
#pragma unroll
        for (int i = 0; i < 4; ++i) {
            const int lin = i * 256 + tid;
            const int k = lin >> 5, n4 = lin & 31;
            const float4 v = *(const float4*)(W + (size_t)(c * 32 + k) * DIMN + n0 + n4 * 4);
            uint32_t* p = &Bs[k][n4 * 4];
            p[0] = f2tf32(v.x); p[1] = f2tf32(v.y); p[2] = f2tf32(v.z); p[3] = f2tf32(v.w);
        }
        __syncthreads();

#pragma unroll
        for (int kk = 0; kk < 4; ++kk) {
            uint32_t a[4][4], b[4][2];
#pragma unroll
            for (int mt = 0; mt < 4; ++mt) {
                const int r = warp_m * 64 + mt * 16 + g;
                a[mt][0] = As[r][kk * 8 + t4];
                a[mt][1] = As[r + 8][kk * 8 + t4];
                a[mt][2] = As[r][kk * 8 + t4 + 4];
                a[mt][3] = As[r + 8][kk * 8 + t4 + 4];
            }
#pragma unroll
            for (int nt = 0; nt < 4; ++nt) {
                const int n = warp_n * 32 + nt * 8 + g;
                b[nt][0] = Bs[kk * 8 + t4][n];
                b[nt][1] = Bs[kk * 8 + t4 + 4][n];
            }
#pragma unroll
            for (int mt = 0; mt < 4; ++mt)
#pragma unroll
                for (int nt = 0; nt < 4; ++nt)
                    mma_tf32(acc[mt][nt], a[mt], b[nt]);
        }
    }

    // ---- epilogue: bias add + STG.64 straight from fragments
#pragma unroll
    for (int mt = 0; mt < 4; ++mt) {
        const int row = m0 + warp_m * 64 + mt * 16 + g;
#pragma unroll
        for (int nt = 0; nt < 4; ++nt) {
            const int col = n0 + warp_n * 32 + nt * 8 + 2 * t4;
            const float2 bb = *(const float2*)(bias + col);
            float2 o0 = make_float2(acc[mt][nt][0] + bb.x, acc[mt][nt][1] + bb.y);
            float2 o1 = make_float2(acc[mt][nt][2] + bb.x, acc[mt][nt][3] + bb.y);
            *(float2*)(C + (size_t)row * DIMN + col)       = o0;
            *(float2*)(C + (size_t)(row + 8) * DIMN + col) = o1;
        }
    }
}

// ---------------- fused masked cross-attention (unchanged, fp32) ----------------
template <int TKP, bool E2F>
__global__ __launch_bounds__(256)
void attn_kernel(const float* __restrict__ Q, const float* __restrict__ K,
                 const float* __restrict__ V, float* __restrict__ O,
                 int Tq, int Tk)
{
    extern __shared__ float sm[];
    float* Ss = sm;                       // [64][TKP]
    float* Qs = sm + 64 * TKP;            // [16][68]
    float* Ks = Qs + 16 * 68;             // [16][132]
    float* Vs = sm + 64 * TKP;            // [32][132] (aliases)

    const int tid = threadIdx.x;
    const int b   = blockIdx.y;
    const int q0  = blockIdx.x * 64;
    const int tx  = tid & 15;
    const int ty  = tid >> 4;
    const int ty4 = ty * 4;
    const int tx8 = tx * 8;
    const float scale = 0.044194173824159216f;
    const float NEG_INF = __int_as_float(0xff800000);

    const float* Qb = Q + (size_t)b * Tq * DIMN;
    const float* Kb = K + (size_t)b * Tk * DIMN;
    const float* Vb = V + (size_t)b * Tk * DIMN;

    const int qr = tid >> 2;
    const int qc = (tid & 3) * 4;
    const int kr = tid >> 1;
    const int kc = (tid & 1) * 8;
    const int qrow = q0 + qr;
    const bool qok = (qrow < Tq);

    for (int nk = 0; nk < TKP / 128; nk++) {
        float acc[4][8];
#pragma unroll
        for (int i = 0; i < 4; i++)
#pragma unroll
            for (int j = 0; j < 8; j++) acc[i][j] = 0.f;

        const int key_l = nk * 128 + kr;
        const bool kok = (key_l < Tk);

        for (int k0 = 0; k0 < DIMN; k0 += 16) {
            float4 qv = make_float4(0.f, 0.f, 0.f, 0.f);
            if (qok) qv = *(const float4*)(Qb + (size_t)qrow * DIMN + k0 + qc);
            float4 kv0 = make_float4(0.f, 0.f, 0.f, 0.f);
            float4 kv1 = make_float4(0.f, 0.f, 0.f, 0.f);
            if (kok) {
                const float* kp = Kb + (size_t)key_l * DIMN + k0 + kc;
                kv0 = *(const float4*)kp;
                kv1 = *(const float4*)(kp + 4);
            }
            __syncthreads();
            Qs[(qc + 0) * 68 + qr] = qv.x;
            Qs[(qc + 1) * 68 + qr] = qv.y;
            Qs[(qc + 2) * 68 + qr] = qv.z;
            Qs[(qc + 3) * 68 + qr] = qv.w;
            Ks[(kc + 0) * 132 + kr] = kv0.x;
            Ks[(kc + 1) * 132 + kr] = kv0.y;
            Ks[(kc + 2) * 132 + kr] = kv0.z;
            Ks[(kc + 3) * 132 + kr] = kv0.w;
            Ks[(kc + 4) * 132 + kr] = kv1.x;
            Ks[(kc + 5) * 132 + kr] = kv1.y;
            Ks[(kc + 6) * 132 + kr] = kv1.z;
            Ks[(kc + 7) * 132 + kr] = kv1.w;
            __syncthreads();
#pragma unroll
            for (int kk = 0; kk < 16; kk++) {
                float qf[4], kf[8];
#pragma unroll
                for (int i = 0; i < 4; i++) qf[i] = Qs[kk * 68 + ty4 + i];
#pragma unroll
                for (int j = 0; j < 8; j++) kf[j] = Ks[kk * 132 + tx8 + j];
#pragma unroll
                for (int i = 0; i < 4; i++)
#pragma unroll
                    for (int j = 0; j < 8; j++) acc[i][j] += qf[i] * kf[j];
            }
        }

#pragma unroll
        for (int i = 0; i < 4; i++) {
            const int q   = q0 + ty4 + i;
            const int j0g = q / 20;
#pragma unroll
            for (int j = 0; j < 8; j++) {
                const int key = nk * 128 + tx8 + j;
                float val;
                if (key >= Tk) {
                    val = NEG_INF;
                } else {
                    bool valid;
                    if (E2F) {
                        valid = (key >= j0g + 20) && (key <= j0g + 80);
                    } else {
                        const int g = key / 20;
                        valid = (q >= g + 20) && (q <= g + 80);
                    }
                    val = valid ? acc[i][j] * scale : -1e9f;
                }
                Ss[(ty4 + i) * TKP + key] = val;
            }
        }
    }
    __syncthreads();

    {
        const int row  = tid >> 2;
        const int part = tid & 3;
        float* srow = Ss + row * TKP;
        float mx = NEG_INF;
        for (int c = part; c < TKP; c += 4) mx = fmaxf(mx, srow[c]);
        mx = fmaxf(mx, __shfl_xor_sync(0xffffffffu, mx, 1));
        mx = fmaxf(mx, __shfl_xor_sync(0xffffffffu, mx, 2));
        float sum = 0.f;
        for (int c = part; c < TKP; c += 4) {
            float e = expf(srow[c] - mx);
            srow[c] = e;
            sum += e;
        }
        sum += __shfl_xor_sync(0xffffffffu, sum, 1);
        sum += __shfl_xor_sync(0xffffffffu, sum, 2);
        const float inv = 1.f / sum;
        for (int c = part; c < TKP; c += 4) srow[c] *= inv;
    }
    __syncthreads();

    const int vr  = tid >> 3;
    const int vcb = (tid & 7) * 16;
    for (int nc = 0; nc < 4; nc++) {
        const int n0 = nc * 128;
        float acc[4][8];
#pragma unroll
        for (int i = 0; i < 4; i++)
#pragma unroll
            for (int j = 0; j < 8; j++) acc[i][j] = 0.f;

        for (int ks = 0; ks < TKP / 32; ks++) {
            const int key = ks * 32 + vr;
            float4 v4[4];
#pragma unroll
            for (int t = 0; t < 4; t++) v4[t] = make_float4(0.f, 0.f, 0.f, 0.f);
            if (key < Tk) {
                const float* vp = Vb + (size_t)key * DIMN + n0 + vcb;
#pragma unroll
                for (int t = 0; t < 4; t++) v4[t] = *(const float4*)(vp + t * 4);
            }
            __syncthreads();
#pragma unroll
            for (int t = 0; t < 4; t++) *(float4*)&Vs[vr * 132 + vcb + t * 4] = v4[t];
            __syncthreads();
#pragma unroll
            for (int kk = 0; kk < 32; kk++) {
                float p[4], v[8];
#pragma unroll
                for (int i = 0; i < 4; i++) p[i] = Ss[(ty4 + i) * TKP + ks * 32 + kk];
#pragma unroll
                for (int j = 0; j < 8; j++) v[j] = Vs[kk * 132 + tx8 + j];
#pragma unroll
                for (int i = 0; i < 4; i++)
#pragma unroll
                    for (int j = 0; j < 8; j++) acc[i][j] += p[i] * v[j];
            }
        }
#pragma unroll
        for (int i = 0; i < 4; i++) {
            const int q = q0 + ty4 + i;
            if (q < Tq) {
                float* op = O + ((size_t)b * Tq + q) * DIMN + n0 + tx8;
                float4 o0 = make_float4(acc[i][0], acc[i][1], acc[i][2], acc[i][3]);
                float4 o1 = make_float4(acc[i][4], acc[i][5], acc[i][6], acc[i][7]);
                *(float4*)op       = o0;
                *(float4*)(op + 4) = o1;
            }
        }
    }
}

static const int SMEM_E2F = (64 * 128 + 32 * 132) * 4;
static const int SMEM_F2E = (64 * 640 + 32 * 132) * 4;

extern "C" void kernel_launch(void* const* d_in, const int* in_sizes, int n_in,
                              void* d_out, int out_size)
{
    (void)in_sizes; (void)n_in; (void)out_size;

    const float* eeg   = (const float*)d_in[0];
    const float* fnirs = (const float*)d_in[1];
    const float* Wqe = (const float*)d_in[2];
    const float* bqe = (const float*)d_in[3];
    const float* Wke = (const float*)d_in[4];
    const float* bke = (const float*)d_in[5];
    const float* Wve = (const float*)d_in[6];
    const float* bve = (const float*)d_in[7];
    const float* Wqf = (const float*)d_in[8];
    const float* bqf = (const float*)d_in[9];
    const float* Wkf = (const float*)d_in[10];
    const float* bkf = (const float*)d_in[11];
    const float* Wvf = (const float*)d_in[12];
    const float* bvf = (const float*)d_in[13];

    float *Qe, *Ke, *Ve, *Qf, *Kf, *Vf;
    cudaGetSymbolAddress((void**)&Qe, g_Qe);
    cudaGetSymbolAddress((void**)&Ke, g_Ke);
    cudaGetSymbolAddress((void**)&Ve, g_Ve);
    cudaGetSymbolAddress((void**)&Qf, g_Qf);
    cudaGetSymbolAddress((void**)&Kf, g_Kf);
    cudaGetSymbolAddress((void**)&Vf, g_Vf);

    float* out           = (float*)d_out;
    float* aligned_eeg   = out;                                // [B, TF, D]
    float* aligned_fnirs = out + (size_t)BATCH * TF * DIMN;    // [B, TE, D]

    const int Me = BATCH * TE;  // 76800
    const int Mf = BATCH * TF;  // 15360

    dim3 blk(256);
    gemm_mma_kernel<<<dim3(4, Me / 128), blk>>>(eeg,   Wqe, bqe, Qe);
    gemm_mma_kernel<<<dim3(4, Me / 128), blk>>>(eeg,   Wke, bke, Ke);
    gemm_mma_kernel<<<dim3(4, Me / 128), blk>>>(eeg,   Wve, bve, Ve);
    gemm_mma_kernel<<<dim3(4, Mf / 128), blk>>>(fnirs, Wqf, bqf, Qf);
    gemm_mma_kernel<<<dim3(4, Mf / 128), blk>>>(fnirs, Wkf, bkf, Kf);
    gemm_mma_kernel<<<dim3(4, Mf / 128), blk>>>(fnirs, Wvf, bvf, Vf);

    cudaFuncSetAttribute(attn_kernel<128, true>,
                         cudaFuncAttributeMaxDynamicSharedMemorySize, SMEM_E2F);
    cudaFuncSetAttribute(attn_kernel<640, false>,
                         cudaFuncAttributeMaxDynamicSharedMemorySize, SMEM_F2E);

    attn_kernel<128, true><<<dim3((TE + 63) / 64, BATCH), blk, SMEM_E2F>>>(
        Qe, Kf, Vf, aligned_fnirs, TE, TF);
    attn_kernel<640, false><<<dim3((TF + 63) / 64, BATCH), blk, SMEM_F2E>>>(
        Qf, Ke, Ve, aligned_eeg, TF, TE);
}

// round 4
// speedup vs baseline: 2.6141x; 1.5696x over previous
#include <cuda_runtime.h>
#include <cstdint>
#include <math.h>

#define BATCH 128
#define DIMN  512
#define TE    600
#define TF    120

// ---------------- scratch (device globals; no allocation allowed) ----------------
__device__ float g_Qe[BATCH * TE * DIMN];
__device__ float g_Ke[BATCH * TE * DIMN];
__device__ float g_Ve[BATCH * TE * DIMN];
__device__ float g_Qf[BATCH * TF * DIMN];
__device__ float g_Kf[BATCH * TF * DIMN];
__device__ float g_Vf[BATCH * TF * DIMN];

__device__ __forceinline__ uint32_t f2tf32(float f) {
    uint32_t r; asm("cvt.rna.tf32.f32 %0, %1;" : "=r"(r) : "f"(f)); return r;
}

// m16n8k8 tf32 MMA, row.col, fp32 accumulate
__device__ __forceinline__ void mma_tf32(float* c, const uint32_t* a, const uint32_t* b) {
    asm volatile("mma.sync.aligned.m16n8k8.row.col.f32.tf32.tf32.f32 "
        "{%0,%1,%2,%3}, {%4,%5,%6,%7}, {%8,%9}, {%0,%1,%2,%3};"
        : "+f"(c[0]), "+f"(c[1]), "+f"(c[2]), "+f"(c[3])
        : "r"(a[0]), "r"(a[1]), "r"(a[2]), "r"(a[3]), "r"(b[0]), "r"(b[1]));
}

// ======================= tf32 mma.sync projection GEMM ===========================
__global__ __launch_bounds__(256, 2)
void gemm_mma_kernel(const float* __restrict__ A, const float* __restrict__ W,
                     const float* __restrict__ bias, float* __restrict__ C)
{
    __shared__ uint32_t As[128][36];
    __shared__ uint32_t Bs[32][132];

    const int tid    = threadIdx.x;
    const int wid    = tid >> 5;
    const int lane   = tid & 31;
    const int warp_m = wid & 1;
    const int warp_n = wid >> 1;
    const int g      = lane >> 2;
    const int t4     = lane & 3;
    const int m0 = blockIdx.y * 128;
    const int n0 = blockIdx.x * 128;

    float acc[4][4][4];
#pragma unroll
    for (int mt = 0; mt < 4; mt++)
#pragma unroll
        for (int nt = 0; nt < 4; nt++)
#pragma unroll
            for (int r = 0; r < 4; r++) acc[mt][nt][r] = 0.f;

    for (int c = 0; c < 16; ++c) {
        __syncthreads();
#pragma unroll
        for (int i = 0; i < 4; ++i) {
            const int lin = i * 256 + tid;
            const int m = lin >> 3, q = lin & 7;
            const float4 v = *(const float4*)(A + (size_t)(m0 + m) * DIMN + c * 32 + q * 4);
            uint32_t* p = &As[m][q * 4];
            p[0] = f2tf32(v.x); p[1] = f2tf32(v.y); p[2] = f2tf32(v.z); p[3] = f2tf32(v.w);
        }
#pragma unroll
        for (int i = 0; i < 4; ++i) {
            const int lin = i * 256 + tid;
            const int k = lin >> 5, n4 = lin & 31;
            const float4 v = *(const float4*)(W + (size_t)(c * 32 + k) * DIMN + n0 + n4 * 4);
            uint32_t* p = &Bs[k][n4 * 4];
            p[0] = f2tf32(v.x); p[1] = f2tf32(v.y); p[2] = f2tf32(v.z); p[3] = f2tf32(v.w);
        }
        __syncthreads();

#pragma unroll
        for (int kk = 0; kk < 4; ++kk) {
            uint32_t a[4][4], b[4][2];
#pragma unroll
            for (int mt = 0; mt < 4; ++mt) {
                const int r = warp_m * 64 + mt * 16 + g;
                a[mt][0] = As[r][kk * 8 + t4];
                a[mt][1] = As[r + 8][kk * 8 + t4];
                a[mt][2] = As[r][kk * 8 + t4 + 4];
                a[mt][3] = As[r + 8][kk * 8 + t4 + 4];
            }
#pragma unroll
            for (int nt = 0; nt < 4; ++nt) {
                const int n = warp_n * 32 + nt * 8 + g;
                b[nt][0] = Bs[kk * 8 + t4][n];
                b[nt][1] = Bs[kk * 8 + t4 + 4][n];
            }
#pragma unroll
            for (int mt = 0; mt < 4; ++mt)
#pragma unroll
                for (int nt = 0; nt < 4; ++nt)
                    mma_tf32(acc[mt][nt], a[mt], b[nt]);
        }
    }

#pragma unroll
    for (int mt = 0; mt < 4; ++mt) {
        const int row = m0 + warp_m * 64 + mt * 16 + g;
#pragma unroll
        for (int nt = 0; nt < 4; ++nt) {
            const int col = n0 + warp_n * 32 + nt * 8 + 2 * t4;
            const float2 bb = *(const float2*)(bias + col);
            float2 o0 = make_float2(acc[mt][nt][0] + bb.x, acc[mt][nt][1] + bb.y);
            float2 o1 = make_float2(acc[mt][nt][2] + bb.x, acc[mt][nt][3] + bb.y);
            *(float2*)(C + (size_t)row * DIMN + col)       = o0;
            *(float2*)(C + (size_t)(row + 8) * DIMN + col) = o1;
        }
    }
}

// ================= tf32 mma.sync fused masked cross-attention ====================
// One CTA = (batch, 64-query tile). 128 threads (4 warps).
// Phase 1: S = scale * Q K^T per 128-key chunk (mma, tf32), staged to smem.
// Phase 2: reference-exact masking + softmax (2 threads/row), P stored as tf32 bits.
// Phase 3: O = P V (mma, tf32).
template <int TKP, bool E2F>
__global__ __launch_bounds__(128)
void attn_mma_kernel(const float* __restrict__ Q, const float* __restrict__ K,
                     const float* __restrict__ V, float* __restrict__ O,
                     int Tq, int Tk)
{
    constexpr int SSS = TKP + 4;                  // 132 or 644; both == 4 (mod 32)
    extern __shared__ char smem[];
    float*    Ss  = (float*)smem;                 // [64][SSS]
    uint32_t* SsU = (uint32_t*)smem;
    uint32_t* Qs  = (uint32_t*)(smem + 64 * SSS * 4);   // [64][36]
    uint32_t* Ks  = Qs + 64 * 36;                       // [128][36]
    uint32_t* Vs  = Qs;                                 // [32][136] (phase 3 alias)

    const int tid    = threadIdx.x;
    const int wid    = tid >> 5;
    const int lane   = tid & 31;
    const int g      = lane >> 2;
    const int t4     = lane & 3;
    const int b      = blockIdx.y;
    const int q0     = blockIdx.x * 64;
    const float scale = 0.044194173824159216f;    // 512^-0.5
    const float NEG_INF = __int_as_float(0xff800000);

    const float* Qb = Q + (size_t)b * Tq * DIMN;
    const float* Kb = K + (size_t)b * Tk * DIMN;
    const float* Vb = V + (size_t)b * Tk * DIMN;

    // ---------------- Phase 1: S = scale * Q K^T ----------------
    for (int kc = 0; kc < TKP / 128; ++kc) {
        float acc[4][4][4];
#pragma unroll
        for (int mt = 0; mt < 4; mt++)
#pragma unroll
            for (int nt = 0; nt < 4; nt++)
#pragma unroll
                for (int r = 0; r < 4; r++) acc[mt][nt][r] = 0.f;

        for (int k0 = 0; k0 < DIMN; k0 += 32) {
            __syncthreads();
            // Q chunk: 64 rows x 32 k
#pragma unroll
            for (int i = 0; i < 4; ++i) {
                const int lin = i * 128 + tid;
                const int m = lin >> 3, q4 = lin & 7;
                float4 v = make_float4(0.f, 0.f, 0.f, 0.f);
                if (q0 + m < Tq)
                    v = *(const float4*)(Qb + (size_t)(q0 + m) * DIMN + k0 + q4 * 4);
                uint32_t* p = &Qs[m * 36 + q4 * 4];
                p[0] = f2tf32(v.x); p[1] = f2tf32(v.y); p[2] = f2tf32(v.z); p[3] = f2tf32(v.w);
            }
            // K chunk: 128 keys x 32 k
#pragma unroll
            for (int i = 0; i < 8; ++i) {
                const int lin = i * 128 + tid;
                const int kl = lin >> 3, q4 = lin & 7;
                const int key = kc * 128 + kl;
                float4 v = make_float4(0.f, 0.f, 0.f, 0.f);
                if (key < Tk)
                    v = *(const float4*)(Kb + (size_t)key * DIMN + k0 + q4 * 4);
                uint32_t* p = &Ks[kl * 36 + q4 * 4];
                p[0] = f2tf32(v.x); p[1] = f2tf32(v.y); p[2] = f2tf32(v.z); p[3] = f2tf32(v.w);
            }
            __syncthreads();
#pragma unroll
            for (int kk = 0; kk < 4; ++kk) {
                uint32_t a[4][4], bb[4][2];
#pragma unroll
                for (int mt = 0; mt < 4; ++mt) {
                    const int r = mt * 16 + g;
                    a[mt][0] = Qs[r * 36 + kk * 8 + t4];
                    a[mt][1] = Qs[(r + 8) * 36 + kk * 8 + t4];
                    a[mt][2] = Qs[r * 36 + kk * 8 + t4 + 4];
                    a[mt][3] = Qs[(r + 8) * 36 + kk * 8 + t4 + 4];
                }
#pragma unroll
                for (int nt = 0; nt < 4; ++nt) {
                    const int n = wid * 32 + nt * 8 + g;
                    bb[nt][0] = Ks[n * 36 + kk * 8 + t4];
                    bb[nt][1] = Ks[n * 36 + kk * 8 + t4 + 4];
                }
#pragma unroll
                for (int mt = 0; mt < 4; ++mt)
#pragma unroll
                    for (int nt = 0; nt < 4; ++nt)
                        mma_tf32(acc[mt][nt], a[mt], bb[nt]);
            }
        }
        // stage scaled scores
#pragma unroll
        for (int mt = 0; mt < 4; ++mt) {
            const int row = mt * 16 + g;
#pragma unroll
            for (int nt = 0; nt < 4; ++nt) {
                const int col = kc * 128 + wid * 32 + nt * 8 + 2 * t4;
                *(float2*)&Ss[row * SSS + col] =
                    make_float2(acc[mt][nt][0] * scale, acc[mt][nt][1] * scale);
                *(float2*)&Ss[(row + 8) * SSS + col] =
                    make_float2(acc[mt][nt][2] * scale, acc[mt][nt][3] * scale);
            }
        }
    }
    __syncthreads();

    // ---------------- Phase 2: mask + softmax, write P as tf32 bits --------------
    {
        const int row  = tid >> 1;
        const int part = tid & 1;
        const int q    = q0 + row;
        float* srow = Ss + row * SSS;
        const int j0g = q / 20;

        float mx = NEG_INF;
        float vals_cache;  // not enough regs to cache all; recompute mask (cheap)
        (void)vals_cache;
        for (int c = part; c < TKP; c += 2) {
            float val;
            if (c >= Tk) val = NEG_INF;
            else {
                bool valid;
                if (E2F) valid = (c >= j0g + 20) && (c <= j0g + 80);
                else { const int gg = c / 20; valid = (q >= gg + 20) && (q <= gg + 80); }
                val = valid ? srow[c] : -1e9f;
            }
            srow[c] = val;
            mx = fmaxf(mx, val);
        }
        mx = fmaxf(mx, __shfl_xor_sync(0xffffffffu, mx, 1));
        float sum = 0.f;
        for (int c = part; c < TKP; c += 2) {
            const float e = expf(srow[c] - mx);
            srow[c] = e;
            sum += e;
        }
        sum += __shfl_xor_sync(0xffffffffu, sum, 1);
        const float inv = 1.f / sum;
        uint32_t* urow = SsU + row * SSS;
        for (int c = part; c < TKP; c += 2)
            urow[c] = f2tf32(srow[c] * inv);
    }

    // ---------------- Phase 3: O = P V ----------------
    for (int nc = 0; nc < 4; ++nc) {
        float acc[4][4][4];
#pragma unroll
        for (int mt = 0; mt < 4; mt++)
#pragma unroll
            for (int nt = 0; nt < 4; nt++)
#pragma unroll
                for (int r = 0; r < 4; r++) acc[mt][nt][r] = 0.f;

        for (int ks = 0; ks < TKP / 32; ++ks) {
            __syncthreads();
            // V chunk: 32 keys x 128 d-cols
#pragma unroll
            for (int i = 0; i < 8; ++i) {
                const int lin = i * 128 + tid;
                const int kl = lin >> 5, c4 = lin & 31;
                const int key = ks * 32 + kl;
                float4 v = make_float4(0.f, 0.f, 0.f, 0.f);
                if (key < Tk)
                    v = *(const float4*)(Vb + (size_t)key * DIMN + nc * 128 + c4 * 4);
                uint32_t* p = &Vs[kl * 136 + c4 * 4];
                p[0] = f2tf32(v.x); p[1] = f2tf32(v.y); p[2] = f2tf32(v.z); p[3] = f2tf32(v.w);
            }
            __syncthreads();
#pragma unroll
            for (int kk = 0; kk < 4; ++kk) {
                uint32_t a[4][4], bb[4][2];
#pragma unroll
                for (int mt = 0; mt < 4; ++mt) {
                    const int r = mt * 16 + g;
                    const int col = ks * 32 + kk * 8 + t4;
                    a[mt][0] = SsU[r * SSS + col];
                    a[mt][1] = SsU[(r + 8) * SSS + col];
                    a[mt][2] = SsU[r * SSS + col + 4];
                    a[mt][3] = SsU[(r + 8) * SSS + col + 4];
                }
#pragma unroll
                for (int nt = 0; nt < 4; ++nt) {
                    const int n = wid * 32 + nt * 8 + g;
                    bb[nt][0] = Vs[(kk * 8 + t4) * 136 + n];
                    bb[nt][1] = Vs[(kk * 8 + t4 + 4) * 136 + n];
                }
#pragma unroll
                for (int mt = 0; mt < 4; ++mt)
#pragma unroll
                    for (int nt = 0; nt < 4; ++nt)
                        mma_tf32(acc[mt][nt], a[mt], bb[nt]);
            }
        }
        // store O chunk
#pragma unroll
        for (int mt = 0; mt < 4; ++mt) {
            const int q  = q0 + mt * 16 + g;
            const int q2 = q + 8;
#pragma unroll
            for (int nt = 0; nt < 4; ++nt) {
                const int col = nc * 128 + wid * 32 + nt * 8 + 2 * t4;
                if (q < Tq)
                    *(float2*)(O + ((size_t)b * Tq + q) * DIMN + col) =
                        make_float2(acc[mt][nt][0], acc[mt][nt][1]);
                if (q2 < Tq)
                    *(float2*)(O + ((size_t)b * Tq + q2) * DIMN + col) =
                        make_float2(acc[mt][nt][2], acc[mt][nt][3]);
            }
        }
    }
}

static const int ATTN_SMEM_E2F = (64 * 132) * 4 + (64 * 36 + 128 * 36) * 4;  //  61,440
static const int ATTN_SMEM_F2E = (64 * 644) * 4 + (64 * 36 + 128 * 36) * 4;  // 192,512

extern "C" void kernel_launch(void* const* d_in, const int* in_sizes, int n_in,
                              void* d_out, int out_size)
{
    (void)in_sizes; (void)n_in; (void)out_size;

    const float* eeg   = (const float*)d_in[0];
    const float* fnirs = (const float*)d_in[1];
    const float* Wqe = (const float*)d_in[2];
    const float* bqe = (const float*)d_in[3];
    const float* Wke = (const float*)d_in[4];
    const float* bke = (const float*)d_in[5];
    const float* Wve = (const float*)d_in[6];
    const float* bve = (const float*)d_in[7];
    const float* Wqf = (const float*)d_in[8];
    const float* bqf = (const float*)d_in[9];
    const float* Wkf = (const float*)d_in[10];
    const float* bkf = (const float*)d_in[11];
    const float* Wvf = (const float*)d_in[12];
    const float* bvf = (const float*)d_in[13];

    float *Qe, *Ke, *Ve, *Qf, *Kf, *Vf;
    cudaGetSymbolAddress((void**)&Qe, g_Qe);
    cudaGetSymbolAddress((void**)&Ke, g_Ke);
    cudaGetSymbolAddress((void**)&Ve, g_Ve);
    cudaGetSymbolAddress((void**)&Qf, g_Qf);
    cudaGetSymbolAddress((void**)&Kf, g_Kf);
    cudaGetSymbolAddress((void**)&Vf, g_Vf);

    float* out           = (float*)d_out;
    float* aligned_eeg   = out;                                // [B, TF, D]
    float* aligned_fnirs = out + (size_t)BATCH * TF * DIMN;    // [B, TE, D]

    const int Me = BATCH * TE;
    const int Mf = BATCH * TF;

    dim3 blk(256);
    gemm_mma_kernel<<<dim3(4, Me / 128), blk>>>(eeg,   Wqe, bqe, Qe);
    gemm_mma_kernel<<<dim3(4, Me / 128), blk>>>(eeg,   Wke, bke, Ke);
    gemm_mma_kernel<<<dim3(4, Me / 128), blk>>>(eeg,   Wve, bve, Ve);
    gemm_mma_kernel<<<dim3(4, Mf / 128), blk>>>(fnirs, Wqf, bqf, Qf);
    gemm_mma_kernel<<<dim3(4, Mf / 128), blk>>>(fnirs, Wkf, bkf, Kf);
    gemm_mma_kernel<<<dim3(4, Mf / 128), blk>>>(fnirs, Wvf, bvf, Vf);

    cudaFuncSetAttribute(attn_mma_kernel<128, true>,
                         cudaFuncAttributeMaxDynamicSharedMemorySize, ATTN_SMEM_E2F);
    cudaFuncSetAttribute(attn_mma_kernel<640, false>,
                         cudaFuncAttributeMaxDynamicSharedMemorySize, ATTN_SMEM_F2E);

    // e2f: Q from eeg (Tq=600), K/V from fnirs (Tk=120) -> aligned_fnirs
    attn_mma_kernel<128, true><<<dim3(10, BATCH), dim3(128), ATTN_SMEM_E2F>>>(
        Qe, Kf, Vf, aligned_fnirs, TE, TF);
    // f2e: Q from fnirs (Tq=120), K/V from eeg (Tk=600) -> aligned_eeg
    attn_mma_kernel<640, false><<<dim3(2, BATCH), dim3(128), ATTN_SMEM_F2E>>>(
        Qf, Ke, Ve, aligned_eeg, TF, TE);
}

// round 5
// speedup vs baseline: 3.0045x; 1.1493x over previous
#include <cuda_runtime.h>
#include <cstdint>
#include <math.h>

#define BATCH 128
#define DIMN  512
#define TE    600
#define TF    120

// ---------------- scratch (device globals; no allocation allowed) ----------------
__device__ float g_Qe[BATCH * TE * DIMN];
__device__ float g_Ke[BATCH * TE * DIMN];
__device__ float g_Ve[BATCH * TE * DIMN];
__device__ float g_Qf[BATCH * TF * DIMN];
__device__ float g_Kf[BATCH * TF * DIMN];
__device__ float g_Vf[BATCH * TF * DIMN];

__device__ __forceinline__ uint32_t f2tf32(float f) {
    uint32_t r; asm("cvt.rna.tf32.f32 %0, %1;" : "=r"(r) : "f"(f)); return r;
}

// m16n8k8 tf32 MMA, row.col, fp32 accumulate
__device__ __forceinline__ void mma_tf32(float* c, const uint32_t* a, const uint32_t* b) {
    asm volatile("mma.sync.aligned.m16n8k8.row.col.f32.tf32.tf32.f32 "
        "{%0,%1,%2,%3}, {%4,%5,%6,%7}, {%8,%9}, {%0,%1,%2,%3};"
        : "+f"(c[0]), "+f"(c[1]), "+f"(c[2]), "+f"(c[3])
        : "r"(a[0]), "r"(a[1]), "r"(a[2]), "r"(a[3]), "r"(b[0]), "r"(b[1]));
}

// ======================= tf32 mma.sync projection GEMM ===========================
__global__ __launch_bounds__(256, 2)
void gemm_mma_kernel(const float* __restrict__ A, const float* __restrict__ W,
                     const float* __restrict__ bias, float* __restrict__ C)
{
    __shared__ uint32_t As[128][36];
    __shared__ uint32_t Bs[32][132];

    const int tid    = threadIdx.x;
    const int wid    = tid >> 5;
    const int lane   = tid & 31;
    const int warp_m = wid & 1;
    const int warp_n = wid >> 1;
    const int g      = lane >> 2;
    const int t4     = lane & 3;
    const int m0 = blockIdx.y * 128;
    const int n0 = blockIdx.x * 128;

    float acc[4][4][4];
#pragma unroll
    for (int mt = 0; mt < 4; mt++)
#pragma unroll
        for (int nt = 0; nt < 4; nt++)
#pragma unroll
            for (int r = 0; r < 4; r++) acc[mt][nt][r] = 0.f;

    for (int c = 0; c < 16; ++c) {
        __syncthreads();
#pragma unroll
        for (int i = 0; i < 4; ++i) {
            const int lin = i * 256 + tid;
            const int m = lin >> 3, q = lin & 7;
            const float4 v = *(const float4*)(A + (size_t)(m0 + m) * DIMN + c * 32 + q * 4);
            uint32_t* p = &As[m][q * 4];
            p[0] = f2tf32(v.x); p[1] = f2tf32(v.y); p[2] = f2tf32(v.z); p[3] = f2tf32(v.w);
        }
#pragma unroll
        for (int i = 0; i < 4; ++i) {
            const int lin = i * 256 + tid;
            const int k = lin >> 5, n4 = lin & 31;
            const float4 v = *(const float4*)(W + (size_t)(c * 32 + k) * DIMN + n0 + n4 * 4);
            uint32_t* p = &Bs[k][n4 * 4];
            p[0] = f2tf32(v.x); p[1] = f2tf32(v.y); p[2] = f2tf32(v.z); p[3] = f2tf32(v.w);
        }
        __syncthreads();

#pragma unroll
        for (int kk = 0; kk < 4; ++kk) {
            uint32_t a[4][4], b[4][2];
#pragma unroll
            for (int mt = 0; mt < 4; ++mt) {
                const int r = warp_m * 64 + mt * 16 + g;
                a[mt][0] = As[r][kk * 8 + t4];
                a[mt][1] = As[r + 8][kk * 8 + t4];
                a[mt][2] = As[r][kk * 8 + t4 + 4];
                a[mt][3] = As[r + 8][kk * 8 + t4 + 4];
            }
#pragma unroll
            for (int nt = 0; nt < 4; ++nt) {
                const int n = warp_n * 32 + nt * 8 + g;
                b[nt][0] = Bs[kk * 8 + t4][n];
                b[nt][1] = Bs[kk * 8 + t4 + 4][n];
            }
#pragma unroll
            for (int mt = 0; mt < 4; ++mt)
#pragma unroll
                for (int nt = 0; nt < 4; ++nt)
                    mma_tf32(acc[mt][nt], a[mt], b[nt]);
        }
    }

#pragma unroll
    for (int mt = 0; mt < 4; ++mt) {
        const int row = m0 + warp_m * 64 + mt * 16 + g;
#pragma unroll
        for (int nt = 0; nt < 4; ++nt) {
            const int col = n0 + warp_n * 32 + nt * 8 + 2 * t4;
            const float2 bb = *(const float2*)(bias + col);
            float2 o0 = make_float2(acc[mt][nt][0] + bb.x, acc[mt][nt][1] + bb.y);
            float2 o1 = make_float2(acc[mt][nt][2] + bb.x, acc[mt][nt][3] + bb.y);
            *(float2*)(C + (size_t)row * DIMN + col)       = o0;
            *(float2*)(C + (size_t)(row + 8) * DIMN + col) = o1;
        }
    }
}

// ================= tf32 mma.sync fused masked cross-attention ====================
// 256 threads (8 warps, 2x4 layout). QTILE queries per CTA (128 for e2f, 64 f2e).
// Phase 1: S = scale*QK^T per 128-key chunk, mask applied in register epilogue.
// Phase 2: softmax (256/QTILE threads per row), P written back as tf32 bits.
// Phase 3: O = P V.
template <int TKP, int QTILE, bool E2F, int MINB>
__global__ __launch_bounds__(256, MINB)
void attn_mma_kernel(const float* __restrict__ Q, const float* __restrict__ K,
                     const float* __restrict__ V, float* __restrict__ O,
                     int Tq, int Tk)
{
    constexpr int SSS = TKP + 4;          // == 4 (mod 32)
    constexpr int MT  = QTILE / 32;       // m-frags per warp (4 for 128, 2 for 64)
    extern __shared__ char smem[];
    float*    Ss  = (float*)smem;                       // [QTILE][SSS]
    uint32_t* SsU = (uint32_t*)smem;
    uint32_t* Qs  = (uint32_t*)(smem + QTILE * SSS * 4); // [QTILE][36]
    uint32_t* Ks  = Qs + QTILE * 36;                     // [128][36]
    uint32_t* Vs  = Qs;                                  // [32][136] (phase 3 alias)

    const int tid    = threadIdx.x;
    const int wid    = tid >> 5;
    const int lane   = tid & 31;
    const int warp_m = wid & 1;
    const int warp_n = wid >> 1;
    const int g      = lane >> 2;
    const int t4     = lane & 3;
    const int b      = blockIdx.y;
    const int q0     = blockIdx.x * QTILE;
    const float scale = 0.044194173824159216f;    // 512^-0.5
    const float NEG_INF = __int_as_float(0xff800000);

    const float* Qb = Q + (size_t)b * Tq * DIMN;
    const float* Kb = K + (size_t)b * Tk * DIMN;
    const float* Vb = V + (size_t)b * Tk * DIMN;

    // ---------------- Phase 1: S = scale * Q K^T (masked) ----------------
    for (int kc = 0; kc < TKP / 128; ++kc) {
        float acc[MT][4][4];
#pragma unroll
        for (int mt = 0; mt < MT; mt++)
#pragma unroll
            for (int nt = 0; nt < 4; nt++)
#pragma unroll
                for (int r = 0; r < 4; r++) acc[mt][nt][r] = 0.f;

        for (int k0 = 0; k0 < DIMN; k0 += 32) {
            __syncthreads();
            // Q chunk: QTILE rows x 32 k
#pragma unroll
            for (int i = 0; i < QTILE / 32; ++i) {
                const int lin = i * 256 + tid;
                const int m = lin >> 3, q4 = lin & 7;
                float4 v = make_float4(0.f, 0.f, 0.f, 0.f);
                if (q0 + m < Tq)
                    v = *(const float4*)(Qb + (size_t)(q0 + m) * DIMN + k0 + q4 * 4);
                uint32_t* p = &Qs[m * 36 + q4 * 4];
                p[0] = f2tf32(v.x); p[1] = f2tf32(v.y); p[2] = f2tf32(v.z); p[3] = f2tf32(v.w);
            }
            // K chunk: 128 keys x 32 k
#pragma unroll
            for (int i = 0; i < 4; ++i) {
                const int lin = i * 256 + tid;
                const int kl = lin >> 3, q4 = lin & 7;
                const int key = kc * 128 + kl;
                float4 v = make_float4(0.f, 0.f, 0.f, 0.f);
                if (key < Tk)
                    v = *(const float4*)(Kb + (size_t)key * DIMN + k0 + q4 * 4);
                uint32_t* p = &Ks[kl * 36 + q4 * 4];
                p[0] = f2tf32(v.x); p[1] = f2tf32(v.y); p[2] = f2tf32(v.z); p[3] = f2tf32(v.w);
            }
            __syncthreads();
#pragma unroll
            for (int kk = 0; kk < 4; ++kk) {
                uint32_t a[MT][4], bb[4][2];
#pragma unroll
                for (int mt = 0; mt < MT; ++mt) {
                    const int r = warp_m * (MT * 16) + mt * 16 + g;
                    a[mt][0] = Qs[r * 36 + kk * 8 + t4];
                    a[mt][1] = Qs[(r + 8) * 36 + kk * 8 + t4];
                    a[mt][2] = Qs[r * 36 + kk * 8 + t4 + 4];
                    a[mt][3] = Qs[(r + 8) * 36 + kk * 8 + t4 + 4];
                }
#pragma unroll
                for (int nt = 0; nt < 4; ++nt) {
                    const int n = warp_n * 32 + nt * 8 + g;
                    bb[nt][0] = Ks[n * 36 + kk * 8 + t4];
                    bb[nt][1] = Ks[n * 36 + kk * 8 + t4 + 4];
                }
#pragma unroll
                for (int mt = 0; mt < MT; ++mt)
#pragma unroll
                    for (int nt = 0; nt < 4; ++nt)
                        mma_tf32(acc[mt][nt], a[mt], bb[nt]);
            }
        }
        // register-side mask + scale, stage to smem
#pragma unroll
        for (int mt = 0; mt < MT; ++mt) {
            const int r0 = warp_m * (MT * 16) + mt * 16 + g;
#pragma unroll
            for (int half = 0; half < 2; ++half) {
                const int row = r0 + half * 8;
                const int q   = q0 + row;
                const int j0g = q / 20;
#pragma unroll
                for (int nt = 0; nt < 4; ++nt) {
                    const int colc = warp_n * 32 + nt * 8 + 2 * t4;
                    float vout[2];
#pragma unroll
                    for (int e = 0; e < 2; ++e) {
                        const int key = kc * 128 + colc + e;
                        float val;
                        if (key >= Tk) val = NEG_INF;
                        else {
                            bool valid;
                            if (E2F) valid = (key >= j0g + 20) && (key <= j0g + 80);
                            else { const int gg = key / 20; valid = (q >= gg + 20) && (q <= gg + 80); }
                            val = valid ? acc[mt][nt][half * 2 + e] * scale : -1e9f;
                        }
                        vout[e] = val;
                    }
                    *(float2*)&Ss[row * SSS + kc * 128 + colc] = make_float2(vout[0], vout[1]);
                }
            }
        }
    }
    __syncthreads();

    // ---------------- Phase 2: softmax, write P as tf32 bits --------------
    {
        constexpr int TPR = 256 / QTILE;   // threads per row (2 or 4)
        const int row  = tid / TPR;
        const int part = tid % TPR;
        float* srow = Ss + row * SSS;

        float mx = NEG_INF;
        for (int c = part; c < TKP; c += TPR) mx = fmaxf(mx, srow[c]);
#pragma unroll
        for (int o = 1; o < TPR; o <<= 1) mx = fmaxf(mx, __shfl_xor_sync(0xffffffffu, mx, o));
        float sum = 0.f;
        for (int c = part; c < TKP; c += TPR) {
            const float e = __expf(srow[c] - mx);
            srow[c] = e;
            sum += e;
        }
#pragma unroll
        for (int o = 1; o < TPR; o <<= 1) sum += __shfl_xor_sync(0xffffffffu, sum, o);
        const float inv = 1.f / sum;
        uint32_t* urow = SsU + row * SSS;
        for (int c = part; c < TKP; c += TPR)
            urow[c] = f2tf32(srow[c] * inv);
    }

    // ---------------- Phase 3: O = P V ----------------
    for (int nc = 0; nc < 4; ++nc) {
        float acc[MT][4][4];
#pragma unroll
        for (int mt = 0; mt < MT; mt++)
#pragma unroll
            for (int nt = 0; nt < 4; nt++)
#pragma unroll
                for (int r = 0; r < 4; r++) acc[mt][nt][r] = 0.f;

        for (int ks = 0; ks < TKP / 32; ++ks) {
            __syncthreads();
            // V chunk: 32 keys x 128 d-cols
#pragma unroll
            for (int i = 0; i < 4; ++i) {
                const int lin = i * 256 + tid;
                const int kl = lin >> 5, c4 = lin & 31;
                const int key = ks * 32 + kl;
                float4 v = make_float4(0.f, 0.f, 0.f, 0.f);
                if (key < Tk)
                    v = *(const float4*)(Vb + (size_t)key * DIMN + nc * 128 + c4 * 4);
                uint32_t* p = &Vs[kl * 136 + c4 * 4];
                p[0] = f2tf32(v.x); p[1] = f2tf32(v.y); p[2] = f2tf32(v.z); p[3] = f2tf32(v.w);
            }
            __syncthreads();
#pragma unroll
            for (int kk = 0; kk < 4; ++kk) {
                uint32_t a[MT][4], bb[4][2];
#pragma unroll
                for (int mt = 0; mt < MT; ++mt) {
                    const int r = warp_m * (MT * 16) + mt * 16 + g;
                    const int col = ks * 32 + kk * 8 + t4;
                    a[mt][0] = SsU[r * SSS + col];
                    a[mt][1] = SsU[(r + 8) * SSS + col];
                    a[mt][2] = SsU[r * SSS + col + 4];
                    a[mt][3] = SsU[(r + 8) * SSS + col + 4];
                }
#pragma unroll
                for (int nt = 0; nt < 4; ++nt) {
                    const int n = warp_n * 32 + nt * 8 + g;
                    bb[nt][0] = Vs[(kk * 8 + t4) * 136 + n];
                    bb[nt][1] = Vs[(kk * 8 + t4 + 4) * 136 + n];
                }
#pragma unroll
                for (int mt = 0; mt < MT; ++mt)
#pragma unroll
                    for (int nt = 0; nt < 4; ++nt)
                        mma_tf32(acc[mt][nt], a[mt], bb[nt]);
            }
        }
        // store O chunk
#pragma unroll
        for (int mt = 0; mt < MT; ++mt) {
            const int q  = q0 + warp_m * (MT * 16) + mt * 16 + g;
            const int q2 = q + 8;
#pragma unroll
            for (int nt = 0; nt < 4; ++nt) {
                const int col = nc * 128 + warp_n * 32 + nt * 8 + 2 * t4;
                if (q < Tq)
                    *(float2*)(O + ((size_t)b * Tq + q) * DIMN + col) =
                        make_float2(acc[mt][nt][0], acc[mt][nt][1]);
                if (q2 < Tq)
                    *(float2*)(O + ((size_t)b * Tq + q2) * DIMN + col) =
                        make_float2(acc[mt][nt][2], acc[mt][nt][3]);
            }
        }
    }
}

static const int ATTN_SMEM_E2F = (128 * 132) * 4 + (128 * 36 + 128 * 36) * 4;  // 104,448
static const int ATTN_SMEM_F2E = (64 * 644) * 4 + (64 * 36 + 128 * 36) * 4;    // 192,512

extern "C" void kernel_launch(void* const* d_in, const int* in_sizes, int n_in,
                              void* d_out, int out_size)
{
    (void)in_sizes; (void)n_in; (void)out_size;

    const float* eeg   = (const float*)d_in[0];
    const float* fnirs = (const float*)d_in[1];
    const float* Wqe = (const float*)d_in[2];
    const float* bqe = (const float*)d_in[3];
    const float* Wke = (const float*)d_in[4];
    const float* bke = (const float*)d_in[5];
    const float* Wve = (const float*)d_in[6];
    const float* bve = (const float*)d_in[7];
    const float* Wqf = (const float*)d_in[8];
    const float* bqf = (const float*)d_in[9];
    const float* Wkf = (const float*)d_in[10];
    const float* bkf = (const float*)d_in[11];
    const float* Wvf = (const float*)d_in[12];
    const float* bvf = (const float*)d_in[13];

    float *Qe, *Ke, *Ve, *Qf, *Kf, *Vf;
    cudaGetSymbolAddress((void**)&Qe, g_Qe);
    cudaGetSymbolAddress((void**)&Ke, g_Ke);
    cudaGetSymbolAddress((void**)&Ve, g_Ve);
    cudaGetSymbolAddress((void**)&Qf, g_Qf);
    cudaGetSymbolAddress((void**)&Kf, g_Kf);
    cudaGetSymbolAddress((void**)&Vf, g_Vf);

    float* out           = (float*)d_out;
    float* aligned_eeg   = out;                                // [B, TF, D]
    float* aligned_fnirs = out + (size_t)BATCH * TF * DIMN;    // [B, TE, D]

    const int Me = BATCH * TE;
    const int Mf = BATCH * TF;

    dim3 blk(256);
    gemm_mma_kernel<<<dim3(4, Me / 128), blk>>>(eeg,   Wqe, bqe, Qe);
    gemm_mma_kernel<<<dim3(4, Me / 128), blk>>>(eeg,   Wke, bke, Ke);
    gemm_mma_kernel<<<dim3(4, Me / 128), blk>>>(eeg,   Wve, bve, Ve);
    gemm_mma_kernel<<<dim3(4, Mf / 128), blk>>>(fnirs, Wqf, bqf, Qf);
    gemm_mma_kernel<<<dim3(4, Mf / 128), blk>>>(fnirs, Wkf, bkf, Kf);
    gemm_mma_kernel<<<dim3(4, Mf / 128), blk>>>(fnirs, Wvf, bvf, Vf);

    cudaFuncSetAttribute((const void*)attn_mma_kernel<128, 128, true, 2>,
                         cudaFuncAttributeMaxDynamicSharedMemorySize, ATTN_SMEM_E2F);
    cudaFuncSetAttribute((const void*)attn_mma_kernel<640, 64, false, 1>,
                         cudaFuncAttributeMaxDynamicSharedMemorySize, ATTN_SMEM_F2E);

    // e2f: Q from eeg (Tq=600), K/V from fnirs (Tk=120) -> aligned_fnirs
    attn_mma_kernel<128, 128, true, 2><<<dim3(5, BATCH), blk, ATTN_SMEM_E2F>>>(
        Qe, Kf, Vf, aligned_fnirs, TE, TF);
    // f2e: Q from fnirs (Tq=120), K/V from eeg (Tk=600) -> aligned_eeg
    attn_mma_kernel<640, 64, false, 1><<<dim3(2, BATCH), blk, ATTN_SMEM_F2E>>>(
        Qf, Ke, Ve, aligned_eeg, TF, TE);
}

// round 6
// speedup vs baseline: 3.1743x; 1.0565x over previous
#include <cuda_runtime.h>
#include <cstdint>
#include <math.h>

#define BATCH 128
#define DIMN  512
#define TE    600
#define TF    120
#define NCHUNK 5   // f2e key chunks of 128 covering 600 keys

// ---------------- scratch (device globals; no allocation allowed) ----------------
__device__ float g_Qe[BATCH * TE * DIMN];
__device__ float g_Ke[BATCH * TE * DIMN];
__device__ float g_Ve[BATCH * TE * DIMN];
__device__ float g_Qf[BATCH * TF * DIMN];
__device__ float g_Kf[BATCH * TF * DIMN];
__device__ float g_Vf[BATCH * TF * DIMN];
__device__ float g_Opart[NCHUNK * BATCH * 128 * DIMN];  // f2e partial O
__device__ float g_M[NCHUNK * BATCH * 128];             // f2e partial row max
__device__ float g_L[NCHUNK * BATCH * 128];             // f2e partial row sum

__device__ __forceinline__ uint32_t f2tf32(float f) {
    uint32_t r; asm("cvt.rna.tf32.f32 %0, %1;" : "=r"(r) : "f"(f)); return r;
}

// m16n8k8 tf32 MMA, row.col, fp32 accumulate
__device__ __forceinline__ void mma_tf32(float* c, const uint32_t* a, const uint32_t* b) {
    asm volatile("mma.sync.aligned.m16n8k8.row.col.f32.tf32.tf32.f32 "
        "{%0,%1,%2,%3}, {%4,%5,%6,%7}, {%8,%9}, {%0,%1,%2,%3};"
        : "+f"(c[0]), "+f"(c[1]), "+f"(c[2]), "+f"(c[3])
        : "r"(a[0]), "r"(a[1]), "r"(a[2]), "r"(a[3]), "r"(b[0]), "r"(b[1]));
}

// ======================= tf32 mma.sync projection GEMM ===========================
__global__ __launch_bounds__(256, 2)
void gemm_mma_kernel(const float* __restrict__ A, const float* __restrict__ W,
                     const float* __restrict__ bias, float* __restrict__ C)
{
    __shared__ uint32_t As[128][36];
    __shared__ uint32_t Bs[32][132];

    const int tid    = threadIdx.x;
    const int wid    = tid >> 5;
    const int lane   = tid & 31;
    const int warp_m = wid & 1;
    const int warp_n = wid >> 1;
    const int g      = lane >> 2;
    const int t4     = lane & 3;
    const int m0 = blockIdx.y * 128;
    const int n0 = blockIdx.x * 128;

    float acc[4][4][4];
#pragma unroll
    for (int mt = 0; mt < 4; mt++)
#pragma unroll
        for (int nt = 0; nt < 4; nt++)
#pragma unroll
            for (int r = 0; r < 4; r++) acc[mt][nt][r] = 0.f;

    for (int c = 0; c < 16; ++c) {
        __syncthreads();
#pragma unroll
        for (int i = 0; i < 4; ++i) {
            const int lin = i * 256 + tid;
            const int m = lin >> 3, q = lin & 7;
            const float4 v = *(const float4*)(A + (size_t)(m0 + m) * DIMN + c * 32 + q * 4);
            uint32_t* p = &As[m][q * 4];
            p[0] = f2tf32(v.x); p[1] = f2tf32(v.y); p[2] = f2tf32(v.z); p[3] = f2tf32(v.w);
        }
#pragma unroll
        for (int i = 0; i < 4; ++i) {
            const int lin = i * 256 + tid;
            const int k = lin >> 5, n4 = lin & 31;
            const float4 v = *(const float4*)(W + (size_t)(c * 32 + k) * DIMN + n0 + n4 * 4);
            uint32_t* p = &Bs[k][n4 * 4];
            p[0] = f2tf32(v.x); p[1] = f2tf32(v.y); p[2] = f2tf32(v.z); p[3] = f2tf32(v.w);
        }
        __syncthreads();

#pragma unroll
        for (int kk = 0; kk < 4; ++kk) {
            uint32_t a[4][4], b[4][2];
#pragma unroll
            for (int mt = 0; mt < 4; ++mt) {
                const int r = warp_m * 64 + mt * 16 + g;
                a[mt][0] = As[r][kk * 8 + t4];
                a[mt][1] = As[r + 8][kk * 8 + t4];
                a[mt][2] = As[r][kk * 8 + t4 + 4];
                a[mt][3] = As[r + 8][kk * 8 + t4 + 4];
            }
#pragma unroll
            for (int nt = 0; nt < 4; ++nt) {
                const int n = warp_n * 32 + nt * 8 + g;
                b[nt][0] = Bs[kk * 8 + t4][n];
                b[nt][1] = Bs[kk * 8 + t4 + 4][n];
            }
#pragma unroll
            for (int mt = 0; mt < 4; ++mt)
#pragma unroll
                for (int nt = 0; nt < 4; ++nt)
                    mma_tf32(acc[mt][nt], a[mt], b[nt]);
        }
    }

#pragma unroll
    for (int mt = 0; mt < 4; ++mt) {
        const int row = m0 + warp_m * 64 + mt * 16 + g;
#pragma unroll
        for (int nt = 0; nt < 4; ++nt) {
            const int col = n0 + warp_n * 32 + nt * 8 + 2 * t4;
            const float2 bb = *(const float2*)(bias + col);
            float2 o0 = make_float2(acc[mt][nt][0] + bb.x, acc[mt][nt][1] + bb.y);
            float2 o1 = make_float2(acc[mt][nt][2] + bb.x, acc[mt][nt][3] + bb.y);
            *(float2*)(C + (size_t)row * DIMN + col)       = o0;
            *(float2*)(C + (size_t)(row + 8) * DIMN + col) = o1;
        }
    }
}

// ================= attention chunk kernel (GEMM-shaped CTA) ======================
// One CTA = (64-query tile, batch, one 128-key chunk). 256 threads, 8 warps (2x4),
// MT=2 (fits 128-reg cap, no spills). Computes masked S chunk, partial softmax
// (m, l, P=exp(s-m)), then O_p = P V.
// FINAL=true  (e2f, single chunk): write O = O_p / l to output.
// FINAL=false (f2e): write O_p + (m,l) to scratch; combine kernel merges chunks.
template <bool E2F, bool FINAL>
__global__ __launch_bounds__(256, 2)
void attn_chunk_kernel(const float* __restrict__ Q, const float* __restrict__ K,
                       const float* __restrict__ V, float* __restrict__ O,
                       float* __restrict__ Opart, float* __restrict__ Mb,
                       float* __restrict__ Lb, int Tq, int Tk)
{
    extern __shared__ char smem[];
    float*    Ss  = (float*)smem;                        // [64][132]
    uint32_t* SsU = (uint32_t*)smem;
    uint32_t* Qs  = (uint32_t*)(smem + 64 * 132 * 4);    // [64][36]
    uint32_t* Ks  = Qs + 64 * 36;                        // [128][36]
    uint32_t* Vs  = Qs;                                  // [32][136] (phase-3 alias)
    float*    l_s = (float*)(smem + 64 * 132 * 4 + (64 * 36 + 128 * 36) * 4);  // [64]

    const int tid    = threadIdx.x;
    const int wid    = tid >> 5;
    const int lane   = tid & 31;
    const int warp_m = wid & 1;
    const int warp_n = wid >> 1;
    const int g      = lane >> 2;
    const int t4     = lane & 3;
    const int q0     = blockIdx.x * 64;
    const int b      = blockIdx.y;
    const int c      = blockIdx.z;          // key chunk
    const float scale = 0.044194173824159216f;    // 512^-0.5
    const float NEG_INF = __int_as_float(0xff800000);

    const float* Qb = Q + (size_t)b * Tq * DIMN;
    const float* Kb = K + (size_t)b * Tk * DIMN;
    const float* Vb = V + (size_t)b * Tk * DIMN;

    // ---------------- Phase 1: S = scale * Q K^T over this 128-key chunk --------
    float acc[2][4][4];
#pragma unroll
    for (int mt = 0; mt < 2; mt++)
#pragma unroll
        for (int nt = 0; nt < 4; nt++)
#pragma unroll
            for (int r = 0; r < 4; r++) acc[mt][nt][r] = 0.f;

    for (int k0 = 0; k0 < DIMN; k0 += 32) {
        __syncthreads();
#pragma unroll
        for (int i = 0; i < 2; ++i) {                    // Q: 64 rows x 32 k
            const int lin = i * 256 + tid;
            const int m = lin >> 3, q4 = lin & 7;
            float4 v = make_float4(0.f, 0.f, 0.f, 0.f);
            if (q0 + m < Tq)
                v = *(const float4*)(Qb + (size_t)(q0 + m) * DIMN + k0 + q4 * 4);
            uint32_t* p = &Qs[m * 36 + q4 * 4];
            p[0] = f2tf32(v.x); p[1] = f2tf32(v.y); p[2] = f2tf32(v.z); p[3] = f2tf32(v.w);
        }
#pragma unroll
        for (int i = 0; i < 4; ++i) {                    // K: 128 keys x 32 k
            const int lin = i * 256 + tid;
            const int kl = lin >> 3, q4 = lin & 7;
            const int key = c * 128 + kl;
            float4 v = make_float4(0.f, 0.f, 0.f, 0.f);
            if (key < Tk)
                v = *(const float4*)(Kb + (size_t)key * DIMN + k0 + q4 * 4);
            uint32_t* p = &Ks[kl * 36 + q4 * 4];
            p[0] = f2tf32(v.x); p[1] = f2tf32(v.y); p[2] = f2tf32(v.z); p[3] = f2tf32(v.w);
        }
        __syncthreads();
#pragma unroll
        for (int kk = 0; kk < 4; ++kk) {
            uint32_t a[2][4], bb[4][2];
#pragma unroll
            for (int mt = 0; mt < 2; ++mt) {
                const int r = warp_m * 32 + mt * 16 + g;
                a[mt][0] = Qs[r * 36 + kk * 8 + t4];
                a[mt][1] = Qs[(r + 8) * 36 + kk * 8 + t4];
                a[mt][2] = Qs[r * 36 + kk * 8 + t4 + 4];
                a[mt][3] = Qs[(r + 8) * 36 + kk * 8 + t4 + 4];
            }
#pragma unroll
            for (int nt = 0; nt < 4; ++nt) {
                const int n = warp_n * 32 + nt * 8 + g;
                bb[nt][0] = Ks[n * 36 + kk * 8 + t4];
                bb[nt][1] = Ks[n * 36 + kk * 8 + t4 + 4];
            }
#pragma unroll
            for (int mt = 0; mt < 2; ++mt)
#pragma unroll
                for (int nt = 0; nt < 4; ++nt)
                    mma_tf32(acc[mt][nt], a[mt], bb[nt]);
        }
    }
    // register-side mask + scale, stage S chunk to smem
#pragma unroll
    for (int mt = 0; mt < 2; ++mt) {
#pragma unroll
        for (int half = 0; half < 2; ++half) {
            const int row = warp_m * 32 + mt * 16 + half * 8 + g;
            const int q   = q0 + row;
            const int j0g = q / 20;
#pragma unroll
            for (int nt = 0; nt < 4; ++nt) {
                const int colc = warp_n * 32 + nt * 8 + 2 * t4;
                float vout[2];
#pragma unroll
                for (int e = 0; e < 2; ++e) {
                    const int key = c * 128 + colc + e;
                    float val;
                    if (key >= Tk) val = NEG_INF;
                    else {
                        bool valid;
                        if (E2F) valid = (key >= j0g + 20) && (key <= j0g + 80);
                        else { const int gg = key / 20; valid = (q >= gg + 20) && (q <= gg + 80); }
                        val = valid ? acc[mt][nt][half * 2 + e] * scale : -1e9f;
                    }
                    vout[e] = val;
                }
                *(float2*)&Ss[row * 132 + colc] = make_float2(vout[0], vout[1]);
            }
        }
    }
    __syncthreads();

    // ---------------- Phase 2: partial softmax (m, l, P = exp(s-m)) -------------
    {
        const int row  = tid >> 2;          // 4 threads/row
        const int part = tid & 3;
        float* srow = Ss + row * 132;

        float mx = NEG_INF;
#pragma unroll
        for (int i = 0; i < 32; ++i) mx = fmaxf(mx, srow[part + i * 4]);
        mx = fmaxf(mx, __shfl_xor_sync(0xffffffffu, mx, 1));
        mx = fmaxf(mx, __shfl_xor_sync(0xffffffffu, mx, 2));
        float sum = 0.f;
        uint32_t* urow = SsU + row * 132;
#pragma unroll
        for (int i = 0; i < 32; ++i) {
            const int cc = part + i * 4;
            const float e = __expf(srow[cc] - mx);
            sum += e;
            urow[cc] = f2tf32(e);
        }
        sum += __shfl_xor_sync(0xffffffffu, sum, 1);
        sum += __shfl_xor_sync(0xffffffffu, sum, 2);
        if (part == 0) {
            l_s[row] = sum;
            if (!FINAL) {
                const int idx = (c * BATCH + b) * 128 + q0 + row;
                Mb[idx] = mx;
                Lb[idx] = sum;
            }
        }
    }
    __syncthreads();

    // ---------------- Phase 3: O_p = P V ----------------
    for (int nc = 0; nc < 4; ++nc) {
        float oacc[2][4][4];
#pragma unroll
        for (int mt = 0; mt < 2; mt++)
#pragma unroll
            for (int nt = 0; nt < 4; nt++)
#pragma unroll
                for (int r = 0; r < 4; r++) oacc[mt][nt][r] = 0.f;

        for (int ks = 0; ks < 4; ++ks) {
            __syncthreads();
#pragma unroll
            for (int i = 0; i < 4; ++i) {                // V: 32 keys x 128 d-cols
                const int lin = i * 256 + tid;
                const int kl = lin >> 5, c4 = lin & 31;
                const int key = c * 128 + ks * 32 + kl;
                float4 v = make_float4(0.f, 0.f, 0.f, 0.f);
                if (key < Tk)
                    v = *(const float4*)(Vb + (size_t)key * DIMN + nc * 128 + c4 * 4);
                uint32_t* p = &Vs[kl * 136 + c4 * 4];
                p[0] = f2tf32(v.x); p[1] = f2tf32(v.y); p[2] = f2tf32(v.z); p[3] = f2tf32(v.w);
            }
            __syncthreads();
#pragma unroll
            for (int kk = 0; kk < 4; ++kk) {
                uint32_t a[2][4], bb[4][2];
#pragma unroll
                for (int mt = 0; mt < 2; ++mt) {
                    const int r = warp_m * 32 + mt * 16 + g;
                    const int col = ks * 32 + kk * 8 + t4;
                    a[mt][0] = SsU[r * 132 + col];
                    a[mt][1] = SsU[(r + 8) * 132 + col];
                    a[mt][2] = SsU[r * 132 + col + 4];
                    a[mt][3] = SsU[(r + 8) * 132 + col + 4];
                }
#pragma unroll
                for (int nt = 0; nt < 4; ++nt) {
                    const int n = warp_n * 32 + nt * 8 + g;
                    bb[nt][0] = Vs[(kk * 8 + t4) * 136 + n];
                    bb[nt][1] = Vs[(kk * 8 + t4 + 4) * 136 + n];
                }
#pragma unroll
                for (int mt = 0; mt < 2; ++mt)
#pragma unroll
                    for (int nt = 0; nt < 4; ++nt)
                        mma_tf32(oacc[mt][nt], a[mt], bb[nt]);
            }
        }
        // store this 128-col d-chunk
#pragma unroll
        for (int mt = 0; mt < 2; ++mt) {
#pragma unroll
            for (int half = 0; half < 2; ++half) {
                const int row = warp_m * 32 + mt * 16 + half * 8 + g;
                const int q   = q0 + row;
#pragma unroll
                for (int nt = 0; nt < 4; ++nt) {
                    const int col = nc * 128 + warp_n * 32 + nt * 8 + 2 * t4;
                    const float v0 = oacc[mt][nt][half * 2 + 0];
                    const float v1 = oacc[mt][nt][half * 2 + 1];
                    if (FINAL) {
                        if (q < Tq) {
                            const float inv = 1.f / l_s[row];
                            *(float2*)(O + ((size_t)b * Tq + q) * DIMN + col) =
                                make_float2(v0 * inv, v1 * inv);
                        }
                    } else {
                        float* dst = Opart + (((size_t)c * BATCH + b) * 128 + q) * DIMN + col;
                        *(float2*)dst = make_float2(v0, v1);
                    }
                }
            }
        }
    }
}

// ----------------- f2e combine: merge 5 chunk partials per row -------------------
__global__ void combine_f2e(const float* __restrict__ Opart,
                            const float* __restrict__ Mb, const float* __restrict__ Lb,
                            float* __restrict__ O)
{
    const int q = blockIdx.x;           // 0..119
    const int b = blockIdx.y;
    const int t = threadIdx.x;          // 128 threads -> float4 each
    float m[NCHUNK], w[NCHUNK];
    float M = __int_as_float(0xff800000);
#pragma unroll
    for (int c = 0; c < NCHUNK; ++c) {
        m[c] = Mb[(c * BATCH + b) * 128 + q];
        M = fmaxf(M, m[c]);
    }
    float den = 0.f;
#pragma unroll
    for (int c = 0; c < NCHUNK; ++c) {
        w[c] = __expf(m[c] - M);
        den += w[c] * Lb[(c * BATCH + b) * 128 + q];
    }
    const float inv = 1.f / den;
    float4 o = make_float4(0.f, 0.f, 0.f, 0.f);
#pragma unroll
    for (int c = 0; c < NCHUNK; ++c) {
        const float4 p = *(const float4*)(Opart + (((size_t)c * BATCH + b) * 128 + q) * DIMN + t * 4);
        const float s = w[c] * inv;
        o.x += s * p.x; o.y += s * p.y; o.z += s * p.z; o.w += s * p.w;
    }
    *(float4*)(O + ((size_t)b * TF + q) * DIMN + t * 4) = o;
}

static const int ATTN_SMEM = 64 * 132 * 4 + (64 * 36 + 128 * 36) * 4 + 64 * 4;  // 61,952

extern "C" void kernel_launch(void* const* d_in, const int* in_sizes, int n_in,
                              void* d_out, int out_size)
{
    (void)in_sizes; (void)n_in; (void)out_size;

    const float* eeg   = (const float*)d_in[0];
    const float* fnirs = (const float*)d_in[1];
    const float* Wqe = (const float*)d_in[2];
    const float* bqe = (const float*)d_in[3];
    const float* Wke = (const float*)d_in[4];
    const float* bke = (const float*)d_in[5];
    const float* Wve = (const float*)d_in[6];
    const float* bve = (const float*)d_in[7];
    const float* Wqf = (const float*)d_in[8];
    const float* bqf = (const float*)d_in[9];
    const float* Wkf = (const float*)d_in[10];
    const float* bkf = (const float*)d_in[11];
    const float* Wvf = (const float*)d_in[12];
    const float* bvf = (const float*)d_in[13];

    float *Qe, *Ke, *Ve, *Qf, *Kf, *Vf, *Opart, *Mb, *Lb;
    cudaGetSymbolAddress((void**)&Qe, g_Qe);
    cudaGetSymbolAddress((void**)&Ke, g_Ke);
    cudaGetSymbolAddress((void**)&Ve, g_Ve);
    cudaGetSymbolAddress((void**)&Qf, g_Qf);
    cudaGetSymbolAddress((void**)&Kf, g_Kf);
    cudaGetSymbolAddress((void**)&Vf, g_Vf);
    cudaGetSymbolAddress((void**)&Opart, g_Opart);
    cudaGetSymbolAddress((void**)&Mb, g_M);
    cudaGetSymbolAddress((void**)&Lb, g_L);

    float* out           = (float*)d_out;
    float* aligned_eeg   = out;                                // [B, TF, D]
    float* aligned_fnirs = out + (size_t)BATCH * TF * DIMN;    // [B, TE, D]

    const int Me = BATCH * TE;
    const int Mf = BATCH * TF;

    dim3 blk(256);
    gemm_mma_kernel<<<dim3(4, Me / 128), blk>>>(eeg,   Wqe, bqe, Qe);
    gemm_mma_kernel<<<dim3(4, Me / 128), blk>>>(eeg,   Wke, bke, Ke);
    gemm_mma_kernel<<<dim3(4, Me / 128), blk>>>(eeg,   Wve, bve, Ve);
    gemm_mma_kernel<<<dim3(4, Mf / 128), blk>>>(fnirs, Wqf, bqf, Qf);
    gemm_mma_kernel<<<dim3(4, Mf / 128), blk>>>(fnirs, Wkf, bkf, Kf);
    gemm_mma_kernel<<<dim3(4, Mf / 128), blk>>>(fnirs, Wvf, bvf, Vf);

    cudaFuncSetAttribute((const void*)attn_chunk_kernel<true, true>,
                         cudaFuncAttributeMaxDynamicSharedMemorySize, ATTN_SMEM);
    cudaFuncSetAttribute((const void*)attn_chunk_kernel<false, false>,
                         cudaFuncAttributeMaxDynamicSharedMemorySize, ATTN_SMEM);

    // e2f: Q from eeg (Tq=600), K/V from fnirs (Tk=120, 1 chunk) -> aligned_fnirs
    attn_chunk_kernel<true, true><<<dim3(10, BATCH, 1), blk, ATTN_SMEM>>>(
        Qe, Kf, Vf, aligned_fnirs, nullptr, nullptr, nullptr, TE, TF);
    // f2e: Q from fnirs (Tq=120), K/V from eeg (Tk=600, 5 chunks) -> partials
    attn_chunk_kernel<false, false><<<dim3(2, BATCH, NCHUNK), blk, ATTN_SMEM>>>(
        Qf, Ke, Ve, nullptr, Opart, Mb, Lb, TF, TE);
    // merge partials -> aligned_eeg
    combine_f2e<<<dim3(TF, BATCH), dim3(128)>>>(Opart, Mb, Lb, aligned_eeg);
}

// round 7
// speedup vs baseline: 3.4865x; 1.0984x over previous
#include <cuda_runtime.h>
#include <cstdint>
#include <math.h>

#define BATCH 128
#define DIMN  512
#define TE    600
#define TF    120
#define NCHUNK 5   // f2e key chunks of 128 covering 600 keys

// ---------------- scratch (device globals; no allocation allowed) ----------------
__device__ float g_Qe[BATCH * TE * DIMN];
__device__ float g_Ke[BATCH * TE * DIMN];
__device__ float g_Ve[BATCH * TE * DIMN];
__device__ float g_Qf[BATCH * TF * DIMN];
__device__ float g_Kf[BATCH * TF * DIMN];
__device__ float g_Vf[BATCH * TF * DIMN];
__device__ float g_Opart[NCHUNK * BATCH * 128 * DIMN];  // f2e partial O
__device__ float g_M[NCHUNK * BATCH * 128];             // f2e partial row max
__device__ float g_L[NCHUNK * BATCH * 128];             // f2e partial row sum

__device__ __forceinline__ uint32_t f2tf32(float f) {
    uint32_t r; asm("cvt.rna.tf32.f32 %0, %1;" : "=r"(r) : "f"(f)); return r;
}

// m16n8k8 tf32 MMA, row.col, fp32 accumulate
__device__ __forceinline__ void mma_tf32(float* c, const uint32_t* a, const uint32_t* b) {
    asm volatile("mma.sync.aligned.m16n8k8.row.col.f32.tf32.tf32.f32 "
        "{%0,%1,%2,%3}, {%4,%5,%6,%7}, {%8,%9}, {%0,%1,%2,%3};"
        : "+f"(c[0]), "+f"(c[1]), "+f"(c[2]), "+f"(c[3])
        : "r"(a[0]), "r"(a[1]), "r"(a[2]), "r"(a[3]), "r"(b[0]), "r"(b[1]));
}

__device__ __forceinline__ void cp_async16(uint32_t dst, const void* src) {
    asm volatile("cp.async.cg.shared.global [%0], [%1], 16;" :: "r"(dst), "l"(src));
}
#define CP_COMMIT() asm volatile("cp.async.commit_group;" ::: "memory")
#define CP_WAIT1()  asm volatile("cp.async.wait_group 1;" ::: "memory")
#define CP_WAIT0()  asm volatile("cp.async.wait_group 0;" ::: "memory")

// =============== tf32 mma.sync projection GEMM, 3-stage cp.async =================
// C[M,512] = A[M,512] @ W[512,512] + b.  128x128 tile, BK=32, 16 chunks.
// Stage layout (words): A[128][36] (4608) + B[32][132] (4224) = 8832 words/stage.
#define GSTAGE_W  8832
#define GB_OFF_W  4608
#define GEMM_SMEM_BYTES (3 * GSTAGE_W * 4)   // 105,984

__global__ __launch_bounds__(256, 2)
void gemm_mma_kernel(const float* __restrict__ A, const float* __restrict__ W,
                     const float* __restrict__ bias, float* __restrict__ C)
{
    extern __shared__ float smem[];
    const uint32_t sb = (uint32_t)__cvta_generic_to_shared(smem);

    const int tid    = threadIdx.x;
    const int wid    = tid >> 5;
    const int lane   = tid & 31;
    const int warp_m = wid & 1;
    const int warp_n = wid >> 1;
    const int g      = lane >> 2;
    const int t4     = lane & 3;
    const int m0 = blockIdx.y * 128;
    const int n0 = blockIdx.x * 128;

    // per-thread staging coords
    const int am = tid >> 3, aq = (tid & 7) * 4;       // A: 32 rows per pass
    const int bk = tid >> 5, bn = (tid & 31) * 4;      // B: 8 k-rows per pass

    float acc[4][4][4];
#pragma unroll
    for (int mt = 0; mt < 4; mt++)
#pragma unroll
        for (int nt = 0; nt < 4; nt++)
#pragma unroll
            for (int r = 0; r < 4; r++) acc[mt][nt][r] = 0.f;

    // ---- async stage issue ----
    auto issue = [&](int c, int s) {
        const uint32_t stA = sb + (uint32_t)(s * GSTAGE_W) * 4;
        const uint32_t stB = sb + (uint32_t)(s * GSTAGE_W + GB_OFF_W) * 4;
#pragma unroll
        for (int i = 0; i < 4; ++i) {
            const int m = am + i * 32;
            cp_async16(stA + (uint32_t)(m * 36 + aq) * 4,
                       A + (size_t)(m0 + m) * DIMN + c * 32 + aq);
        }
#pragma unroll
        for (int i = 0; i < 4; ++i) {
            const int k = bk + i * 8;
            cp_async16(stB + (uint32_t)(k * 132 + bn) * 4,
                       W + (size_t)(c * 32 + k) * DIMN + n0 + bn);
        }
        CP_COMMIT();
    };

    issue(0, 0);
    issue(1, 1);

    for (int c = 0; c < 16; ++c) {
        const int s = c % 3;
        CP_WAIT1();            // stage c's data resident
        __syncthreads();

        const float* Af = smem + s * GSTAGE_W;
        const float* Bf = smem + s * GSTAGE_W + GB_OFF_W;
#pragma unroll
        for (int kk = 0; kk < 4; ++kk) {
            uint32_t a[4][4], b[4][2];
#pragma unroll
            for (int mt = 0; mt < 4; ++mt) {
                const int r = warp_m * 64 + mt * 16 + g;
                a[mt][0] = f2tf32(Af[r * 36 + kk * 8 + t4]);
                a[mt][1] = f2tf32(Af[(r + 8) * 36 + kk * 8 + t4]);
                a[mt][2] = f2tf32(Af[r * 36 + kk * 8 + t4 + 4]);
                a[mt][3] = f2tf32(Af[(r + 8) * 36 + kk * 8 + t4 + 4]);
            }
#pragma unroll
            for (int nt = 0; nt < 4; ++nt) {
                const int n = warp_n * 32 + nt * 8 + g;
                b[nt][0] = f2tf32(Bf[(kk * 8 + t4) * 132 + n]);
                b[nt][1] = f2tf32(Bf[(kk * 8 + t4 + 4) * 132 + n]);
            }
#pragma unroll
            for (int mt = 0; mt < 4; ++mt)
#pragma unroll
                for (int nt = 0; nt < 4; ++nt)
                    mma_tf32(acc[mt][nt], a[mt], b[nt]);
        }
        __syncthreads();       // all warps done with buffer before refill
        if (c + 2 < 16) issue(c + 2, (c + 2) % 3);
    }

#pragma unroll
    for (int mt = 0; mt < 4; ++mt) {
        const int row = m0 + warp_m * 64 + mt * 16 + g;
#pragma unroll
        for (int nt = 0; nt < 4; ++nt) {
            const int col = n0 + warp_n * 32 + nt * 8 + 2 * t4;
            const float2 bb = *(const float2*)(bias + col);
            float2 o0 = make_float2(acc[mt][nt][0] + bb.x, acc[mt][nt][1] + bb.y);
            float2 o1 = make_float2(acc[mt][nt][2] + bb.x, acc[mt][nt][3] + bb.y);
            *(float2*)(C + (size_t)row * DIMN + col)       = o0;
            *(float2*)(C + (size_t)(row + 8) * DIMN + col) = o1;
        }
    }
}

// ================= attention chunk kernel (GEMM-shaped CTA) ======================
template <bool E2F, bool FINAL>
__global__ __launch_bounds__(256, 2)
void attn_chunk_kernel(const float* __restrict__ Q, const float* __restrict__ K,
                       const float* __restrict__ V, float* __restrict__ O,
                       float* __restrict__ Opart, float* __restrict__ Mb,
                       float* __restrict__ Lb, int Tq, int Tk)
{
    extern __shared__ char smemc[];
    float*    Ss  = (float*)smemc;                        // [64][132]
    uint32_t* SsU = (uint32_t*)smemc;
    uint32_t* Qs  = (uint32_t*)(smemc + 64 * 132 * 4);    // [64][36]
    uint32_t* Ks  = Qs + 64 * 36;                         // [128][36]
    uint32_t* Vs  = Qs;                                   // [32][136] (phase-3 alias)
    float*    l_s = (float*)(smemc + 64 * 132 * 4 + (64 * 36 + 128 * 36) * 4);  // [64]

    const int tid    = threadIdx.x;
    const int wid    = tid >> 5;
    const int lane   = tid & 31;
    const int warp_m = wid & 1;
    const int warp_n = wid >> 1;
    const int g      = lane >> 2;
    const int t4     = lane & 3;
    const int q0     = blockIdx.x * 64;
    const int b      = blockIdx.y;
    const int c      = blockIdx.z;
    const float scale = 0.044194173824159216f;
    const float NEG_INF = __int_as_float(0xff800000);

    const float* Qb = Q + (size_t)b * Tq * DIMN;
    const float* Kb = K + (size_t)b * Tk * DIMN;
    const float* Vb = V + (size_t)b * Tk * DIMN;

    float acc[2][4][4];
#pragma unroll
    for (int mt = 0; mt < 2; mt++)
#pragma unroll
        for (int nt = 0; nt < 4; nt++)
#pragma unroll
            for (int r = 0; r < 4; r++) acc[mt][nt][r] = 0.f;

    for (int k0 = 0; k0 < DIMN; k0 += 32) {
        __syncthreads();
#pragma unroll
        for (int i = 0; i < 2; ++i) {
            const int lin = i * 256 + tid;
            const int m = lin >> 3, q4 = lin & 7;
            float4 v = make_float4(0.f, 0.f, 0.f, 0.f);
            if (q0 + m < Tq)
                v = *(const float4*)(Qb + (size_t)(q0 + m) * DIMN + k0 + q4 * 4);
            uint32_t* p = &Qs[m * 36 + q4 * 4];
            p[0] = f2tf32(v.x); p[1] = f2tf32(v.y); p[2] = f2tf32(v.z); p[3] = f2tf32(v.w);
        }
#pragma unroll
        for (int i = 0; i < 4; ++i) {
            const int lin = i * 256 + tid;
            const int kl = lin >> 3, q4 = lin & 7;
            const int key = c * 128 + kl;
            float4 v = make_float4(0.f, 0.f, 0.f, 0.f);
            if (key < Tk)
                v = *(const float4*)(Kb + (size_t)key * DIMN + k0 + q4 * 4);
            uint32_t* p = &Ks[kl * 36 + q4 * 4];
            p[0] = f2tf32(v.x); p[1] = f2tf32(v.y); p[2] = f2tf32(v.z); p[3] = f2tf32(v.w);
        }
        __syncthreads();
#pragma unroll
        for (int kk = 0; kk < 4; ++kk) {
            uint32_t a[2][4], bb[4][2];
#pragma unroll
            for (int mt = 0; mt < 2; ++mt) {
                const int r = warp_m * 32 + mt * 16 + g;
                a[mt][0] = Qs[r * 36 + kk * 8 + t4];
                a[mt][1] = Qs[(r + 8) * 36 + kk * 8 + t4];
                a[mt][2] = Qs[r * 36 + kk * 8 + t4 + 4];
                a[mt][3] = Qs[(r + 8) * 36 + kk * 8 + t4 + 4];
            }
#pragma unroll
            for (int nt = 0; nt < 4; ++nt) {
                const int n = warp_n * 32 + nt * 8 + g;
                bb[nt][0] = Ks[n * 36 + kk * 8 + t4];
                bb[nt][1] = Ks[n * 36 + kk * 8 + t4 + 4];
            }
#pragma unroll
            for (int mt = 0; mt < 2; ++mt)
#pragma unroll
                for (int nt = 0; nt < 4; ++nt)
                    mma_tf32(acc[mt][nt], a[mt], bb[nt]);
        }
    }
#pragma unroll
    for (int mt = 0; mt < 2; ++mt) {
#pragma unroll
        for (int half = 0; half < 2; ++half) {
            const int row = warp_m * 32 + mt * 16 + half * 8 + g;
            const int q   = q0 + row;
            const int j0g = q / 20;
#pragma unroll
            for (int nt = 0; nt < 4; ++nt) {
                const int colc = warp_n * 32 + nt * 8 + 2 * t4;
                float vout[2];
#pragma unroll
                for (int e = 0; e < 2; ++e) {
                    const int key = c * 128 + colc + e;
                    float val;
                    if (key >= Tk) val = NEG_INF;
                    else {
                        bool valid;
                        if (E2F) valid = (key >= j0g + 20) && (key <= j0g + 80);
                        else { const int gg = key / 20; valid = (q >= gg + 20) && (q <= gg + 80); }
                        val = valid ? acc[mt][nt][half * 2 + e] * scale : -1e9f;
                    }
                    vout[e] = val;
                }
                *(float2*)&Ss[row * 132 + colc] = make_float2(vout[0], vout[1]);
            }
        }
    }
    __syncthreads();

    {
        const int row  = tid >> 2;
        const int part = tid & 3;
        float* srow = Ss + row * 132;

        float mx = NEG_INF;
#pragma unroll
        for (int i = 0; i < 32; ++i) mx = fmaxf(mx, srow[part + i * 4]);
        mx = fmaxf(mx, __shfl_xor_sync(0xffffffffu, mx, 1));
        mx = fmaxf(mx, __shfl_xor_sync(0xffffffffu, mx, 2));
        float sum = 0.f;
        uint32_t* urow = SsU + row * 132;
#pragma unroll
        for (int i = 0; i < 32; ++i) {
            const int cc = part + i * 4;
            const float e = __expf(srow[cc] - mx);
            sum += e;
            urow[cc] = f2tf32(e);
        }
        sum += __shfl_xor_sync(0xffffffffu, sum, 1);
        sum += __shfl_xor_sync(0xffffffffu, sum, 2);
        if (part == 0) {
            l_s[row] = sum;
            if (!FINAL) {
                const int idx = (c * BATCH + b) * 128 + q0 + row;
                Mb[idx] = mx;
                Lb[idx] = sum;
            }
        }
    }
    __syncthreads();

    for (int nc = 0; nc < 4; ++nc) {
        float oacc[2][4][4];
#pragma unroll
        for (int mt = 0; mt < 2; mt++)
#pragma unroll
            for (int nt = 0; nt < 4; nt++)
#pragma unroll
                for (int r = 0; r < 4; r++) oacc[mt][nt][r] = 0.f;

        for (int ks = 0; ks < 4; ++ks) {
            __syncthreads();
#pragma unroll
            for (int i = 0; i < 4; ++i) {
                const int lin = i * 256 + tid;
                const int kl = lin >> 5, c4 = lin & 31;
                const int key = c * 128 + ks * 32 + kl;
                float4 v = make_float4(0.f, 0.f, 0.f, 0.f);
                if (key < Tk)
                    v = *(const float4*)(Vb + (size_t)key * DIMN + nc * 128 + c4 * 4);
                uint32_t* p = &Vs[kl * 136 + c4 * 4];
                p[0] = f2tf32(v.x); p[1] = f2tf32(v.y); p[2] = f2tf32(v.z); p[3] = f2tf32(v.w);
            }
            __syncthreads();
#pragma unroll
            for (int kk = 0; kk < 4; ++kk) {
                uint32_t a[2][4], bb[4][2];
#pragma unroll
                for (int mt = 0; mt < 2; ++mt) {
                    const int r = warp_m * 32 + mt * 16 + g;
                    const int col = ks * 32 + kk * 8 + t4;
                    a[mt][0] = SsU[r * 132 + col];
                    a[mt][1] = SsU[(r + 8) * 132 + col];
                    a[mt][2] = SsU[r * 132 + col + 4];
                    a[mt][3] = SsU[(r + 8) * 132 + col + 4];
                }
#pragma unroll
                for (int nt = 0; nt < 4; ++nt) {
                    const int n = warp_n * 32 + nt * 8 + g;
                    bb[nt][0] = Vs[(kk * 8 + t4) * 136 + n];
                    bb[nt][1] = Vs[(kk * 8 + t4 + 4) * 136 + n];
                }
#pragma unroll
                for (int mt = 0; mt < 2; ++mt)
#pragma unroll
                    for (int nt = 0; nt < 4; ++nt)
                        mma_tf32(oacc[mt][nt], a[mt], bb[nt]);
            }
        }
#pragma unroll
        for (int mt = 0; mt < 2; ++mt) {
#pragma unroll
            for (int half = 0; half < 2; ++half) {
                const int row = warp_m * 32 + mt * 16 + half * 8 + g;
                const int q   = q0 + row;
#pragma unroll
                for (int nt = 0; nt < 4; ++nt) {
                    const int col = nc * 128 + warp_n * 32 + nt * 8 + 2 * t4;
                    const float v0 = oacc[mt][nt][half * 2 + 0];
                    const float v1 = oacc[mt][nt][half * 2 + 1];
                    if (FINAL) {
                        if (q < Tq) {
                            const float inv = 1.f / l_s[row];
                            *(float2*)(O + ((size_t)b * Tq + q) * DIMN + col) =
                                make_float2(v0 * inv, v1 * inv);
                        }
                    } else {
                        float* dst = Opart + (((size_t)c * BATCH + b) * 128 + q) * DIMN + col;
                        *(float2*)dst = make_float2(v0, v1);
                    }
                }
            }
        }
    }
}

// ----------------- f2e combine: merge 5 chunk partials per row -------------------
__global__ void combine_f2e(const float* __restrict__ Opart,
                            const float* __restrict__ Mb, const float* __restrict__ Lb,
                            float* __restrict__ O)
{
    const int q = blockIdx.x;
    const int b = blockIdx.y;
    const int t = threadIdx.x;
    float m[NCHUNK], w[NCHUNK];
    float M = __int_as_float(0xff800000);
#pragma unroll
    for (int c = 0; c < NCHUNK; ++c) {
        m[c] = Mb[(c * BATCH + b) * 128 + q];
        M = fmaxf(M, m[c]);
    }
    float den = 0.f;
#pragma unroll
    for (int c = 0; c < NCHUNK; ++c) {
        w[c] = __expf(m[c] - M);
        den += w[c] * Lb[(c * BATCH + b) * 128 + q];
    }
    const float inv = 1.f / den;
    float4 o = make_float4(0.f, 0.f, 0.f, 0.f);
#pragma unroll
    for (int c = 0; c < NCHUNK; ++c) {
        const float4 p = *(const float4*)(Opart + (((size_t)c * BATCH + b) * 128 + q) * DIMN + t * 4);
        const float s = w[c] * inv;
        o.x += s * p.x; o.y += s * p.y; o.z += s * p.z; o.w += s * p.w;
    }
    *(float4*)(O + ((size_t)b * TF + q) * DIMN + t * 4) = o;
}

static const int ATTN_SMEM = 64 * 132 * 4 + (64 * 36 + 128 * 36) * 4 + 64 * 4;  // 61,952

extern "C" void kernel_launch(void* const* d_in, const int* in_sizes, int n_in,
                              void* d_out, int out_size)
{
    (void)in_sizes; (void)n_in; (void)out_size;

    const float* eeg   = (const float*)d_in[0];
    const float* fnirs = (const float*)d_in[1];
    const float* Wqe = (const float*)d_in[2];
    const float* bqe = (const float*)d_in[3];
    const float* Wke = (const float*)d_in[4];
    const float* bke = (const float*)d_in[5];
    const float* Wve = (const float*)d_in[6];
    const float* bve = (const float*)d_in[7];
    const float* Wqf = (const float*)d_in[8];
    const float* bqf = (const float*)d_in[9];
    const float* Wkf = (const float*)d_in[10];
    const float* bkf = (const float*)d_in[11];
    const float* Wvf = (const float*)d_in[12];
    const float* bvf = (const float*)d_in[13];

    float *Qe, *Ke, *Ve, *Qf, *Kf, *Vf, *Opart, *Mb, *Lb;
    cudaGetSymbolAddress((void**)&Qe, g_Qe);
    cudaGetSymbolAddress((void**)&Ke, g_Ke);
    cudaGetSymbolAddress((void**)&Ve, g_Ve);
    cudaGetSymbolAddress((void**)&Qf, g_Qf);
    cudaGetSymbolAddress((void**)&Kf, g_Kf);
    cudaGetSymbolAddress((void**)&Vf, g_Vf);
    cudaGetSymbolAddress((void**)&Opart, g_Opart);
    cudaGetSymbolAddress((void**)&Mb, g_M);
    cudaGetSymbolAddress((void**)&Lb, g_L);

    float* out           = (float*)d_out;
    float* aligned_eeg   = out;                                // [B, TF, D]
    float* aligned_fnirs = out + (size_t)BATCH * TF * DIMN;    // [B, TE, D]

    const int Me = BATCH * TE;
    const int Mf = BATCH * TF;

    cudaFuncSetAttribute(gemm_mma_kernel,
                         cudaFuncAttributeMaxDynamicSharedMemorySize, GEMM_SMEM_BYTES);

    dim3 blk(256);
    gemm_mma_kernel<<<dim3(4, Me / 128), blk, GEMM_SMEM_BYTES>>>(eeg,   Wqe, bqe, Qe);
    gemm_mma_kernel<<<dim3(4, Me / 128), blk, GEMM_SMEM_BYTES>>>(eeg,   Wke, bke, Ke);
    gemm_mma_kernel<<<dim3(4, Me / 128), blk, GEMM_SMEM_BYTES>>>(eeg,   Wve, bve, Ve);
    gemm_mma_kernel<<<dim3(4, Mf / 128), blk, GEMM_SMEM_BYTES>>>(fnirs, Wqf, bqf, Qf);
    gemm_mma_kernel<<<dim3(4, Mf / 128), blk, GEMM_SMEM_BYTES>>>(fnirs, Wkf, bkf, Kf);
    gemm_mma_kernel<<<dim3(4, Mf / 128), blk, GEMM_SMEM_BYTES>>>(fnirs, Wvf, bvf, Vf);

    cudaFuncSetAttribute((const void*)attn_chunk_kernel<true, true>,
                         cudaFuncAttributeMaxDynamicSharedMemorySize, ATTN_SMEM);
    cudaFuncSetAttribute((const void*)attn_chunk_kernel<false, false>,
                         cudaFuncAttributeMaxDynamicSharedMemorySize, ATTN_SMEM);

    attn_chunk_kernel<true, true><<<dim3(10, BATCH, 1), blk, ATTN_SMEM>>>(
        Qe, Kf, Vf, aligned_fnirs, nullptr, nullptr, nullptr, TE, TF);
    attn_chunk_kernel<false, false><<<dim3(2, BATCH, NCHUNK), blk, ATTN_SMEM>>>(
        Qf, Ke, Ve, nullptr, Opart, Mb, Lb, TF, TE);
    combine_f2e<<<dim3(TF, BATCH), dim3(128)>>>(Opart, Mb, Lb, aligned_eeg);
}

// round 9
// speedup vs baseline: 3.6569x; 1.0489x over previous
#include <cuda_runtime.h>
#include <cstdint>
#include <math.h>

#define BATCH 128
#define DIMN  512
#define TE    600
#define TF    120
#define NCHUNK 5   // f2e key chunks of 128 covering 600 keys

// ---------------- scratch (device globals; no allocation allowed) ----------------
__device__ uint32_t g_Ae[BATCH * TE * DIMN];   // eeg as tf32 bits
__device__ uint32_t g_Af[BATCH * TF * DIMN];   // fnirs as tf32 bits
__device__ uint32_t g_Wc[6 * DIMN * DIMN];     // 6 weight matrices as tf32 bits
__device__ uint32_t g_Qe[BATCH * TE * DIMN];   // projections as tf32 bits
__device__ uint32_t g_Ke[BATCH * TE * DIMN];
__device__ uint32_t g_Ve[BATCH * TE * DIMN];
__device__ uint32_t g_Qf[BATCH * TF * DIMN];
__device__ uint32_t g_Kf[BATCH * TF * DIMN];
__device__ uint32_t g_Vf[BATCH * TF * DIMN];
__device__ float g_Opart[NCHUNK * BATCH * 128 * DIMN];  // f2e partial O
__device__ float g_M[NCHUNK * BATCH * 128];             // f2e partial row max
__device__ float g_L[NCHUNK * BATCH * 128];             // f2e partial row sum

__device__ __forceinline__ uint32_t f2tf32(float f) {
    uint32_t r; asm("cvt.rna.tf32.f32 %0, %1;" : "=r"(r) : "f"(f)); return r;
}

// m16n8k8 tf32 MMA, row.col, fp32 accumulate
__device__ __forceinline__ void mma_tf32(float* c, const uint32_t* a, const uint32_t* b) {
    asm volatile("mma.sync.aligned.m16n8k8.row.col.f32.tf32.tf32.f32 "
        "{%0,%1,%2,%3}, {%4,%5,%6,%7}, {%8,%9}, {%0,%1,%2,%3};"
        : "+f"(c[0]), "+f"(c[1]), "+f"(c[2]), "+f"(c[3])
        : "r"(a[0]), "r"(a[1]), "r"(a[2]), "r"(a[3]), "r"(b[0]), "r"(b[1]));
}

__device__ __forceinline__ void cp_async16(uint32_t dst, const void* src) {
    asm volatile("cp.async.cg.shared.global [%0], [%1], 16;" :: "r"(dst), "l"(src));
}
#define CP_COMMIT() asm volatile("cp.async.commit_group;" ::: "memory")
#define CP_WAIT1()  asm volatile("cp.async.wait_group 1;" ::: "memory")

// ---------------- fp32 -> tf32-bits conversion (elementwise) ---------------------
__global__ void cvt_kernel(const float* __restrict__ src, uint32_t* __restrict__ dst, int n)
{
    const int i = (blockIdx.x * 256 + threadIdx.x) * 4;
    if (i < n) {
        const float4 v = *(const float4*)(src + i);
        uint4 o;
        o.x = f2tf32(v.x); o.y = f2tf32(v.y); o.z = f2tf32(v.z); o.w = f2tf32(v.w);
        *(uint4*)(dst + i) = o;
    }
}

// =============== tf32 mma.sync projection GEMM, 3-stage cp.async =================
// Fused over 3 weight sets: blockIdx.x in [0,12): w = x>>2, n0 = (x&3)*128.
// Mainloop is pure LDS->MMA (operands pre-converted to tf32 bits).
#define GSTAGE_W  8832
#define GB_OFF_W  4608
#define GEMM_SMEM_BYTES (3 * GSTAGE_W * 4)   // 105,984

__global__ __launch_bounds__(256, 2)
void gemm_mma_kernel(const uint32_t* __restrict__ A, const uint32_t* __restrict__ Wc,
                     const float* __restrict__ b0, const float* __restrict__ b1,
                     const float* __restrict__ b2,
                     uint32_t* __restrict__ C0, uint32_t* __restrict__ C1,
                     uint32_t* __restrict__ C2)
{
    extern __shared__ uint32_t smem[];
    const uint32_t sb = (uint32_t)__cvta_generic_to_shared(smem);

    const int tid    = threadIdx.x;
    const int wid    = tid >> 5;
    const int lane   = tid & 31;
    const int warp_m = wid & 1;
    const int warp_n = wid >> 1;
    const int g      = lane >> 2;
    const int t4     = lane & 3;
    const int wsel = blockIdx.x >> 2;
    const int n0   = (blockIdx.x & 3) * 128;
    const int m0   = blockIdx.y * 128;

    const uint32_t* W = Wc + (size_t)wsel * DIMN * DIMN;
    const float* bias = (wsel == 0) ? b0 : (wsel == 1) ? b1 : b2;
    uint32_t* C       = (wsel == 0) ? C0 : (wsel == 1) ? C1 : C2;

    const int am = tid >> 3, aq = (tid & 7) * 4;
    const int bk = tid >> 5, bn = (tid & 31) * 4;

    float acc[4][4][4];
#pragma unroll
    for (int mt = 0; mt < 4; mt++)
#pragma unroll
        for (int nt = 0; nt < 4; nt++)
#pragma unroll
            for (int r = 0; r < 4; r++) acc[mt][nt][r] = 0.f;

    auto issue = [&](int c, int s) {
        const uint32_t stA = sb + (uint32_t)(s * GSTAGE_W) * 4;
        const uint32_t stB = sb + (uint32_t)(s * GSTAGE_W + GB_OFF_W) * 4;
#pragma unroll
        for (int i = 0; i < 4; ++i) {
            const int m = am + i * 32;
            cp_async16(stA + (uint32_t)(m * 36 + aq) * 4,
                       A + (size_t)(m0 + m) * DIMN + c * 32 + aq);
        }
#pragma unroll
        for (int i = 0; i < 4; ++i) {
            const int k = bk + i * 8;
            cp_async16(stB + (uint32_t)(k * 132 + bn) * 4,
                       W + (size_t)(c * 32 + k) * DIMN + n0 + bn);
        }
        CP_COMMIT();
    };

    issue(0, 0);
    issue(1, 1);

    for (int c = 0; c < 16; ++c) {
        const int s = c % 3;
        CP_WAIT1();
        __syncthreads();
        if (c + 2 < 16) issue(c + 2, (c + 2) % 3);

        const uint32_t* Af = smem + s * GSTAGE_W;
        const uint32_t* Bf = smem + s * GSTAGE_W + GB_OFF_W;
#pragma unroll
        for (int kk = 0; kk < 4; ++kk) {
            uint32_t a[4][4], b[4][2];
#pragma unroll
            for (int mt = 0; mt < 4; ++mt) {
                const int r = warp_m * 64 + mt * 16 + g;
                a[mt][0] = Af[r * 36 + kk * 8 + t4];
                a[mt][1] = Af[(r + 8) * 36 + kk * 8 + t4];
                a[mt][2] = Af[r * 36 + kk * 8 + t4 + 4];
                a[mt][3] = Af[(r + 8) * 36 + kk * 8 + t4 + 4];
            }
#pragma unroll
            for (int nt = 0; nt < 4; ++nt) {
                const int n = warp_n * 32 + nt * 8 + g;
                b[nt][0] = Bf[(kk * 8 + t4) * 132 + n];
                b[nt][1] = Bf[(kk * 8 + t4 + 4) * 132 + n];
            }
#pragma unroll
            for (int mt = 0; mt < 4; ++mt)
#pragma unroll
                for (int nt = 0; nt < 4; ++nt)
                    mma_tf32(acc[mt][nt], a[mt], b[nt]);
        }
    }

    // epilogue: bias add in fp32, store as tf32 bits (consumed by attention)
#pragma unroll
    for (int mt = 0; mt < 4; ++mt) {
        const int row = m0 + warp_m * 64 + mt * 16 + g;
#pragma unroll
        for (int nt = 0; nt < 4; ++nt) {
            const int col = n0 + warp_n * 32 + nt * 8 + 2 * t4;
            const float2 bb = *(const float2*)(bias + col);
            uint2 o0 = make_uint2(f2tf32(acc[mt][nt][0] + bb.x), f2tf32(acc[mt][nt][1] + bb.y));
            uint2 o1 = make_uint2(f2tf32(acc[mt][nt][2] + bb.x), f2tf32(acc[mt][nt][3] + bb.y));
            *(uint2*)(C + (size_t)row * DIMN + col)       = o0;
            *(uint2*)(C + (size_t)(row + 8) * DIMN + col) = o1;
        }
    }
}

// ================= attention chunk kernel (GEMM-shaped CTA) ======================
// Operands are tf32 bits already: staging is raw uint4 copies, no CVT in loops.
template <bool E2F, bool FINAL>
__global__ __launch_bounds__(256, 2)
void attn_chunk_kernel(const uint32_t* __restrict__ Q, const uint32_t* __restrict__ K,
                       const uint32_t* __restrict__ V, float* __restrict__ O,
                       float* __restrict__ Opart, float* __restrict__ Mb,
                       float* __restrict__ Lb, int Tq, int Tk)
{
    extern __shared__ char smemc[];
    float*    Ss  = (float*)smemc;                        // [64][132]
    uint32_t* SsU = (uint32_t*)smemc;
    uint32_t* Qs  = (uint32_t*)(smemc + 64 * 132 * 4);    // [64][36]
    uint32_t* Ks  = Qs + 64 * 36;                         // [128][36]
    uint32_t* Vs  = Qs;                                   // [32][136] (phase-3 alias)
    float*    l_s = (float*)(smemc + 64 * 132 * 4 + (64 * 36 + 128 * 36) * 4);  // [64]

    const int tid    = threadIdx.x;
    const int wid    = tid >> 5;
    const int lane   = tid & 31;
    const int warp_m = wid & 1;
    const int warp_n = wid >> 1;
    const int g      = lane >> 2;
    const int t4     = lane & 3;
    const int q0     = blockIdx.x * 64;
    const int b      = blockIdx.y;
    const int c      = blockIdx.z;
    const float scale = 0.044194173824159216f;
    const float NEG_INF = __int_as_float(0xff800000);

    const uint32_t* Qb = Q + (size_t)b * Tq * DIMN;
    const uint32_t* Kb = K + (size_t)b * Tk * DIMN;
    const uint32_t* Vb = V + (size_t)b * Tk * DIMN;

    float acc[2][4][4];
#pragma unroll
    for (int mt = 0; mt < 2; mt++)
#pragma unroll
        for (int nt = 0; nt < 4; nt++)
#pragma unroll
            for (int r = 0; r < 4; r++) acc[mt][nt][r] = 0.f;

    for (int k0 = 0; k0 < DIMN; k0 += 32) {
        __syncthreads();
#pragma unroll
        for (int i = 0; i < 2; ++i) {                // Q: 64 rows x 32 k, raw copy
            const int lin = i * 256 + tid;
            const int m = lin >> 3, q4 = lin & 7;
            uint4 v = make_uint4(0u, 0u, 0u, 0u);
            if (q0 + m < Tq)
                v = *(const uint4*)(Qb + (size_t)(q0 + m) * DIMN + k0 + q4 * 4);
            *(uint4*)&Qs[m * 36 + q4 * 4] = v;
        }
#pragma unroll
        for (int i = 0; i < 4; ++i) {                // K: 128 keys x 32 k, raw copy
            const int lin = i * 256 + tid;
            const int kl = lin >> 3, q4 = lin & 7;
            const int key = c * 128 + kl;
            uint4 v = make_uint4(0u, 0u, 0u, 0u);
            if (key < Tk)
                v = *(const uint4*)(Kb + (size_t)key * DIMN + k0 + q4 * 4);
            *(uint4*)&Ks[kl * 36 + q4 * 4] = v;
        }
        __syncthreads();
#pragma unroll
        for (int kk = 0; kk < 4; ++kk) {
            uint32_t a[2][4], bb[4][2];
#pragma unroll
            for (int mt = 0; mt < 2; ++mt) {
                const int r = warp_m * 32 + mt * 16 + g;
                a[mt][0] = Qs[r * 36 + kk * 8 + t4];
                a[mt][1] = Qs[(r + 8) * 36 + kk * 8 + t4];
                a[mt][2] = Qs[r * 36 + kk * 8 + t4 + 4];
                a[mt][3] = Qs[(r + 8) * 36 + kk * 8 + t4 + 4];
            }
#pragma unroll
            for (int nt = 0; nt < 4; ++nt) {
                const int n = warp_n * 32 + nt * 8 + g;
                bb[nt][0] = Ks[n * 36 + kk * 8 + t4];
                bb[nt][1] = Ks[n * 36 + kk * 8 + t4 + 4];
            }
#pragma unroll
            for (int mt = 0; mt < 2; ++mt)
#pragma unroll
                for (int nt = 0; nt < 4; ++nt)
                    mma_tf32(acc[mt][nt], a[mt], bb[nt]);
        }
    }
#pragma unroll
    for (int mt = 0; mt < 2; ++mt) {
#pragma unroll
        for (int half = 0; half < 2; ++half) {
            const int row = warp_m * 32 + mt * 16 + half * 8 + g;
            const int q   = q0 + row;
            const int j0g = q / 20;
#pragma unroll
            for (int nt = 0; nt < 4; ++nt) {
                const int colc = warp_n * 32 + nt * 8 + 2 * t4;
                float vout[2];
#pragma unroll
                for (int e = 0; e < 2; ++e) {
                    const int key = c * 128 + colc + e;
                    float val;
                    if (key >= Tk) val = NEG_INF;
                    else {
                        bool valid;
                        if (E2F) valid = (key >= j0g + 20) && (key <= j0g + 80);
                        else { const int gg = key / 20; valid = (q >= gg + 20) && (q <= gg + 80); }
                        val = valid ? acc[mt][nt][half * 2 + e] * scale : -1e9f;
                    }
                    vout[e] = val;
                }
                *(float2*)&Ss[row * 132 + colc] = make_float2(vout[0], vout[1]);
            }
        }
    }
    __syncthreads();

    {
        const int row  = tid >> 2;
        const int part = tid & 3;
        float* srow = Ss + row * 132;

        float mx = NEG_INF;
#pragma unroll
        for (int i = 0; i < 32; ++i) mx = fmaxf(mx, srow[part + i * 4]);
        mx = fmaxf(mx, __shfl_xor_sync(0xffffffffu, mx, 1));
        mx = fmaxf(mx, __shfl_xor_sync(0xffffffffu, mx, 2));
        float sum = 0.f;
        uint32_t* urow = SsU + row * 132;
#pragma unroll
        for (int i = 0; i < 32; ++i) {
            const int cc = part + i * 4;
            const float e = __expf(srow[cc] - mx);
            sum += e;
            urow[cc] = f2tf32(e);
        }
        sum += __shfl_xor_sync(0xffffffffu, sum, 1);
        sum += __shfl_xor_sync(0xffffffffu, sum, 2);
        if (part == 0) {
            l_s[row] = sum;
            if (!FINAL) {
                const int idx = (c * BATCH + b) * 128 + q0 + row;
                Mb[idx] = mx;
                Lb[idx] = sum;
            }
        }
    }
    __syncthreads();

    for (int nc = 0; nc < 4; ++nc) {
        float oacc[2][4][4];
#pragma unroll
        for (int mt = 0; mt < 2; mt++)
#pragma unroll
            for (int nt = 0; nt < 4; nt++)
#pragma unroll
                for (int r = 0; r < 4; r++) oacc[mt][nt][r] = 0.f;

        for (int ks = 0; ks < 4; ++ks) {
            __syncthreads();
#pragma unroll
            for (int i = 0; i < 4; ++i) {            // V: 32 keys x 128 cols, raw copy
                const int lin = i * 256 + tid;
                const int kl = lin >> 5, c4 = lin & 31;
                const int key = c * 128 + ks * 32 + kl;
                uint4 v = make_uint4(0u, 0u, 0u, 0u);
                if (key < Tk)
                    v = *(const uint4*)(Vb + (size_t)key * DIMN + nc * 128 + c4 * 4);
                *(uint4*)&Vs[kl * 136 + c4 * 4] = v;
            }
            __syncthreads();
#pragma unroll
            for (int kk = 0; kk < 4; ++kk) {
                uint32_t a[2][4], bb[4][2];
#pragma unroll
                for (int mt = 0; mt < 2; ++mt) {
                    const int r = warp_m * 32 + mt * 16 + g;
                    const int col = ks * 32 + kk * 8 + t4;
                    a[mt][0] = SsU[r * 132 + col];
                    a[mt][1] = SsU[(r + 8) * 132 + col];
                    a[mt][2] = SsU[r * 132 + col + 4];
                    a[mt][3] = SsU[(r + 8) * 132 + col + 4];
                }
#pragma unroll
                for (int nt = 0; nt < 4; ++nt) {
                    const int n = warp_n * 32 + nt * 8 + g;
                    bb[nt][0] = Vs[(kk * 8 + t4) * 136 + n];
                    bb[nt][1] = Vs[(kk * 8 + t4 + 4) * 136 + n];
                }
#pragma unroll
                for (int mt = 0; mt < 2; ++mt)
#pragma unroll
                    for (int nt = 0; nt < 4; ++nt)
                        mma_tf32(oacc[mt][nt], a[mt], bb[nt]);
            }
        }
#pragma unroll
        for (int mt = 0; mt < 2; ++mt) {
#pragma unroll
            for (int half = 0; half < 2; ++half) {
                const int row = warp_m * 32 + mt * 16 + half * 8 + g;
                const int q   = q0 + row;
#pragma unroll
                for (int nt = 0; nt < 4; ++nt) {
                    const int col = nc * 128 + warp_n * 32 + nt * 8 + 2 * t4;
                    const float v0 = oacc[mt][nt][half * 2 + 0];
                    const float v1 = oacc[mt][nt][half * 2 + 1];
                    if (FINAL) {
                        if (q < Tq) {
                            const float inv = 1.f / l_s[row];
                            *(float2*)(O + ((size_t)b * Tq + q) * DIMN + col) =
                                make_float2(v0 * inv, v1 * inv);
                        }
                    } else {
                        float* dst = Opart + (((size_t)c * BATCH + b) * 128 + q) * DIMN + col;
                        *(float2*)dst = make_float2(v0, v1);
                    }
                }
            }
        }
    }
}

// ----------------- f2e combine: merge 5 chunk partials per row -------------------
__global__ void combine_f2e(const float* __restrict__ Opart,
                            const float* __restrict__ Mb, const float* __restrict__ Lb,
                            float* __restrict__ O)
{
    const int q = blockIdx.x;
    const int b = blockIdx.y;
    const int t = threadIdx.x;
    float m[NCHUNK], w[NCHUNK];
    float M = __int_as_float(0xff800000);
#pragma unroll
    for (int c = 0; c < NCHUNK; ++c) {
        m[c] = Mb[(c * BATCH + b) * 128 + q];
        M = fmaxf(M, m[c]);
    }
    float den = 0.f;
#pragma unroll
    for (int c = 0; c < NCHUNK; ++c) {
        w[c] = __expf(m[c] - M);
        den += w[c] * Lb[(c * BATCH + b) * 128 + q];
    }
    const float inv = 1.f / den;
    float4 o = make_float4(0.f, 0.f, 0.f, 0.f);
#pragma unroll
    for (int c = 0; c < NCHUNK; ++c) {
        const float4 p = *(const float4*)(Opart + (((size_t)c * BATCH + b) * 128 + q) * DIMN + t * 4);
        const float s = w[c] * inv;
        o.x += s * p.x; o.y += s * p.y; o.z += s * p.z; o.w += s * p.w;
    }
    *(float4*)(O + ((size_t)b * TF + q) * DIMN + t * 4) = o;
}

static const int ATTN_SMEM = 64 * 132 * 4 + (64 * 36 + 128 * 36) * 4 + 64 * 4;  // 61,952

extern "C" void kernel_launch(void* const* d_in, const int* in_sizes, int n_in,
                              void* d_out, int out_size)
{
    (void)in_sizes; (void)n_in; (void)out_size;

    const float* eeg   = (const float*)d_in[0];
    const float* fnirs = (const float*)d_in[1];
    const float* Wqe = (const float*)d_in[2];
    const float* bqe = (const float*)d_in[3];
    const float* Wke = (const float*)d_in[4];
    const float* bke = (const float*)d_in[5];
    const float* Wve = (const float*)d_in[6];
    const float* bve = (const float*)d_in[7];
    const float* Wqf = (const float*)d_in[8];
    const float* bqf = (const float*)d_in[9];
    const float* Wkf = (const float*)d_in[10];
    const float* bkf = (const float*)d_in[11];
    const float* Wvf = (const float*)d_in[12];
    const float* bvf = (const float*)d_in[13];

    uint32_t *Ae, *Af, *Wc, *Qe, *Ke, *Ve, *Qf, *Kf, *Vf;
    float *Opart, *Mb, *Lb;
    cudaGetSymbolAddress((void**)&Ae, g_Ae);
    cudaGetSymbolAddress((void**)&Af, g_Af);
    cudaGetSymbolAddress((void**)&Wc, g_Wc);
    cudaGetSymbolAddress((void**)&Qe, g_Qe);
    cudaGetSymbolAddress((void**)&Ke, g_Ke);
    cudaGetSymbolAddress((void**)&Ve, g_Ve);
    cudaGetSymbolAddress((void**)&Qf, g_Qf);
    cudaGetSymbolAddress((void**)&Kf, g_Kf);
    cudaGetSymbolAddress((void**)&Vf, g_Vf);
    cudaGetSymbolAddress((void**)&Opart, g_Opart);
    cudaGetSymbolAddress((void**)&Mb, g_M);
    cudaGetSymbolAddress((void**)&Lb, g_L);

    float* out           = (float*)d_out;
    float* aligned_eeg   = out;                                // [B, TF, D]
    float* aligned_fnirs = out + (size_t)BATCH * TF * DIMN;    // [B, TE, D]

    const int Me = BATCH * TE;
    const int Mf = BATCH * TF;
    const int NW = DIMN * DIMN;

    // ---- stage 0: convert inputs to tf32 bits
    const int ne = Me * DIMN, nf = Mf * DIMN;
    cvt_kernel<<<(ne / 4 + 255) / 256, 256>>>(eeg,   Ae, ne);
    cvt_kernel<<<(nf / 4 + 255) / 256, 256>>>(fnirs, Af, nf);
    cvt_kernel<<<(NW / 4 + 255) / 256, 256>>>(Wqe, Wc + 0 * (size_t)NW, NW);
    cvt_kernel<<<(NW / 4 + 255) / 256, 256>>>(Wke, Wc + 1 * (size_t)NW, NW);
    cvt_kernel<<<(NW / 4 + 255) / 256, 256>>>(Wve, Wc + 2 * (size_t)NW, NW);
    cvt_kernel<<<(NW / 4 + 255) / 256, 256>>>(Wqf, Wc + 3 * (size_t)NW, NW);
    cvt_kernel<<<(NW / 4 + 255) / 256, 256>>>(Wkf, Wc + 4 * (size_t)NW, NW);
    cvt_kernel<<<(NW / 4 + 255) / 256, 256>>>(Wvf, Wc + 5 * (size_t)NW, NW);

    cudaFuncSetAttribute(gemm_mma_kernel,
                         cudaFuncAttributeMaxDynamicSharedMemorySize, GEMM_SMEM_BYTES);

    dim3 blk(256);
    // ---- stage 1: fused projections (3 weight sets per launch)
    gemm_mma_kernel<<<dim3(12, Me / 128), blk, GEMM_SMEM_BYTES>>>(
        Ae, Wc, bqe, bke, bve, Qe, Ke, Ve);
    gemm_mma_kernel<<<dim3(12, Mf / 128), blk, GEMM_SMEM_BYTES>>>(
        Af, Wc + 3 * (size_t)NW, bqf, bkf, bvf, Qf, Kf, Vf);

    cudaFuncSetAttribute((const void*)attn_chunk_kernel<true, true>,
                         cudaFuncAttributeMaxDynamicSharedMemorySize, ATTN_SMEM);
    cudaFuncSetAttribute((const void*)attn_chunk_kernel<false, false>,
                         cudaFuncAttributeMaxDynamicSharedMemorySize, ATTN_SMEM);

    // ---- stage 2: attention
    attn_chunk_kernel<true, true><<<dim3(10, BATCH, 1), blk, ATTN_SMEM>>>(
        Qe, Kf, Vf, aligned_fnirs, nullptr, nullptr, nullptr, TE, TF);
    attn_chunk_kernel<false, false><<<dim3(2, BATCH, NCHUNK), blk, ATTN_SMEM>>>(
        Qf, Ke, Ve, nullptr, Opart, Mb, Lb, TF, TE);
    combine_f2e<<<dim3(TF, BATCH), dim3(128)>>>(Opart, Mb, Lb, aligned_eeg);
}

// round 10
// speedup vs baseline: 3.9841x; 1.0895x over previous
#include <cuda_runtime.h>
#include <cstdint>
#include <math.h>

#define BATCH 128
#define DIMN  512
#define TE    600
#define TF    120
#define NCHUNK 5   // f2e key chunks of 128 covering 600 keys

// ---------------- scratch (device globals; no allocation allowed) ----------------
__device__ uint32_t g_Ae[BATCH * TE * DIMN];   // eeg, tf32 bits, pair-permuted cols
__device__ uint32_t g_Af[BATCH * TF * DIMN];   // fnirs, tf32 bits, pair-permuted cols
__device__ uint32_t g_Wt[6 * DIMN * DIMN];     // weights transposed [n][k], permuted
__device__ uint32_t g_Qe[BATCH * TE * DIMN];   // projections as tf32 bits (plain)
__device__ uint32_t g_Ke[BATCH * TE * DIMN];
__device__ uint32_t g_Ve[BATCH * TE * DIMN];
__device__ uint32_t g_Qf[BATCH * TF * DIMN];
__device__ uint32_t g_Kf[BATCH * TF * DIMN];
__device__ uint32_t g_Vf[BATCH * TF * DIMN];
__device__ float g_Opart[NCHUNK * BATCH * 128 * DIMN];
__device__ float g_M[NCHUNK * BATCH * 128];
__device__ float g_L[NCHUNK * BATCH * 128];

__device__ __forceinline__ uint32_t f2tf32(float f) {
    uint32_t r; asm("cvt.rna.tf32.f32 %0, %1;" : "=r"(r) : "f"(f)); return r;
}

// m16n8k8 tf32 MMA, row.col, fp32 accumulate
__device__ __forceinline__ void mma_tf32(float* c, const uint32_t* a, const uint32_t* b) {
    asm volatile("mma.sync.aligned.m16n8k8.row.col.f32.tf32.tf32.f32 "
        "{%0,%1,%2,%3}, {%4,%5,%6,%7}, {%8,%9}, {%0,%1,%2,%3};"
        : "+f"(c[0]), "+f"(c[1]), "+f"(c[2]), "+f"(c[3])
        : "r"(a[0]), "r"(a[1]), "r"(a[2]), "r"(a[3]), "r"(b[0]), "r"(b[1]));
}

__device__ __forceinline__ void cp_async16(uint32_t dst, const void* src) {
    asm volatile("cp.async.cg.shared.global [%0], [%1], 16;" :: "r"(dst), "l"(src));
}
#define CP_COMMIT() asm volatile("cp.async.commit_group;" ::: "memory")
#define CP_WAIT1()  asm volatile("cp.async.wait_group 1;" ::: "memory")

// ------- activation cvt: fp32 -> tf32 bits with pair-permuted column order -------
// Within each 8-k group, order [0,4,1,5,2,6,3,7] so frag pairs (t4, t4+4) adjoin.
__global__ void cvt_perm_kernel(const float* __restrict__ src, uint32_t* __restrict__ dst, int n)
{
    const int i = (blockIdx.x * 256 + threadIdx.x) * 4;
    if (i < n) {
        const float4 v = *(const float4*)(src + i);
        const int base = i & ~7;          // 8-group start (groups never straddle rows)
        const int o0   = (i & 7) < 4 ? 0 : 1;
        dst[base + o0 + 0] = f2tf32(v.x);
        dst[base + o0 + 2] = f2tf32(v.y);
        dst[base + o0 + 4] = f2tf32(v.z);
        dst[base + o0 + 6] = f2tf32(v.w);
    }
}

// ------- weight transpose: W[k][n] -> Wt[n][perm(k)] tf32 bits -------------------
__global__ void wt_kernel(const float* __restrict__ W, uint32_t* __restrict__ Wt)
{
    __shared__ uint32_t s[32][33];
    const int k0 = blockIdx.x * 32, n0 = blockIdx.y * 32;
    const int tx = threadIdx.x, ty = threadIdx.y;
#pragma unroll
    for (int r = ty; r < 32; r += 8)
        s[r][tx] = f2tf32(W[(size_t)(k0 + r) * DIMN + n0 + tx]);   // s[k][n]
    __syncthreads();
    const int j  = tx & 7;
    const int jp = (j < 4) ? (2 * j) : (2 * (j - 4) + 1);
    const int kcol = k0 + (tx & 24) + jp;
#pragma unroll
    for (int r = ty; r < 32; r += 8)
        Wt[(size_t)(n0 + r) * DIMN + kcol] = s[tx][r];
}

// =============== tf32 mma.sync projection GEMM, 3-stage cp.async =================
// Fused over 3 weight sets: wsel = blockIdx.x>>2, n0 = (blockIdx.x&3)*128.
// Permuted+swizzled stage layout: all fragment loads are conflict-free LDS.64.
#define GSTAGE_W  8192
#define GB_OFF_W  4096
#define GEMM_SMEM_BYTES (3 * GSTAGE_W * 4)   // 98,304

__global__ __launch_bounds__(256, 2)
void gemm_mma_kernel(const uint32_t* __restrict__ A, const uint32_t* __restrict__ Wt,
                     const float* __restrict__ b0, const float* __restrict__ b1,
                     const float* __restrict__ b2,
                     uint32_t* __restrict__ C0, uint32_t* __restrict__ C1,
                     uint32_t* __restrict__ C2)
{
    extern __shared__ uint32_t smem[];
    const uint32_t sb = (uint32_t)__cvta_generic_to_shared(smem);

    const int tid    = threadIdx.x;
    const int wid    = tid >> 5;
    const int lane   = tid & 31;
    const int warp_m = wid & 1;
    const int warp_n = wid >> 1;
    const int g      = lane >> 2;
    const int t4     = lane & 3;
    const int wsel = blockIdx.x >> 2;
    const int n0   = (blockIdx.x & 3) * 128;
    const int m0   = blockIdx.y * 128;
    const int sw   = (g & 3) << 3;            // fragment-load swizzle

    const uint32_t* W = Wt + (size_t)wsel * DIMN * DIMN;
    const float* bias = (wsel == 0) ? b0 : (wsel == 1) ? b1 : b2;
    uint32_t* C       = (wsel == 0) ? C0 : (wsel == 1) ? C1 : C2;

    const int sm_ = tid >> 3;                 // 0..31  (staging row within pass)
    const int sq  = tid & 7;                  // 0..7   (16B chunk within row)

    float acc[4][4][4];
#pragma unroll
    for (int mt = 0; mt < 4; mt++)
#pragma unroll
        for (int nt = 0; nt < 4; nt++)
#pragma unroll
            for (int r = 0; r < 4; r++) acc[mt][nt][r] = 0.f;

    auto issue = [&](int c, int s) {
        const uint32_t stA = sb + (uint32_t)(s * GSTAGE_W) * 4;
        const uint32_t stB = sb + (uint32_t)(s * GSTAGE_W + GB_OFF_W) * 4;
#pragma unroll
        for (int i = 0; i < 4; ++i) {
            const int m = sm_ + i * 32;
            const uint32_t dstw = (uint32_t)(m * 32 + ((sq * 4) ^ ((m & 3) << 3)));
            cp_async16(stA + dstw * 4, A + (size_t)(m0 + m) * DIMN + c * 32 + sq * 4);
        }
#pragma unroll
        for (int i = 0; i < 4; ++i) {
            const int nn = sm_ + i * 32;
            const uint32_t dstw = (uint32_t)(nn * 32 + ((sq * 4) ^ ((nn & 3) << 3)));
            cp_async16(stB + dstw * 4, W + (size_t)(n0 + nn) * DIMN + c * 32 + sq * 4);
        }
        CP_COMMIT();
    };

    issue(0, 0);
    issue(1, 1);

    for (int c = 0; c < 16; ++c) {
        const int s = c % 3;
        CP_WAIT1();
        __syncthreads();
        if (c + 2 < 16) issue(c + 2, (c + 2) % 3);

        const uint32_t* Af = smem + s * GSTAGE_W;
        const uint32_t* Bf = smem + s * GSTAGE_W + GB_OFF_W;
#pragma unroll
        for (int kk = 0; kk < 4; ++kk) {
            const int kcol = ((kk * 8) ^ sw) + 2 * t4;
            uint32_t a[4][4], b[4][2];
#pragma unroll
            for (int mt = 0; mt < 4; ++mt) {
                const int r = warp_m * 64 + mt * 16 + g;
                const uint2 v0 = *(const uint2*)&Af[r * 32 + kcol];
                const uint2 v1 = *(const uint2*)&Af[(r + 8) * 32 + kcol];
                a[mt][0] = v0.x; a[mt][1] = v1.x; a[mt][2] = v0.y; a[mt][3] = v1.y;
            }
#pragma unroll
            for (int nt = 0; nt < 4; ++nt) {
                const int n = warp_n * 32 + nt * 8 + g;
                const uint2 vb = *(const uint2*)&Bf[n * 32 + kcol];
                b[nt][0] = vb.x; b[nt][1] = vb.y;
            }
#pragma unroll
            for (int mt = 0; mt < 4; ++mt)
#pragma unroll
                for (int nt = 0; nt < 4; ++nt)
                    mma_tf32(acc[mt][nt], a[mt], b[nt]);
        }
    }

    // epilogue: bias add in fp32, store as plain tf32 bits (consumed by attention)
#pragma unroll
    for (int mt = 0; mt < 4; ++mt) {
        const int row = m0 + warp_m * 64 + mt * 16 + g;
#pragma unroll
        for (int nt = 0; nt < 4; ++nt) {
            const int col = n0 + warp_n * 32 + nt * 8 + 2 * t4;
            const float2 bb = *(const float2*)(bias + col);
            uint2 o0 = make_uint2(f2tf32(acc[mt][nt][0] + bb.x), f2tf32(acc[mt][nt][1] + bb.y));
            uint2 o1 = make_uint2(f2tf32(acc[mt][nt][2] + bb.x), f2tf32(acc[mt][nt][3] + bb.y));
            *(uint2*)(C + (size_t)row * DIMN + col)       = o0;
            *(uint2*)(C + (size_t)(row + 8) * DIMN + col) = o1;
        }
    }
}

// ================= attention chunk kernel (unchanged from R9) ====================
template <bool E2F, bool FINAL>
__global__ __launch_bounds__(256, 2)
void attn_chunk_kernel(const uint32_t* __restrict__ Q, const uint32_t* __restrict__ K,
                       const uint32_t* __restrict__ V, float* __restrict__ O,
                       float* __restrict__ Opart, float* __restrict__ Mb,
                       float* __restrict__ Lb, int Tq, int Tk)
{
    extern __shared__ char smemc[];
    float*    Ss  = (float*)smemc;                        // [64][132]
    uint32_t* SsU = (uint32_t*)smemc;
    uint32_t* Qs  = (uint32_t*)(smemc + 64 * 132 * 4);    // [64][36]
    uint32_t* Ks  = Qs + 64 * 36;                         // [128][36]
    uint32_t* Vs  = Qs;                                   // [32][136] (phase-3 alias)
    float*    l_s = (float*)(smemc + 64 * 132 * 4 + (64 * 36 + 128 * 36) * 4);  // [64]

    const int tid    = threadIdx.x;
    const int wid    = tid >> 5;
    const int lane   = tid & 31;
    const int warp_m = wid & 1;
    const int warp_n = wid >> 1;
    const int g      = lane >> 2;
    const int t4     = lane & 3;
    const int q0     = blockIdx.x * 64;
    const int b      = blockIdx.y;
    const int c      = blockIdx.z;
    const float scale = 0.044194173824159216f;
    const float NEG_INF = __int_as_float(0xff800000);

    const uint32_t* Qb = Q + (size_t)b * Tq * DIMN;
    const uint32_t* Kb = K + (size_t)b * Tk * DIMN;
    const uint32_t* Vb = V + (size_t)b * Tk * DIMN;

    float acc[2][4][4];
#pragma unroll
    for (int mt = 0; mt < 2; mt++)
#pragma unroll
        for (int nt = 0; nt < 4; nt++)
#pragma unroll
            for (int r = 0; r < 4; r++) acc[mt][nt][r] = 0.f;

    for (int k0 = 0; k0 < DIMN; k0 += 32) {
        __syncthreads();
#pragma unroll
        for (int i = 0; i < 2; ++i) {
            const int lin = i * 256 + tid;
            const int m = lin >> 3, q4 = lin & 7;
            uint4 v = make_uint4(0u, 0u, 0u, 0u);
            if (q0 + m < Tq)
                v = *(const uint4*)(Qb + (size_t)(q0 + m) * DIMN + k0 + q4 * 4);
            *(uint4*)&Qs[m * 36 + q4 * 4] = v;
        }
#pragma unroll
        for (int i = 0; i < 4; ++i) {
            const int lin = i * 256 + tid;
            const int kl = lin >> 3, q4 = lin & 7;
            const int key = c * 128 + kl;
            uint4 v = make_uint4(0u, 0u, 0u, 0u);
            if (key < Tk)
                v = *(const uint4*)(Kb + (size_t)key * DIMN + k0 + q4 * 4);
            *(uint4*)&Ks[kl * 36 + q4 * 4] = v;
        }
        __syncthreads();
#pragma unroll
        for (int kk = 0; kk < 4; ++kk) {
            uint32_t a[2][4], bb[4][2];
#pragma unroll
            for (int mt = 0; mt < 2; ++mt) {
                const int r = warp_m * 32 + mt * 16 + g;
                a[mt][0] = Qs[r * 36 + kk * 8 + t4];
                a[mt][1] = Qs[(r + 8) * 36 + kk * 8 + t4];
                a[mt][2] = Qs[r * 36 + kk * 8 + t4 + 4];
                a[mt][3] = Qs[(r + 8) * 36 + kk * 8 + t4 + 4];
            }
#pragma unroll
            for (int nt = 0; nt < 4; ++nt) {
                const int n = warp_n * 32 + nt * 8 + g;
                bb[nt][0] = Ks[n * 36 + kk * 8 + t4];
                bb[nt][1] = Ks[n * 36 + kk * 8 + t4 + 4];
            }
#pragma unroll
            for (int mt = 0; mt < 2; ++mt)
#pragma unroll
                for (int nt = 0; nt < 4; ++nt)
                    mma_tf32(acc[mt][nt], a[mt], bb[nt]);
        }
    }
#pragma unroll
    for (int mt = 0; mt < 2; ++mt) {
#pragma unroll
        for (int half = 0; half < 2; ++half) {
            const int row = warp_m * 32 + mt * 16 + half * 8 + g;
            const int q   = q0 + row;
            const int j0g = q / 20;
#pragma unroll
            for (int nt = 0; nt < 4; ++nt) {
                const int colc = warp_n * 32 + nt * 8 + 2 * t4;
                float vout[2];
#pragma unroll
                for (int e = 0; e < 2; ++e) {
                    const int key = c * 128 + colc + e;
                    float val;
                    if (key >= Tk) val = NEG_INF;
                    else {
                        bool valid;
                        if (E2F) valid = (key >= j0g + 20) && (key <= j0g + 80);
                        else { const int gg = key / 20; valid = (q >= gg + 20) && (q <= gg + 80); }
                        val = valid ? acc[mt][nt][half * 2 + e] * scale : -1e9f;
                    }
                    vout[e] = val;
                }
                *(float2*)&Ss[row * 132 + colc] = make_float2(vout[0], vout[1]);
            }
        }
    }
    __syncthreads();

    {
        const int row  = tid >> 2;
        const int part = tid & 3;
        float* srow = Ss + row * 132;

        float mx = NEG_INF;
#pragma unroll
        for (int i = 0; i < 32; ++i) mx = fmaxf(mx, srow[part + i * 4]);
        mx = fmaxf(mx, __shfl_xor_sync(0xffffffffu, mx, 1));
        mx = fmaxf(mx, __shfl_xor_sync(0xffffffffu, mx, 2));
        float sum = 0.f;
        uint32_t* urow = SsU + row * 132;
#pragma unroll
        for (int i = 0; i < 32; ++i) {
            const int cc = part + i * 4;
            const float e = __expf(srow[cc] - mx);
            sum += e;
            urow[cc] = f2tf32(e);
        }
        sum += __shfl_xor_sync(0xffffffffu, sum, 1);
        sum += __shfl_xor_sync(0xffffffffu, sum, 2);
        if (part == 0) {
            l_s[row] = sum;
            if (!FINAL) {
                const int idx = (c * BATCH + b) * 128 + q0 + row;
                Mb[idx] = mx;
                Lb[idx] = sum;
            }
        }
    }
    __syncthreads();

    for (int nc = 0; nc < 4; ++nc) {
        float oacc[2][4][4];
#pragma unroll
        for (int mt = 0; mt < 2; mt++)
#pragma unroll
            for (int nt = 0; nt < 4; nt++)
#pragma unroll
                for (int r = 0; r < 4; r++) oacc[mt][nt][r] = 0.f;

        for (int ks = 0; ks < 4; ++ks) {
            __syncthreads();
#pragma unroll
            for (int i = 0; i < 4; ++i) {
                const int lin = i * 256 + tid;
                const int kl = lin >> 5, c4 = lin & 31;
                const int key = c * 128 + ks * 32 + kl;
                uint4 v = make_uint4(0u, 0u, 0u, 0u);
                if (key < Tk)
                    v = *(const uint4*)(Vb + (size_t)key * DIMN + nc * 128 + c4 * 4);
                *(uint4*)&Vs[kl * 136 + c4 * 4] = v;
            }
            __syncthreads();
#pragma unroll
            for (int kk = 0; kk < 4; ++kk) {
                uint32_t a[2][4], bb[4][2];
#pragma unroll
                for (int mt = 0; mt < 2; ++mt) {
                    const int r = warp_m * 32 + mt * 16 + g;
                    const int col = ks * 32 + kk * 8 + t4;
                    a[mt][0] = SsU[r * 132 + col];
                    a[mt][1] = SsU[(r + 8) * 132 + col];
                    a[mt][2] = SsU[r * 132 + col + 4];
                    a[mt][3] = SsU[(r + 8) * 132 + col + 4];
                }
#pragma unroll
                for (int nt = 0; nt < 4; ++nt) {
                    const int n = warp_n * 32 + nt * 8 + g;
                    bb[nt][0] = Vs[(kk * 8 + t4) * 136 + n];
                    bb[nt][1] = Vs[(kk * 8 + t4 + 4) * 136 + n];
                }
#pragma unroll
                for (int mt = 0; mt < 2; ++mt)
#pragma unroll
                    for (int nt = 0; nt < 4; ++nt)
                        mma_tf32(oacc[mt][nt], a[mt], bb[nt]);
            }
        }
#pragma unroll
        for (int mt = 0; mt < 2; ++mt) {
#pragma unroll
            for (int half = 0; half < 2; ++half) {
                const int row = warp_m * 32 + mt * 16 + half * 8 + g;
                const int q   = q0 + row;
#pragma unroll
                for (int nt = 0; nt < 4; ++nt) {
                    const int col = nc * 128 + warp_n * 32 + nt * 8 + 2 * t4;
                    const float v0 = oacc[mt][nt][half * 2 + 0];
                    const float v1 = oacc[mt][nt][half * 2 + 1];
                    if (FINAL) {
                        if (q < Tq) {
                            const float inv = 1.f / l_s[row];
                            *(float2*)(O + ((size_t)b * Tq + q) * DIMN + col) =
                                make_float2(v0 * inv, v1 * inv);
                        }
                    } else {
                        float* dst = Opart + (((size_t)c * BATCH + b) * 128 + q) * DIMN + col;
                        *(float2*)dst = make_float2(v0, v1);
                    }
                }
            }
        }
    }
}

// ----------------- f2e combine: merge 5 chunk partials per row -------------------
__global__ void combine_f2e(const float* __restrict__ Opart,
                            const float* __restrict__ Mb, const float* __restrict__ Lb,
                            float* __restrict__ O)
{
    const int q = blockIdx.x;
    const int b = blockIdx.y;
    const int t = threadIdx.x;
    float m[NCHUNK], w[NCHUNK];
    float M = __int_as_float(0xff800000);
#pragma unroll
    for (int c = 0; c < NCHUNK; ++c) {
        m[c] = Mb[(c * BATCH + b) * 128 + q];
        M = fmaxf(M, m[c]);
    }
    float den = 0.f;
#pragma unroll
    for (int c = 0; c < NCHUNK; ++c) {
        w[c] = __expf(m[c] - M);
        den += w[c] * Lb[(c * BATCH + b) * 128 + q];
    }
    const float inv = 1.f / den;
    float4 o = make_float4(0.f, 0.f, 0.f, 0.f);
#pragma unroll
    for (int c = 0; c < NCHUNK; ++c) {
        const float4 p = *(const float4*)(Opart + (((size_t)c * BATCH + b) * 128 + q) * DIMN + t * 4);
        const float s = w[c] * inv;
        o.x += s * p.x; o.y += s * p.y; o.z += s * p.z; o.w += s * p.w;
    }
    *(float4*)(O + ((size_t)b * TF + q) * DIMN + t * 4) = o;
}

static const int ATTN_SMEM = 64 * 132 * 4 + (64 * 36 + 128 * 36) * 4 + 64 * 4;  // 61,952

extern "C" void kernel_launch(void* const* d_in, const int* in_sizes, int n_in,
                              void* d_out, int out_size)
{
    (void)in_sizes; (void)n_in; (void)out_size;

    const float* eeg   = (const float*)d_in[0];
    const float* fnirs = (const float*)d_in[1];
    const float* Wqe = (const float*)d_in[2];
    const float* bqe = (const float*)d_in[3];
    const float* Wke = (const float*)d_in[4];
    const float* bke = (const float*)d_in[5];
    const float* Wve = (const float*)d_in[6];
    const float* bve = (const float*)d_in[7];
    const float* Wqf = (const float*)d_in[8];
    const float* bqf = (const float*)d_in[9];
    const float* Wkf = (const float*)d_in[10];
    const float* bkf = (const float*)d_in[11];
    const float* Wvf = (const float*)d_in[12];
    const float* bvf = (const float*)d_in[13];

    uint32_t *Ae, *Af, *Wt, *Qe, *Ke, *Ve, *Qf, *Kf, *Vf;
    float *Opart, *Mb, *Lb;
    cudaGetSymbolAddress((void**)&Ae, g_Ae);
    cudaGetSymbolAddress((void**)&Af, g_Af);
    cudaGetSymbolAddress((void**)&Wt, g_Wt);
    cudaGetSymbolAddress((void**)&Qe, g_Qe);
    cudaGetSymbolAddress((void**)&Ke, g_Ke);
    cudaGetSymbolAddress((void**)&Ve, g_Ve);
    cudaGetSymbolAddress((void**)&Qf, g_Qf);
    cudaGetSymbolAddress((void**)&Kf, g_Kf);
    cudaGetSymbolAddress((void**)&Vf, g_Vf);
    cudaGetSymbolAddress((void**)&Opart, g_Opart);
    cudaGetSymbolAddress((void**)&Mb, g_M);
    cudaGetSymbolAddress((void**)&Lb, g_L);

    float* out           = (float*)d_out;
    float* aligned_eeg   = out;                                // [B, TF, D]
    float* aligned_fnirs = out + (size_t)BATCH * TF * DIMN;    // [B, TE, D]

    const int Me = BATCH * TE;
    const int Mf = BATCH * TF;
    const size_t NW = (size_t)DIMN * DIMN;

    // ---- stage 0: convert activations (permuted) + transpose weights (permuted)
    const int ne = Me * DIMN, nf = Mf * DIMN;
    cvt_perm_kernel<<<(ne / 4 + 255) / 256, 256>>>(eeg,   Ae, ne);
    cvt_perm_kernel<<<(nf / 4 + 255) / 256, 256>>>(fnirs, Af, nf);
    dim3 wblk(32, 8), wgrd(DIMN / 32, DIMN / 32);
    wt_kernel<<<wgrd, wblk>>>(Wqe, Wt + 0 * NW);
    wt_kernel<<<wgrd, wblk>>>(Wke, Wt + 1 * NW);
    wt_kernel<<<wgrd, wblk>>>(Wve, Wt + 2 * NW);
    wt_kernel<<<wgrd, wblk>>>(Wqf, Wt + 3 * NW);
    wt_kernel<<<wgrd, wblk>>>(Wkf, Wt + 4 * NW);
    wt_kernel<<<wgrd, wblk>>>(Wvf, Wt + 5 * NW);

    cudaFuncSetAttribute(gemm_mma_kernel,
                         cudaFuncAttributeMaxDynamicSharedMemorySize, GEMM_SMEM_BYTES);

    dim3 blk(256);
    // ---- stage 1: fused projections (3 weight sets per launch)
    gemm_mma_kernel<<<dim3(12, Me / 128), blk, GEMM_SMEM_BYTES>>>(
        Ae, Wt, bqe, bke, bve, Qe, Ke, Ve);
    gemm_mma_kernel<<<dim3(12, Mf / 128), blk, GEMM_SMEM_BYTES>>>(
        Af, Wt + 3 * NW, bqf, bkf, bvf, Qf, Kf, Vf);

    cudaFuncSetAttribute((const void*)attn_chunk_kernel<true, true>,
                         cudaFuncAttributeMaxDynamicSharedMemorySize, ATTN_SMEM);
    cudaFuncSetAttribute((const void*)attn_chunk_kernel<false, false>,
                         cudaFuncAttributeMaxDynamicSharedMemorySize, ATTN_SMEM);

    // ---- stage 2: attention
    attn_chunk_kernel<true, true><<<dim3(10, BATCH, 1), blk, ATTN_SMEM>>>(
        Qe, Kf, Vf, aligned_fnirs, nullptr, nullptr, nullptr, TE, TF);
    attn_chunk_kernel<false, false><<<dim3(2, BATCH, NCHUNK), blk, ATTN_SMEM>>>(
        Qf, Ke, Ve, nullptr, Opart, Mb, Lb, TF, TE);
    combine_f2e<<<dim3(TF, BATCH), dim3(128)>>>(Opart, Mb, Lb, aligned_eeg);
}

// round 11
// speedup vs baseline: 5.2704x; 1.3228x over previous
#include <cuda_runtime.h>
#include <cuda_fp16.h>
#include <cstdint>
#include <math.h>

#define BATCH 128
#define DIMN  512
#define DIMW  256          // row length in half2 words
#define TE    600
#define TF    120
#define NCHUNK 5           // f2e key chunks of 128 covering 600 keys

// ---------------- scratch (device globals; no allocation allowed) ----------------
__device__ uint32_t g_Ae[BATCH * TE * DIMW];   // eeg, half2 words, pair-permuted
__device__ uint32_t g_Af[BATCH * TF * DIMW];   // fnirs, half2 words, pair-permuted
__device__ uint32_t g_Wt[6 * DIMN * DIMW];     // weights [n][k-half2], permuted
__device__ uint32_t g_Qe[BATCH * TE * DIMN];   // projections as tf32 bits (plain)
__device__ uint32_t g_Ke[BATCH * TE * DIMN];
__device__ uint32_t g_Ve[BATCH * TE * DIMN];
__device__ uint32_t g_Qf[BATCH * TF * DIMN];
__device__ uint32_t g_Kf[BATCH * TF * DIMN];
__device__ uint32_t g_Vf[BATCH * TF * DIMN];
__device__ float g_Opart[NCHUNK * BATCH * 128 * DIMN];
__device__ float g_M[NCHUNK * BATCH * 128];
__device__ float g_L[NCHUNK * BATCH * 128];

__device__ __forceinline__ uint32_t f2tf32(float f) {
    uint32_t r; asm("cvt.rna.tf32.f32 %0, %1;" : "=r"(r) : "f"(f)); return r;
}
__device__ __forceinline__ uint32_t pack_h2(float lo, float hi) {
    half2 h = __floats2half2_rn(lo, hi);
    return *(uint32_t*)&h;
}

// m16n8k8 tf32 MMA (attention)
__device__ __forceinline__ void mma_tf32(float* c, const uint32_t* a, const uint32_t* b) {
    asm volatile("mma.sync.aligned.m16n8k8.row.col.f32.tf32.tf32.f32 "
        "{%0,%1,%2,%3}, {%4,%5,%6,%7}, {%8,%9}, {%0,%1,%2,%3};"
        : "+f"(c[0]), "+f"(c[1]), "+f"(c[2]), "+f"(c[3])
        : "r"(a[0]), "r"(a[1]), "r"(a[2]), "r"(a[3]), "r"(b[0]), "r"(b[1]));
}
// m16n8k16 fp16 MMA, fp32 accumulate (projections)
__device__ __forceinline__ void mma_f16(float* c, const uint32_t* a, const uint32_t* b) {
    asm volatile("mma.sync.aligned.m16n8k16.row.col.f32.f16.f16.f32 "
        "{%0,%1,%2,%3}, {%4,%5,%6,%7}, {%8,%9}, {%0,%1,%2,%3};"
        : "+f"(c[0]), "+f"(c[1]), "+f"(c[2]), "+f"(c[3])
        : "r"(a[0]), "r"(a[1]), "r"(a[2]), "r"(a[3]), "r"(b[0]), "r"(b[1]));
}

__device__ __forceinline__ void cp_async16(uint32_t dst, const void* src) {
    asm volatile("cp.async.cg.shared.global [%0], [%1], 16;" :: "r"(dst), "l"(src));
}
#define CP_COMMIT() asm volatile("cp.async.commit_group;" ::: "memory")
#define CP_WAIT1()  asm volatile("cp.async.wait_group 1;" ::: "memory")

// ------- activation cvt: fp32 -> half2 words, pair-permuted within 8-word groups -
// Word j (k-halfs 2j,2j+1) stored at (j<4 ? 2j : 2(j-4)+1).
__global__ void cvt_perm_h(const float* __restrict__ src, uint32_t* __restrict__ dst, int n)
{
    const int i = (blockIdx.x * 256 + threadIdx.x) * 4;   // float index
    if (i < n) {
        const float4 v = *(const float4*)(src + i);
        const uint32_t w0 = pack_h2(v.x, v.y);
        const uint32_t w1 = pack_h2(v.z, v.w);
        const int p    = i >> 1;          // half2 word index (even)
        const int base = p & ~7;
        const int j0   = p & 7;           // in {0,2,4,6}
        const int d0 = (j0 < 4) ? 2 * j0 : 2 * (j0 - 4) + 1;
        const int j1 = j0 + 1;
        const int d1 = (j1 < 4) ? 2 * j1 : 2 * (j1 - 4) + 1;
        dst[base + d0] = w0;
        dst[base + d1] = w1;
    }
}

// ------- weight transform: W[k][n] fp32 -> Wt[n][perm(k-half2)] ------------------
__global__ void wt_h_kernel(const float* __restrict__ W, uint32_t* __restrict__ Wt)
{
    __shared__ float s[32][33];
    const int k0 = blockIdx.x * 32, n0 = blockIdx.y * 32;
    const int tx = threadIdx.x, ty = threadIdx.y;
#pragma unroll
    for (int r = ty; r < 32; r += 8)
        s[r][tx] = W[(size_t)(k0 + r) * DIMN + n0 + tx];   // s[k][n]
    __syncthreads();
#pragma unroll
    for (int w = ty; w < 16; w += 8) {                     // half2 word within chunk
        const uint32_t h = pack_h2(s[2 * w][tx], s[2 * w + 1][tx]);
        const int j  = w & 7;
        const int jp = (j < 4) ? 2 * j : 2 * (j - 4) + 1;
        const int pos = (w & 8) + jp;
        Wt[(size_t)(n0 + tx) * DIMW + k0 / 2 + pos] = h;
    }
}

// =============== fp16 m16n8k16 projection GEMM, 3-stage cp.async =================
// Fused over 3 weight sets: wsel = blockIdx.x>>2, n0 = (blockIdx.x&3)*128.
// 16-word rows, XOR-swizzled; all fragment loads are conflict-free LDS.64.
#define GSTAGE_W  4096      // A 128x16 + B 128x16 half2 words
#define GB_OFF_W  2048
#define GEMM_SMEM_BYTES (3 * GSTAGE_W * 4)   // 49,152

__global__ __launch_bounds__(256, 2)
void gemm_mma_kernel(const uint32_t* __restrict__ A, const uint32_t* __restrict__ Wt,
                     const float* __restrict__ b0, const float* __restrict__ b1,
                     const float* __restrict__ b2,
                     uint32_t* __restrict__ C0, uint32_t* __restrict__ C1,
                     uint32_t* __restrict__ C2)
{
    extern __shared__ uint32_t smem[];
    const uint32_t sb = (uint32_t)__cvta_generic_to_shared(smem);

    const int tid    = threadIdx.x;
    const int wid    = tid >> 5;
    const int lane   = tid & 31;
    const int warp_m = wid & 1;
    const int warp_n = wid >> 1;
    const int g      = lane >> 2;
    const int t4     = lane & 3;
    const int wsel = blockIdx.x >> 2;
    const int n0   = (blockIdx.x & 3) * 128;
    const int m0   = blockIdx.y * 128;

    const uint32_t* W = Wt + (size_t)wsel * DIMN * DIMW;
    const float* bias = (wsel == 0) ? b0 : (wsel == 1) ? b1 : b2;
    uint32_t* C       = (wsel == 0) ? C0 : (wsel == 1) ? C1 : C2;

    const int sm_ = tid >> 2;                 // 0..63 (staging row within pass)
    const int sq  = tid & 3;                  // 0..3  (16B chunk within 16-word row)

    float acc[4][4][4];
#pragma unroll
    for (int mt = 0; mt < 4; mt++)
#pragma unroll
        for (int nt = 0; nt < 4; nt++)
#pragma unroll
            for (int r = 0; r < 4; r++) acc[mt][nt][r] = 0.f;

    auto issue = [&](int c, int s) {
        const uint32_t stA = sb + (uint32_t)(s * GSTAGE_W) * 4;
        const uint32_t stB = sb + (uint32_t)(s * GSTAGE_W + GB_OFF_W) * 4;
#pragma unroll
        for (int i = 0; i < 2; ++i) {
            const int m = sm_ + i * 64;
            const uint32_t dstw = (uint32_t)(m * 16 + ((sq * 4) ^ ((m & 3) << 2)));
            cp_async16(stA + dstw * 4, A + (size_t)(m0 + m) * DIMW + c * 16 + sq * 4);
        }
#pragma unroll
        for (int i = 0; i < 2; ++i) {
            const int nn = sm_ + i * 64;
            const uint32_t dstw = (uint32_t)(nn * 16 + ((sq * 4) ^ ((nn & 3) << 2)));
            cp_async16(stB + dstw * 4, W + (size_t)(n0 + nn) * DIMW + c * 16 + sq * 4);
        }
        CP_COMMIT();
    };

    issue(0, 0);
    issue(1, 1);

    const int sw = (g & 3) << 2;              // fragment-load swizzle (row&3 == g&3)

    for (int c = 0; c < 16; ++c) {
        const int s = c % 3;
        CP_WAIT1();
        __syncthreads();
        if (c + 2 < 16) issue(c + 2, (c + 2) % 3);

        const uint32_t* Af = smem + s * GSTAGE_W;
        const uint32_t* Bf = smem + s * GSTAGE_W + GB_OFF_W;
#pragma unroll
        for (int kk = 0; kk < 2; ++kk) {
            const int off = (kk * 8 + 2 * t4) ^ sw;
            uint32_t a[4][4], b[4][2];
#pragma unroll
            for (int mt = 0; mt < 4; ++mt) {
                const int r = warp_m * 64 + mt * 16 + g;
                const uint2 v0 = *(const uint2*)&Af[r * 16 + off];
                const uint2 v1 = *(const uint2*)&Af[(r + 8) * 16 + off];
                a[mt][0] = v0.x; a[mt][1] = v1.x; a[mt][2] = v0.y; a[mt][3] = v1.y;
            }
#pragma unroll
            for (int nt = 0; nt < 4; ++nt) {
                const int n = warp_n * 32 + nt * 8 + g;
                const uint2 vb = *(const uint2*)&Bf[n * 16 + off];
                b[nt][0] = vb.x; b[nt][1] = vb.y;
            }
#pragma unroll
            for (int mt = 0; mt < 4; ++mt)
#pragma unroll
                for (int nt = 0; nt < 4; ++nt)
                    mma_f16(acc[mt][nt], a[mt], b[nt]);
        }
    }

    // epilogue: bias add in fp32, store as plain tf32 bits (consumed by attention)
#pragma unroll
    for (int mt = 0; mt < 4; ++mt) {
        const int row = m0 + warp_m * 64 + mt * 16 + g;
#pragma unroll
        for (int nt = 0; nt < 4; ++nt) {
            const int col = n0 + warp_n * 32 + nt * 8 + 2 * t4;
            const float2 bb = *(const float2*)(bias + col);
            uint2 o0 = make_uint2(f2tf32(acc[mt][nt][0] + bb.x), f2tf32(acc[mt][nt][1] + bb.y));
            uint2 o1 = make_uint2(f2tf32(acc[mt][nt][2] + bb.x), f2tf32(acc[mt][nt][3] + bb.y));
            *(uint2*)(C + (size_t)row * DIMN + col)       = o0;
            *(uint2*)(C + (size_t)(row + 8) * DIMN + col) = o1;
        }
    }
}

// ================= attention chunk kernel (unchanged, tf32) ======================
template <bool E2F, bool FINAL>
__global__ __launch_bounds__(256, 2)
void attn_chunk_kernel(const uint32_t* __restrict__ Q, const uint32_t* __restrict__ K,
                       const uint32_t* __restrict__ V, float* __restrict__ O,
                       float* __restrict__ Opart, float* __restrict__ Mb,
                       float* __restrict__ Lb, int Tq, int Tk)
{
    extern __shared__ char smemc[];
    float*    Ss  = (float*)smemc;                        // [64][132]
    uint32_t* SsU = (uint32_t*)smemc;
    uint32_t* Qs  = (uint32_t*)(smemc + 64 * 132 * 4);    // [64][36]
    uint32_t* Ks  = Qs + 64 * 36;                         // [128][36]
    uint32_t* Vs  = Qs;                                   // [32][136] (phase-3 alias)
    float*    l_s = (float*)(smemc + 64 * 132 * 4 + (64 * 36 + 128 * 36) * 4);  // [64]

    const int tid    = threadIdx.x;
    const int wid    = tid >> 5;
    const int lane   = tid & 31;
    const int warp_m = wid & 1;
    const int warp_n = wid >> 1;
    const int g      = lane >> 2;
    const int t4     = lane & 3;
    const int q0     = blockIdx.x * 64;
    const int b      = blockIdx.y;
    const int c      = blockIdx.z;
    const float scale = 0.044194173824159216f;
    const float NEG_INF = __int_as_float(0xff800000);

    const uint32_t* Qb = Q + (size_t)b * Tq * DIMN;
    const uint32_t* Kb = K + (size_t)b * Tk * DIMN;
    const uint32_t* Vb = V + (size_t)b * Tk * DIMN;

    float acc[2][4][4];
#pragma unroll
    for (int mt = 0; mt < 2; mt++)
#pragma unroll
        for (int nt = 0; nt < 4; nt++)
#pragma unroll
            for (int r = 0; r < 4; r++) acc[mt][nt][r] = 0.f;

    for (int k0 = 0; k0 < DIMN; k0 += 32) {
        __syncthreads();
#pragma unroll
        for (int i = 0; i < 2; ++i) {
            const int lin = i * 256 + tid;
            const int m = lin >> 3, q4 = lin & 7;
            uint4 v = make_uint4(0u, 0u, 0u, 0u);
            if (q0 + m < Tq)
                v = *(const uint4*)(Qb + (size_t)(q0 + m) * DIMN + k0 + q4 * 4);
            *(uint4*)&Qs[m * 36 + q4 * 4] = v;
        }
#pragma unroll
        for (int i = 0; i < 4; ++i) {
            const int lin = i * 256 + tid;
            const int kl = lin >> 3, q4 = lin & 7;
            const int key = c * 128 + kl;
            uint4 v = make_uint4(0u, 0u, 0u, 0u);
            if (key < Tk)
                v = *(const uint4*)(Kb + (size_t)key * DIMN + k0 + q4 * 4);
            *(uint4*)&Ks[kl * 36 + q4 * 4] = v;
        }
        __syncthreads();
#pragma unroll
        for (int kk = 0; kk < 4; ++kk) {
            uint32_t a[2][4], bb[4][2];
#pragma unroll
            for (int mt = 0; mt < 2; ++mt) {
                const int r = warp_m * 32 + mt * 16 + g;
                a[mt][0] = Qs[r * 36 + kk * 8 + t4];
                a[mt][1] = Qs[(r + 8) * 36 + kk * 8 + t4];
                a[mt][2] = Qs[r * 36 + kk * 8 + t4 + 4];
                a[mt][3] = Qs[(r + 8) * 36 + kk * 8 + t4 + 4];
            }
#pragma unroll
            for (int nt = 0; nt < 4; ++nt) {
                const int n = warp_n * 32 + nt * 8 + g;
                bb[nt][0] = Ks[n * 36 + kk * 8 + t4];
                bb[nt][1] = Ks[n * 36 + kk * 8 + t4 + 4];
            }
#pragma unroll
            for (int mt = 0; mt < 2; ++mt)
#pragma unroll
                for (int nt = 0; nt < 4; ++nt)
                    mma_tf32(acc[mt][nt], a[mt], bb[nt]);
        }
    }
#pragma unroll
    for (int mt = 0; mt < 2; ++mt) {
#pragma unroll
        for (int half = 0; half < 2; ++half) {
            const int row = warp_m * 32 + mt * 16 + half * 8 + g;
            const int q   = q0 + row;
            const int j0g = q / 20;
#pragma unroll
            for (int nt = 0; nt < 4; ++nt) {
                const int colc = warp_n * 32 + nt * 8 + 2 * t4;
                float vout[2];
#pragma unroll
                for (int e = 0; e < 2; ++e) {
                    const int key = c * 128 + colc + e;
                    float val;
                    if (key >= Tk) val = NEG_INF;
                    else {
                        bool valid;
                        if (E2F) valid = (key >= j0g + 20) && (key <= j0g + 80);
                        else { const int gg = key / 20; valid = (q >= gg + 20) && (q <= gg + 80); }
                        val = valid ? acc[mt][nt][half * 2 + e] * scale : -1e9f;
                    }
                    vout[e] = val;
                }
                *(float2*)&Ss[row * 132 + colc] = make_float2(vout[0], vout[1]);
            }
        }
    }
    __syncthreads();

    {
        const int row  = tid >> 2;
        const int part = tid & 3;
        float* srow = Ss + row * 132;

        float mx = NEG_INF;
#pragma unroll
        for (int i = 0; i < 32; ++i) mx = fmaxf(mx, srow[part + i * 4]);
        mx = fmaxf(mx, __shfl_xor_sync(0xffffffffu, mx, 1));
        mx = fmaxf(mx, __shfl_xor_sync(0xffffffffu, mx, 2));
        float sum = 0.f;
        uint32_t* urow = SsU + row * 132;
#pragma unroll
        for (int i = 0; i < 32; ++i) {
            const int cc = part + i * 4;
            const float e = __expf(srow[cc] - mx);
            sum += e;
            urow[cc] = f2tf32(e);
        }
        sum += __shfl_xor_sync(0xffffffffu, sum, 1);
        sum += __shfl_xor_sync(0xffffffffu, sum, 2);
        if (part == 0) {
            l_s[row] = sum;
            if (!FINAL) {
                const int idx = (c * BATCH + b) * 128 + q0 + row;
                Mb[idx] = mx;
                Lb[idx] = sum;
            }
        }
    }
    __syncthreads();

    for (int nc = 0; nc < 4; ++nc) {
        float oacc[2][4][4];
#pragma unroll
        for (int mt = 0; mt < 2; mt++)
#pragma unroll
            for (int nt = 0; nt < 4; nt++)
#pragma unroll
                for (int r = 0; r < 4; r++) oacc[mt][nt][r] = 0.f;

        for (int ks = 0; ks < 4; ++ks) {
            __syncthreads();
#pragma unroll
            for (int i = 0; i < 4; ++i) {
                const int lin = i * 256 + tid;
                const int kl = lin >> 5, c4 = lin & 31;
                const int key = c * 128 + ks * 32 + kl;
                uint4 v = make_uint4(0u, 0u, 0u, 0u);
                if (key < Tk)
                    v = *(const uint4*)(Vb + (size_t)key * DIMN + nc * 128 + c4 * 4);
                *(uint4*)&Vs[kl * 136 + c4 * 4] = v;
            }
            __syncthreads();
#pragma unroll
            for (int kk = 0; kk < 4; ++kk) {
                uint32_t a[2][4], bb[4][2];
#pragma unroll
                for (int mt = 0; mt < 2; ++mt) {
                    const int r = warp_m * 32 + mt * 16 + g;
                    const int col = ks * 32 + kk * 8 + t4;
                    a[mt][0] = SsU[r * 132 + col];
                    a[mt][1] = SsU[(r + 8) * 132 + col];
                    a[mt][2] = SsU[r * 132 + col + 4];
                    a[mt][3] = SsU[(r + 8) * 132 + col + 4];
                }
#pragma unroll
                for (int nt = 0; nt < 4; ++nt) {
                    const int n = warp_n * 32 + nt * 8 + g;
                    bb[nt][0] = Vs[(kk * 8 + t4) * 136 + n];
                    bb[nt][1] = Vs[(kk * 8 + t4 + 4) * 136 + n];
                }
#pragma unroll
                for (int mt = 0; mt < 2; ++mt)
#pragma unroll
                    for (int nt = 0; nt < 4; ++nt)
                        mma_tf32(oacc[mt][nt], a[mt], bb[nt]);
            }
        }
#pragma unroll
        for (int mt = 0; mt < 2; ++mt) {
#pragma unroll
            for (int half = 0; half < 2; ++half) {
                const int row = warp_m * 32 + mt * 16 + half * 8 + g;
                const int q   = q0 + row;
#pragma unroll
                for (int nt = 0; nt < 4; ++nt) {
                    const int col = nc * 128 + warp_n * 32 + nt * 8 + 2 * t4;
                    const float v0 = oacc[mt][nt][half * 2 + 0];
                    const float v1 = oacc[mt][nt][half * 2 + 1];
                    if (FINAL) {
                        if (q < Tq) {
                            const float inv = 1.f / l_s[row];
                            *(float2*)(O + ((size_t)b * Tq + q) * DIMN + col) =
                                make_float2(v0 * inv, v1 * inv);
                        }
                    } else {
                        float* dst = Opart + (((size_t)c * BATCH + b) * 128 + q) * DIMN + col;
                        *(float2*)dst = make_float2(v0, v1);
                    }
                }
            }
        }
    }
}

// ----------------- f2e combine: merge 5 chunk partials per row -------------------
__global__ void combine_f2e(const float* __restrict__ Opart,
                            const float* __restrict__ Mb, const float* __restrict__ Lb,
                            float* __restrict__ O)
{
    const int q = blockIdx.x;
    const int b = blockIdx.y;
    const int t = threadIdx.x;
    float m[NCHUNK], w[NCHUNK];
    float M = __int_as_float(0xff800000);
#pragma unroll
    for (int c = 0; c < NCHUNK; ++c) {
        m[c] = Mb[(c * BATCH + b) * 128 + q];
        M = fmaxf(M, m[c]);
    }
    float den = 0.f;
#pragma unroll
    for (int c = 0; c < NCHUNK; ++c) {
        w[c] = __expf(m[c] - M);
        den += w[c] * Lb[(c * BATCH + b) * 128 + q];
    }
    const float inv = 1.f / den;
    float4 o = make_float4(0.f, 0.f, 0.f, 0.f);
#pragma unroll
    for (int c = 0; c < NCHUNK; ++c) {
        const float4 p = *(const float4*)(Opart + (((size_t)c * BATCH + b) * 128 + q) * DIMN + t * 4);
        const float s = w[c] * inv;
        o.x += s * p.x; o.y += s * p.y; o.z += s * p.z; o.w += s * p.w;
    }
    *(float4*)(O + ((size_t)b * TF + q) * DIMN + t * 4) = o;
}

static const int ATTN_SMEM = 64 * 132 * 4 + (64 * 36 + 128 * 36) * 4 + 64 * 4;  // 61,952

extern "C" void kernel_launch(void* const* d_in, const int* in_sizes, int n_in,
                              void* d_out, int out_size)
{
    (void)in_sizes; (void)n_in; (void)out_size;

    const float* eeg   = (const float*)d_in[0];
    const float* fnirs = (const float*)d_in[1];
    const float* Wqe = (const float*)d_in[2];
    const float* bqe = (const float*)d_in[3];
    const float* Wke = (const float*)d_in[4];
    const float* bke = (const float*)d_in[5];
    const float* Wve = (const float*)d_in[6];
    const float* bve = (const float*)d_in[7];
    const float* Wqf = (const float*)d_in[8];
    const float* bqf = (const float*)d_in[9];
    const float* Wkf = (const float*)d_in[10];
    const float* bkf = (const float*)d_in[11];
    const float* Wvf = (const float*)d_in[12];
    const float* bvf = (const float*)d_in[13];

    uint32_t *Ae, *Af, *Wt, *Qe, *Ke, *Ve, *Qf, *Kf, *Vf;
    float *Opart, *Mb, *Lb;
    cudaGetSymbolAddress((void**)&Ae, g_Ae);
    cudaGetSymbolAddress((void**)&Af, g_Af);
    cudaGetSymbolAddress((void**)&Wt, g_Wt);
    cudaGetSymbolAddress((void**)&Qe, g_Qe);
    cudaGetSymbolAddress((void**)&Ke, g_Ke);
    cudaGetSymbolAddress((void**)&Ve, g_Ve);
    cudaGetSymbolAddress((void**)&Qf, g_Qf);
    cudaGetSymbolAddress((void**)&Kf, g_Kf);
    cudaGetSymbolAddress((void**)&Vf, g_Vf);
    cudaGetSymbolAddress((void**)&Opart, g_Opart);
    cudaGetSymbolAddress((void**)&Mb, g_M);
    cudaGetSymbolAddress((void**)&Lb, g_L);

    float* out           = (float*)d_out;
    float* aligned_eeg   = out;                                // [B, TF, D]
    float* aligned_fnirs = out + (size_t)BATCH * TF * DIMN;    // [B, TE, D]

    const int Me = BATCH * TE;
    const int Mf = BATCH * TF;
    const size_t NWW = (size_t)DIMN * DIMW;

    // ---- stage 0: convert activations + transform weights (fp16, permuted)
    const int ne = Me * DIMN, nf = Mf * DIMN;
    cvt_perm_h<<<(ne / 4 + 255) / 256, 256>>>(eeg,   Ae, ne);
    cvt_perm_h<<<(nf / 4 + 255) / 256, 256>>>(fnirs, Af, nf);
    dim3 wblk(32, 8), wgrd(DIMN / 32, DIMN / 32);
    wt_h_kernel<<<wgrd, wblk>>>(Wqe, Wt + 0 * NWW);
    wt_h_kernel<<<wgrd, wblk>>>(Wke, Wt + 1 * NWW);
    wt_h_kernel<<<wgrd, wblk>>>(Wve, Wt + 2 * NWW);
    wt_h_kernel<<<wgrd, wblk>>>(Wqf, Wt + 3 * NWW);
    wt_h_kernel<<<wgrd, wblk>>>(Wkf, Wt + 4 * NWW);
    wt_h_kernel<<<wgrd, wblk>>>(Wvf, Wt + 5 * NWW);

    cudaFuncSetAttribute(gemm_mma_kernel,
                         cudaFuncAttributeMaxDynamicSharedMemorySize, GEMM_SMEM_BYTES);

    dim3 blk(256);
    // ---- stage 1: fused projections (3 weight sets per launch)
    gemm_mma_kernel<<<dim3(12, Me / 128), blk, GEMM_SMEM_BYTES>>>(
        Ae, Wt, bqe, bke, bve, Qe, Ke, Ve);
    gemm_mma_kernel<<<dim3(12, Mf / 128), blk, GEMM_SMEM_BYTES>>>(
        Af, Wt + 3 * NWW, bqf, bkf, bvf, Qf, Kf, Vf);

    cudaFuncSetAttribute((const void*)attn_chunk_kernel<true, true>,
                         cudaFuncAttributeMaxDynamicSharedMemorySize, ATTN_SMEM);
    cudaFuncSetAttribute((const void*)attn_chunk_kernel<false, false>,
                         cudaFuncAttributeMaxDynamicSharedMemorySize, ATTN_SMEM);

    // ---- stage 2: attention (tf32, unchanged)
    attn_chunk_kernel<true, true><<<dim3(10, BATCH, 1), blk, ATTN_SMEM>>>(
        Qe, Kf, Vf, aligned_fnirs, nullptr, nullptr, nullptr, TE, TF);
    attn_chunk_kernel<false, false><<<dim3(2, BATCH, NCHUNK), blk, ATTN_SMEM>>>(
        Qf, Ke, Ve, nullptr, Opart, Mb, Lb, TF, TE);
    combine_f2e<<<dim3(TF, BATCH), dim3(128)>>>(Opart, Mb, Lb, aligned_eeg);
}

// round 13
// speedup vs baseline: 5.6756x; 1.0769x over previous
#include <cuda_runtime.h>
#include <cuda_fp16.h>
#include <cstdint>
#include <math.h>

#define BATCH 128
#define DIMN  512
#define DIMW  256          // row length in half2 words
#define TE    600
#define TF    120
#define NCHUNK 5           // f2e key chunks of 128 covering 600 keys

// ---------------- scratch (device globals; no allocation allowed) ----------------
__device__ uint32_t g_Ae[BATCH * TE * DIMW];   // eeg, half2 words, pair-permuted
__device__ uint32_t g_Af[BATCH * TF * DIMW];   // fnirs, half2 words, pair-permuted
__device__ uint32_t g_Wt[6 * DIMN * DIMW];     // weights [n][k-half2], permuted
__device__ uint32_t g_Qe[BATCH * TE * DIMW];   // Q/K: half2 pair-permuted
__device__ uint32_t g_Ke[BATCH * TE * DIMW];
__device__ uint32_t g_Ve[BATCH * TE * DIMW];   // V: half2 plain
__device__ uint32_t g_Qf[BATCH * TF * DIMW];
__device__ uint32_t g_Kf[BATCH * TF * DIMW];
__device__ uint32_t g_Vf[BATCH * TF * DIMW];
__device__ float g_Opart[NCHUNK * BATCH * 128 * DIMN];
__device__ float g_M[NCHUNK * BATCH * 128];
__device__ float g_L[NCHUNK * BATCH * 128];

__device__ __forceinline__ uint32_t pack_h2(float lo, float hi) {
    half2 h = __floats2half2_rn(lo, hi);
    return *(uint32_t*)&h;
}

// m16n8k16 fp16 MMA, fp32 accumulate
__device__ __forceinline__ void mma_f16(float* c, const uint32_t* a, const uint32_t* b) {
    asm volatile("mma.sync.aligned.m16n8k16.row.col.f32.f16.f16.f32 "
        "{%0,%1,%2,%3}, {%4,%5,%6,%7}, {%8,%9}, {%0,%1,%2,%3};"
        : "+f"(c[0]), "+f"(c[1]), "+f"(c[2]), "+f"(c[3])
        : "r"(a[0]), "r"(a[1]), "r"(a[2]), "r"(a[3]), "r"(b[0]), "r"(b[1]));
}

__device__ __forceinline__ void cp_async16(uint32_t dst, const void* src) {
    asm volatile("cp.async.cg.shared.global [%0], [%1], 16;" :: "r"(dst), "l"(src));
}
#define CP_COMMIT() asm volatile("cp.async.commit_group;" ::: "memory")
#define CP_WAIT1()  asm volatile("cp.async.wait_group 1;" ::: "memory")

// ------- activation cvt: fp32 -> half2 words, pair-permuted within 8-word groups -
__global__ void cvt_perm_h(const float* __restrict__ src, uint32_t* __restrict__ dst, int n)
{
    const int i = (blockIdx.x * 256 + threadIdx.x) * 4;
    if (i < n) {
        const float4 v = *(const float4*)(src + i);
        const uint32_t w0 = pack_h2(v.x, v.y);
        const uint32_t w1 = pack_h2(v.z, v.w);
        const int p    = i >> 1;
        const int base = p & ~7;
        const int j0   = p & 7;
        const int d0 = (j0 < 4) ? 2 * j0 : 2 * (j0 - 4) + 1;
        const int j1 = j0 + 1;
        const int d1 = (j1 < 4) ? 2 * j1 : 2 * (j1 - 4) + 1;
        dst[base + d0] = w0;
        dst[base + d1] = w1;
    }
}

// ------- weight transform: W[k][n] fp32 -> Wt[n][perm(k-half2)] ------------------
__global__ void wt_h_kernel(const float* __restrict__ W, uint32_t* __restrict__ Wt)
{
    __shared__ float s[32][33];
    const int k0 = blockIdx.x * 32, n0 = blockIdx.y * 32;
    const int tx = threadIdx.x, ty = threadIdx.y;
#pragma unroll
    for (int r = ty; r < 32; r += 8)
        s[r][tx] = W[(size_t)(k0 + r) * DIMN + n0 + tx];
    __syncthreads();
#pragma unroll
    for (int w = ty; w < 16; w += 8) {
        const uint32_t h = pack_h2(s[2 * w][tx], s[2 * w + 1][tx]);
        const int j  = w & 7;
        const int jp = (j < 4) ? 2 * j : 2 * (j - 4) + 1;
        const int pos = (w & 8) + jp;
        Wt[(size_t)(n0 + tx) * DIMW + k0 / 2 + pos] = h;
    }
}

// =============== fp16 m16n8k16 projection GEMM, 3-stage cp.async =================
#define GSTAGE_W  4096
#define GB_OFF_W  2048
#define GEMM_SMEM_BYTES (3 * GSTAGE_W * 4)

__global__ __launch_bounds__(256, 2)
void gemm_mma_kernel(const uint32_t* __restrict__ A, const uint32_t* __restrict__ Wt,
                     const float* __restrict__ b0, const float* __restrict__ b1,
                     const float* __restrict__ b2,
                     uint32_t* __restrict__ C0, uint32_t* __restrict__ C1,
                     uint32_t* __restrict__ C2)
{
    extern __shared__ uint32_t smem[];
    const uint32_t sb = (uint32_t)__cvta_generic_to_shared(smem);

    const int tid    = threadIdx.x;
    const int wid    = tid >> 5;
    const int lane   = tid & 31;
    const int warp_m = wid & 1;
    const int warp_n = wid >> 1;
    const int g      = lane >> 2;
    const int t4     = lane & 3;
    const int wsel = blockIdx.x >> 2;
    const int n0   = (blockIdx.x & 3) * 128;
    const int m0   = blockIdx.y * 128;

    const uint32_t* W = Wt + (size_t)wsel * DIMN * DIMW;
    const float* bias = (wsel == 0) ? b0 : (wsel == 1) ? b1 : b2;
    uint32_t* C       = (wsel == 0) ? C0 : (wsel == 1) ? C1 : C2;

    const int sm_ = tid >> 2;
    const int sq  = tid & 3;

    float acc[4][4][4];
#pragma unroll
    for (int mt = 0; mt < 4; mt++)
#pragma unroll
        for (int nt = 0; nt < 4; nt++)
#pragma unroll
            for (int r = 0; r < 4; r++) acc[mt][nt][r] = 0.f;

    auto issue = [&](int c, int s) {
        const uint32_t stA = sb + (uint32_t)(s * GSTAGE_W) * 4;
        const uint32_t stB = sb + (uint32_t)(s * GSTAGE_W + GB_OFF_W) * 4;
#pragma unroll
        for (int i = 0; i < 2; ++i) {
            const int m = sm_ + i * 64;
            const uint32_t dstw = (uint32_t)(m * 16 + ((sq * 4) ^ ((m & 3) << 2)));
            cp_async16(stA + dstw * 4, A + (size_t)(m0 + m) * DIMW + c * 16 + sq * 4);
        }
#pragma unroll
        for (int i = 0; i < 2; ++i) {
            const int nn = sm_ + i * 64;
            const uint32_t dstw = (uint32_t)(nn * 16 + ((sq * 4) ^ ((nn & 3) << 2)));
            cp_async16(stB + dstw * 4, W + (size_t)(n0 + nn) * DIMW + c * 16 + sq * 4);
        }
        CP_COMMIT();
    };

    issue(0, 0);
    issue(1, 1);

    const int sw = (g & 3) << 2;

    for (int c = 0; c < 16; ++c) {
        const int s = c % 3;
        CP_WAIT1();
        __syncthreads();
        if (c + 2 < 16) issue(c + 2, (c + 2) % 3);

        const uint32_t* Af = smem + s * GSTAGE_W;
        const uint32_t* Bf = smem + s * GSTAGE_W + GB_OFF_W;
#pragma unroll
        for (int kk = 0; kk < 2; ++kk) {
            const int off = (kk * 8 + 2 * t4) ^ sw;
            uint32_t a[4][4], b[4][2];
#pragma unroll
            for (int mt = 0; mt < 4; ++mt) {
                const int r = warp_m * 64 + mt * 16 + g;
                const uint2 v0 = *(const uint2*)&Af[r * 16 + off];
                const uint2 v1 = *(const uint2*)&Af[(r + 8) * 16 + off];
                a[mt][0] = v0.x; a[mt][1] = v1.x; a[mt][2] = v0.y; a[mt][3] = v1.y;
            }
#pragma unroll
            for (int nt = 0; nt < 4; ++nt) {
                const int n = warp_n * 32 + nt * 8 + g;
                const uint2 vb = *(const uint2*)&Bf[n * 16 + off];
                b[nt][0] = vb.x; b[nt][1] = vb.y;
            }
#pragma unroll
            for (int mt = 0; mt < 4; ++mt)
#pragma unroll
                for (int nt = 0; nt < 4; ++nt)
                    mma_f16(acc[mt][nt], a[mt], b[nt]);
        }
    }

    // epilogue: bias add fp32, pack half2. Q/K (wsel 0,1): pair-permuted; V: plain.
#pragma unroll
    for (int mt = 0; mt < 4; ++mt) {
        const int row = m0 + warp_m * 64 + mt * 16 + g;
#pragma unroll
        for (int nt = 0; nt < 4; ++nt) {
            const int col = n0 + warp_n * 32 + nt * 8 + 2 * t4;
            const float2 bb = *(const float2*)(bias + col);
            const int wplain = n0 / 2 + warp_n * 16 + nt * 4 + t4;
            const int wperm  = n0 / 2 + warp_n * 16 + ((nt & 2) ? 8 : 0) + 2 * t4 + (nt & 1);
            const int dw = (wsel == 2) ? wplain : wperm;
            C[(size_t)row * DIMW + dw] =
                pack_h2(acc[mt][nt][0] + bb.x, acc[mt][nt][1] + bb.y);
            C[(size_t)(row + 8) * DIMW + dw] =
                pack_h2(acc[mt][nt][2] + bb.x, acc[mt][nt][3] + bb.y);
        }
    }
}

// ================= fp16 attention chunk kernel ===================================
// smem: Ss fp32 [64][132] | Ps half2 [64][68] | stage (QK [192][16] / Vt [128][16]) | l_s
#define SS_OFF 0
#define PS_OFF 33792
#define ST_OFF 51200
#define LS_OFF 63488
#define ATTN_SMEM 63744

template <bool E2F, bool FINAL>
__global__ __launch_bounds__(256, 2)
void attn_chunk_kernel(const uint32_t* __restrict__ Q, const uint32_t* __restrict__ K,
                       const uint32_t* __restrict__ V, float* __restrict__ O,
                       float* __restrict__ Opart, float* __restrict__ Mb,
                       float* __restrict__ Lb, int Tq, int Tk)
{
    extern __shared__ char smemc[];
    float*    Ss = (float*)(smemc + SS_OFF);
    uint32_t* Ps = (uint32_t*)(smemc + PS_OFF);
    uint32_t* Qs = (uint32_t*)(smemc + ST_OFF);      // [64][16]
    uint32_t* Ks = Qs + 64 * 16;                     // [128][16]
    uint32_t* Vt = Qs;                               // [128][16] (phase-3 alias)
    float*    l_s = (float*)(smemc + LS_OFF);

    const int tid    = threadIdx.x;
    const int wid    = tid >> 5;
    const int lane   = tid & 31;
    const int warp_m = wid & 1;
    const int warp_n = wid >> 1;
    const int g      = lane >> 2;
    const int t4     = lane & 3;
    const int q0     = blockIdx.x * 64;
    const int b      = blockIdx.y;
    const int kchunk = blockIdx.z;
    const float scale = 0.044194173824159216f;
    const float NEG_INF = __int_as_float(0xff800000);
    const int sw = (g & 3) << 2;

    const uint32_t* Qb = Q + (size_t)b * Tq * DIMW;
    const uint32_t* Kb = K + (size_t)b * Tk * DIMW;
    const uint32_t* Vb = V + (size_t)b * Tk * DIMW;

    // ---------------- Phase 1: S = scale * Q K^T (fp16 k16) ----------------------
    float acc[2][4][4];
#pragma unroll
    for (int mt = 0; mt < 2; mt++)
#pragma unroll
        for (int nt = 0; nt < 4; nt++)
#pragma unroll
            for (int r = 0; r < 4; r++) acc[mt][nt][r] = 0.f;

    for (int ch = 0; ch < 16; ++ch) {
        __syncthreads();
        {   // Q: 64 rows x 16 words (1 uint4/thread)
            const int r = tid >> 2, c4 = tid & 3;
            uint4 v = make_uint4(0u, 0u, 0u, 0u);
            if (q0 + r < Tq)
                v = *(const uint4*)(Qb + (size_t)(q0 + r) * DIMW + ch * 16 + c4 * 4);
            *(uint4*)&Qs[r * 16 + ((c4 * 4) ^ ((r & 3) << 2))] = v;
        }
#pragma unroll
        for (int i = 0; i < 2; ++i) {   // K: 128 keys x 16 words
            const int lin = i * 256 + tid;
            const int r = lin >> 2, c4 = lin & 3;
            const int key = kchunk * 128 + r;
            uint4 v = make_uint4(0u, 0u, 0u, 0u);
            if (key < Tk)
                v = *(const uint4*)(Kb + (size_t)key * DIMW + ch * 16 + c4 * 4);
            *(uint4*)&Ks[r * 16 + ((c4 * 4) ^ ((r & 3) << 2))] = v;
        }
        __syncthreads();
#pragma unroll
        for (int kk = 0; kk < 2; ++kk) {
            const int off = (kk * 8 + 2 * t4) ^ sw;
            uint32_t a[2][4], bb[4][2];
#pragma unroll
            for (int mt = 0; mt < 2; ++mt) {
                const int r = warp_m * 32 + mt * 16 + g;
                const uint2 v0 = *(const uint2*)&Qs[r * 16 + off];
                const uint2 v1 = *(const uint2*)&Qs[(r + 8) * 16 + off];
                a[mt][0] = v0.x; a[mt][1] = v1.x; a[mt][2] = v0.y; a[mt][3] = v1.y;
            }
#pragma unroll
            for (int nt = 0; nt < 4; ++nt) {
                const int n = warp_n * 32 + nt * 8 + g;
                const uint2 vb = *(const uint2*)&Ks[n * 16 + off];
                bb[nt][0] = vb.x; bb[nt][1] = vb.y;
            }
#pragma unroll
            for (int mt = 0; mt < 2; ++mt)
#pragma unroll
                for (int nt = 0; nt < 4; ++nt)
                    mma_f16(acc[mt][nt], a[mt], bb[nt]);
        }
    }
    // mask + scale, stage S to smem (fp32)
#pragma unroll
    for (int mt = 0; mt < 2; ++mt) {
#pragma unroll
        for (int half = 0; half < 2; ++half) {
            const int row = warp_m * 32 + mt * 16 + half * 8 + g;
            const int q   = q0 + row;
            const int j0g = q / 20;
#pragma unroll
            for (int nt = 0; nt < 4; ++nt) {
                const int colc = warp_n * 32 + nt * 8 + 2 * t4;
                float vout[2];
#pragma unroll
                for (int e = 0; e < 2; ++e) {
                    const int key = kchunk * 128 + colc + e;
                    float val;
                    if (key >= Tk) val = NEG_INF;
                    else {
                        bool valid;
                        if (E2F) valid = (key >= j0g + 20) && (key <= j0g + 80);
                        else { const int gg = key / 20; valid = (q >= gg + 20) && (q <= gg + 80); }
                        val = valid ? acc[mt][nt][half * 2 + e] * scale : -1e9f;
                    }
                    vout[e] = val;
                }
                *(float2*)&Ss[row * 132 + colc] = make_float2(vout[0], vout[1]);
            }
        }
    }
    __syncthreads();

    // ---------------- Phase 2: softmax; write unnormalized P as half2 ------------
    {
        const int row  = tid >> 2;
        const int part = tid & 3;
        const float* srow = Ss + row * 132;

        float mx = NEG_INF;
#pragma unroll
        for (int i = 0; i < 16; ++i) {
            const float2 s2 = *(const float2*)&srow[2 * (part + 4 * i)];
            mx = fmaxf(mx, fmaxf(s2.x, s2.y));
        }
        mx = fmaxf(mx, __shfl_xor_sync(0xffffffffu, mx, 1));
        mx = fmaxf(mx, __shfl_xor_sync(0xffffffffu, mx, 2));
        float sum = 0.f;
        uint32_t* prow = Ps + row * 68;
#pragma unroll
        for (int i = 0; i < 16; ++i) {
            const int w = part + 4 * i;
            const float2 s2 = *(const float2*)&srow[2 * w];
            const float e0 = __expf(s2.x - mx);
            const float e1 = __expf(s2.y - mx);
            sum += e0 + e1;
            const int j = w & 7;
            const int pw = (w & ~7) + ((j < 4) ? 2 * j : 2 * (j - 4) + 1);
            prow[pw] = pack_h2(e0, e1);
        }
        sum += __shfl_xor_sync(0xffffffffu, sum, 1);
        sum += __shfl_xor_sync(0xffffffffu, sum, 2);
        if (part == 0) {
            l_s[row] = sum;
            if (!FINAL) {
                const int idx = (kchunk * BATCH + b) * 128 + q0 + row;
                Mb[idx] = mx;
                Lb[idx] = sum;
            }
        }
    }
    __syncthreads();

    // ---------------- Phase 3: O = P V (fp16 k16, V transposed on the fly) -------
    for (int nc = 0; nc < 4; ++nc) {
        float oacc[2][4][4];
#pragma unroll
        for (int mt = 0; mt < 2; mt++)
#pragma unroll
            for (int nt = 0; nt < 4; nt++)
#pragma unroll
                for (int r = 0; r < 4; r++) oacc[mt][nt][r] = 0.f;

        for (int ks = 0; ks < 4; ++ks) {
            __syncthreads();
#pragma unroll
            for (int i = 0; i < 4; ++i) {       // V transpose stage: [128 d][16 kw]
                const int u  = i * 256 + tid;
                const int kw = (u >> 2) & 15;
                const int wd = (u & 3) | ((u >> 6) << 2);
                const int key0 = kchunk * 128 + ks * 32 + 2 * kw;
                uint32_t w0 = 0u, w1 = 0u;
                if (key0 < Tk)     w0 = Vb[(size_t)key0 * DIMW + nc * 64 + wd];
                if (key0 + 1 < Tk) w1 = Vb[(size_t)(key0 + 1) * DIMW + nc * 64 + wd];
                const uint32_t lo = __byte_perm(w0, w1, 0x5410);
                const uint32_t hi = __byte_perm(w0, w1, 0x7632);
                const int j  = kw & 7;
                const int ps = (kw & 8) + ((j < 4) ? 2 * j : 2 * (j - 4) + 1);
                const int d0 = 2 * wd, d1 = 2 * wd + 1;
                Vt[d0 * 16 + (ps ^ ((d0 & 3) << 2))] = lo;
                Vt[d1 * 16 + (ps ^ ((d1 & 3) << 2))] = hi;
            }
            __syncthreads();
#pragma unroll
            for (int kk = 0; kk < 2; ++kk) {
                const int offv = (kk * 8 + 2 * t4) ^ sw;
                const int offp = ks * 16 + kk * 8 + 2 * t4;
                uint32_t a[2][4], bb[4][2];
#pragma unroll
                for (int mt = 0; mt < 2; ++mt) {
                    const int r = warp_m * 32 + mt * 16 + g;
                    const uint2 v0 = *(const uint2*)&Ps[r * 68 + offp];
                    const uint2 v1 = *(const uint2*)&Ps[(r + 8) * 68 + offp];
                    a[mt][0] = v0.x; a[mt][1] = v1.x; a[mt][2] = v0.y; a[mt][3] = v1.y;
                }
#pragma unroll
                for (int nt = 0; nt < 4; ++nt) {
                    const int n = warp_n * 32 + nt * 8 + g;
                    const uint2 vb = *(const uint2*)&Vt[n * 16 + offv];
                    bb[nt][0] = vb.x; bb[nt][1] = vb.y;
                }
#pragma unroll
                for (int mt = 0; mt < 2; ++mt)
#pragma unroll
                    for (int nt = 0; nt < 4; ++nt)
                        mma_f16(oacc[mt][nt], a[mt], bb[nt]);
            }
        }
#pragma unroll
        for (int mt = 0; mt < 2; ++mt) {
#pragma unroll
            for (int half = 0; half < 2; ++half) {
                const int row = warp_m * 32 + mt * 16 + half * 8 + g;
                const int q   = q0 + row;
#pragma unroll
                for (int nt = 0; nt < 4; ++nt) {
                    const int col = nc * 128 + warp_n * 32 + nt * 8 + 2 * t4;
                    const float v0 = oacc[mt][nt][half * 2 + 0];
                    const float v1 = oacc[mt][nt][half * 2 + 1];
                    if (FINAL) {
                        if (q < Tq) {
                            const float inv = 1.f / l_s[row];
                            *(float2*)(O + ((size_t)b * Tq + q) * DIMN + col) =
                                make_float2(v0 * inv, v1 * inv);
                        }
                    } else {
                        float* dst = Opart + (((size_t)kchunk * BATCH + b) * 128 + q) * DIMN + col;
                        *(float2*)dst = make_float2(v0, v1);
                    }
                }
            }
        }
    }
}

// ----------------- f2e combine: merge 5 chunk partials per row -------------------
__global__ void combine_f2e(const float* __restrict__ Opart,
                            const float* __restrict__ Mb, const float* __restrict__ Lb,
                            float* __restrict__ O)
{
    const int q = blockIdx.x;
    const int b = blockIdx.y;
    const int t = threadIdx.x;
    float m[NCHUNK], w[NCHUNK];
    float M = __int_as_float(0xff800000);
#pragma unroll
    for (int c = 0; c < NCHUNK; ++c) {
        m[c] = Mb[(c * BATCH + b) * 128 + q];
        M = fmaxf(M, m[c]);
    }
    float den = 0.f;
#pragma unroll
    for (int c = 0; c < NCHUNK; ++c) {
        w[c] = __expf(m[c] - M);
        den += w[c] * Lb[(c * BATCH + b) * 128 + q];
    }
    const float inv = 1.f / den;
    float4 o = make_float4(0.f, 0.f, 0.f, 0.f);
#pragma unroll
    for (int c = 0; c < NCHUNK; ++c) {
        const float4 p = *(const float4*)(Opart + (((size_t)c * BATCH + b) * 128 + q) * DIMN + t * 4);
        const float s = w[c] * inv;
        o.x += s * p.x; o.y += s * p.y; o.z += s * p.z; o.w += s * p.w;
    }
    *(float4*)(O + ((size_t)b * TF + q) * DIMN + t * 4) = o;
}

extern "C" void kernel_launch(void* const* d_in, const int* in_sizes, int n_in,
                              void* d_out, int out_size)
{
    (void)in_sizes; (void)n_in; (void)out_size;

    const float* eeg   = (const float*)d_in[0];
    const float* fnirs = (const float*)d_in[1];
    const float* Wqe = (const float*)d_in[2];
    const float* bqe = (const float*)d_in[3];
    const float* Wke = (const float*)d_in[4];
    const float* bke = (const float*)d_in[5];
    const float* Wve = (const float*)d_in[6];
    const float* bve = (const float*)d_in[7];
    const float* Wqf = (const float*)d_in[8];
    const float* bqf = (const float*)d_in[9];
    const float* Wkf = (const float*)d_in[10];
    const float* bkf = (const float*)d_in[11];
    const float* Wvf = (const float*)d_in[12];
    const float* bvf = (const float*)d_in[13];

    uint32_t *Ae, *Af, *Wt, *Qe, *Ke, *Ve, *Qf, *Kf, *Vf;
    float *Opart, *Mb, *Lb;
    cudaGetSymbolAddress((void**)&Ae, g_Ae);
    cudaGetSymbolAddress((void**)&Af, g_Af);
    cudaGetSymbolAddress((void**)&Wt, g_Wt);
    cudaGetSymbolAddress((void**)&Qe, g_Qe);
    cudaGetSymbolAddress((void**)&Ke, g_Ke);
    cudaGetSymbolAddress((void**)&Ve, g_Ve);
    cudaGetSymbolAddress((void**)&Qf, g_Qf);
    cudaGetSymbolAddress((void**)&Kf, g_Kf);
    cudaGetSymbolAddress((void**)&Vf, g_Vf);
    cudaGetSymbolAddress((void**)&Opart, g_Opart);
    cudaGetSymbolAddress((void**)&Mb, g_M);
    cudaGetSymbolAddress((void**)&Lb, g_L);

    float* out           = (float*)d_out;
    float* aligned_eeg   = out;                                // [B, TF, D]
    float* aligned_fnirs = out + (size_t)BATCH * TF * DIMN;    // [B, TE, D]

    const int Me = BATCH * TE;
    const int Mf = BATCH * TF;
    const size_t NWW = (size_t)DIMN * DIMW;

    const int ne = Me * DIMN, nf = Mf * DIMN;
    cvt_perm_h<<<(ne / 4 + 255) / 256, 256>>>(eeg,   Ae, ne);
    cvt_perm_h<<<(nf / 4 + 255) / 256, 256>>>(fnirs, Af, nf);
    dim3 wblk(32, 8), wgrd(DIMN / 32, DIMN / 32);
    wt_h_kernel<<<wgrd, wblk>>>(Wqe, Wt + 0 * NWW);
    wt_h_kernel<<<wgrd, wblk>>>(Wke, Wt + 1 * NWW);
    wt_h_kernel<<<wgrd, wblk>>>(Wve, Wt + 2 * NWW);
    wt_h_kernel<<<wgrd, wblk>>>(Wqf, Wt + 3 * NWW);
    wt_h_kernel<<<wgrd, wblk>>>(Wkf, Wt + 4 * NWW);
    wt_h_kernel<<<wgrd, wblk>>>(Wvf, Wt + 5 * NWW);

    cudaFuncSetAttribute(gemm_mma_kernel,
                         cudaFuncAttributeMaxDynamicSharedMemorySize, GEMM_SMEM_BYTES);

    dim3 blk(256);
    gemm_mma_kernel<<<dim3(12, Me / 128), blk, GEMM_SMEM_BYTES>>>(
        Ae, Wt, bqe, bke, bve, Qe, Ke, Ve);
    gemm_mma_kernel<<<dim3(12, Mf / 128), blk, GEMM_SMEM_BYTES>>>(
        Af, Wt + 3 * NWW, bqf, bkf, bvf, Qf, Kf, Vf);

    cudaFuncSetAttribute((const void*)attn_chunk_kernel<true, true>,
                         cudaFuncAttributeMaxDynamicSharedMemorySize, ATTN_SMEM);
    cudaFuncSetAttribute((const void*)attn_chunk_kernel<false, false>,
                         cudaFuncAttributeMaxDynamicSharedMemorySize, ATTN_SMEM);

    attn_chunk_kernel<true, true><<<dim3(10, BATCH, 1), blk, ATTN_SMEM>>>(
        Qe, Kf, Vf, aligned_fnirs, nullptr, nullptr, nullptr, TE, TF);
    attn_chunk_kernel<false, false><<<dim3(2, BATCH, NCHUNK), blk, ATTN_SMEM>>>(
        Qf, Ke, Ve, nullptr, Opart, Mb, Lb, TF, TE);
    combine_f2e<<<dim3(TF, BATCH), dim3(128)>>>(Opart, Mb, Lb, aligned_eeg);
}